// round 2
// baseline (speedup 1.0000x reference)
#include <cuda_runtime.h>

// Problem constants
#define PB   4
#define PK   2048
#define PD   1024
#define PH   16
#define PNC  1024   // NCTX = K/2

// ---------------- scratch (device globals: allocation-free) ----------------
__device__ float g_xr[PB * PK * PD];            // RoPE'd tokens, permuted (ctx first, then tgt)
__device__ int   g_perm[PB * PK];               // slot -> original token index
__device__ float g_qkv_ctx[PB * PNC * 3072];    // ctx tokens @ ctx_in_w^T   [q|k|v]
__device__ float g_kv_tgt[PB * PNC * 2048];     // ctx tokens @ tgt_in_w(k,v)^T  [k|v]
__device__ float g_q_tgt[PB * PNC * PD];        // tgt tokens @ tgt_in_w(q)^T
__device__ float g_o_ctx[PB * PNC * PD];        // attention outputs
__device__ float g_o_tgt[PB * PNC * PD];

// ---------------- perm: stable partition (ctx slots 0..1023, tgt 1024..2047) ---
// is_context dtype is unknown (bool may arrive as u8, i32, or f32). Detect:
// byte-sum of the first 2048 bytes is EXACTLY 1024 (or 255*1024) iff 1-byte flags
// (each batch has exactly NCTX=1024 trues by construction). For 4-byte elements,
// true is a nonzero word for both int32(1) and float32(1.0f), false is zero.
__global__ void build_perm(const void* __restrict__ is_ctx_raw,
                           int* __restrict__ perm) {
    const unsigned char* u8  = (const unsigned char*)is_ctx_raw;
    const unsigned int*  u32 = (const unsigned int*)is_ctx_raw;
    int b = blockIdx.x;
    int lane = threadIdx.x;           // 32 threads

    // dtype detection (all blocks do it; cheap)
    int s = 0;
    for (int i = lane; i < 2048; i += 32) s += (int)u8[i];
#pragma unroll
    for (int off = 16; off; off >>= 1) s += __shfl_xor_sync(0xffffffffu, s, off);
    bool one_byte = (s == 1024) || (s == 255 * 1024);

    int cbase = 0, tbase = PNC;
    for (int j0 = 0; j0 < PK; j0 += 32) {
        int j = j0 + lane;
        int c = one_byte ? (u8[b * PK + j] != 0) : (u32[b * PK + j] != 0u);
        unsigned mask = __ballot_sync(0xffffffffu, c);
        int pre = __popc(mask & ((1u << lane) - 1u));
        int slot = c ? (cbase + pre) : (tbase + lane - pre);
        perm[b * PK + slot] = j;
        int nc = __popc(mask);
        cbase += nc;
        tbase += 32 - nc;
    }
}

// ---------------- RoPE + gather into sorted order ----------------
// block = one output slot (token), 512 threads = 512 (even,odd) pairs
__global__ __launch_bounds__(512) void rope_gather(
    const float* __restrict__ x, const float* __restrict__ coords,
    const float* __restrict__ rope, const int* __restrict__ perm,
    float* __restrict__ xr) {
    int s = blockIdx.x & (PK - 1);
    int b = blockIdx.x >> 11;
    int j = perm[b * PK + s];
    long tokin = (long)b * PK + j;

    float cy = coords[tokin * 2 + 0];
    float cx = coords[tokin * 2 + 1];
    // match reference: clip(coords/IMG*(MAXPOS-1), 0, MAXPOS-1) then trunc to int
    int ypos = (int)fminf(fmaxf(cy / 224.0f * 1023.0f, 0.0f), 1023.0f);
    int xpos = (int)fminf(fmaxf(cx / 224.0f * 1023.0f, 0.0f), 1023.0f);

    int t = threadIdx.x;
    int i = t & 255;                       // pair index within half
    int pos = (t < 256) ? xpos : ypos;     // first half uses x_rope, second y_rope
    int base = (t < 256) ? (2 * i) : (512 + 2 * i);

    float c  = rope[((long)pos * 256 + i) * 2 + 0];
    float sn = rope[((long)pos * 256 + i) * 2 + 1];
    float2 p = *(const float2*)(x + tokin * PD + base);
    float2 r;
    r.x = p.x * c - p.y * sn;
    r.y = p.x * sn + p.y * c;
    *(float2*)(xr + ((long)b * PK + s) * PD + base) = r;
}

// ---------------- generic fp32 NT-GEMM: C[m,n] = sum_k A[m,k]*W[n,k] + bias[n] ----
// BM=BN=128, BK=16, 256 threads, 8x8 micro-tile. Per-batch via blockIdx.z.
// If perm != nullptr: epilogue scatters rows to out[b, perm[b, m+slotOff], n] (ld=PD).
__global__ __launch_bounds__(256) void gemm_nt(
    const float* __restrict__ A, long sA,
    const float* __restrict__ W,
    const float* __restrict__ bias,
    float* __restrict__ Cout, long sC, int ldc,
    int Kd,
    const int* __restrict__ perm, int slotOff) {
    __shared__ float As[16][128];
    __shared__ float Bs[16][128];

    int b = blockIdx.z;
    const float* Ab = A + (long)b * sA + (long)blockIdx.y * 128 * Kd;
    const float* Wb = W + (long)blockIdx.x * 128 * Kd;

    int tid = threadIdx.x;
    int tx = tid & 15, ty = tid >> 4;
    int lr = tid >> 2;            // 0..63
    int lc = (tid & 3) * 4;       // 0,4,8,12

    float acc[8][8];
#pragma unroll
    for (int i = 0; i < 8; i++)
#pragma unroll
        for (int j = 0; j < 8; j++) acc[i][j] = 0.0f;

    for (int k0 = 0; k0 < Kd; k0 += 16) {
        float4 a0 = *(const float4*)(Ab + (long)lr * Kd + k0 + lc);
        float4 a1 = *(const float4*)(Ab + (long)(lr + 64) * Kd + k0 + lc);
        float4 w0 = *(const float4*)(Wb + (long)lr * Kd + k0 + lc);
        float4 w1 = *(const float4*)(Wb + (long)(lr + 64) * Kd + k0 + lc);
        __syncthreads();
        As[lc + 0][lr] = a0.x; As[lc + 1][lr] = a0.y; As[lc + 2][lr] = a0.z; As[lc + 3][lr] = a0.w;
        As[lc + 0][lr + 64] = a1.x; As[lc + 1][lr + 64] = a1.y; As[lc + 2][lr + 64] = a1.z; As[lc + 3][lr + 64] = a1.w;
        Bs[lc + 0][lr] = w0.x; Bs[lc + 1][lr] = w0.y; Bs[lc + 2][lr] = w0.z; Bs[lc + 3][lr] = w0.w;
        Bs[lc + 0][lr + 64] = w1.x; Bs[lc + 1][lr + 64] = w1.y; Bs[lc + 2][lr + 64] = w1.z; Bs[lc + 3][lr + 64] = w1.w;
        __syncthreads();
#pragma unroll
        for (int kk = 0; kk < 16; kk++) {
            float ar[8], br[8];
            *(float4*)(ar)     = *(const float4*)&As[kk][ty * 8];
            *(float4*)(ar + 4) = *(const float4*)&As[kk][ty * 8 + 4];
            *(float4*)(br)     = *(const float4*)&Bs[kk][tx * 8];
            *(float4*)(br + 4) = *(const float4*)&Bs[kk][tx * 8 + 4];
#pragma unroll
            for (int i = 0; i < 8; i++)
#pragma unroll
                for (int j = 0; j < 8; j++)
                    acc[i][j] = fmaf(ar[i], br[j], acc[i][j]);
        }
    }

    int m0 = blockIdx.y * 128 + ty * 8;
    int n0 = blockIdx.x * 128 + tx * 8;
    float bs[8];
#pragma unroll
    for (int j = 0; j < 8; j++) bs[j] = bias[n0 + j];

#pragma unroll
    for (int i = 0; i < 8; i++) {
        int m = m0 + i;
        float4 v0, v1;
        v0.x = acc[i][0] + bs[0]; v0.y = acc[i][1] + bs[1];
        v0.z = acc[i][2] + bs[2]; v0.w = acc[i][3] + bs[3];
        v1.x = acc[i][4] + bs[4]; v1.y = acc[i][5] + bs[5];
        v1.z = acc[i][6] + bs[6]; v1.w = acc[i][7] + bs[7];
        float* dst;
        if (perm != nullptr) {
            int tok = perm[b * PK + m + slotOff];
            dst = Cout + ((long)b * PK + tok) * PD + n0;
        } else {
            dst = Cout + (long)b * sC + (long)m * ldc + n0;
        }
        *(float4*)(dst)     = v0;
        *(float4*)(dst + 4) = v1;
    }
}

// ---------------- attention: softmax(Q K^T / 8) V per (b, h), flash-tiled -------
// block = (b, h, 64-query tile), 256 threads, 4x4 register micro-tiles.
// smem: Qs natural [r][d], KP = K transposed [d][c] (reused as P [r][c]), Vs natural [c][d].
__global__ __launch_bounds__(256) void attn(
    const float* __restrict__ Q, long sQ, int ldq,
    const float* __restrict__ Kp, long sK, int ldk,
    const float* __restrict__ Vp, long sV, int ldv,
    float* __restrict__ O, long sO) {
    __shared__ float Qs[64 * 64];
    __shared__ float KP[64 * 64];
    __shared__ float Vs[64 * 64];

    int b = blockIdx.z, h = blockIdx.y;
    int q0 = blockIdx.x * 64;
    const float* Qb = Q + (long)b * sQ + h * 64;
    const float* Kb = Kp + (long)b * sK + h * 64;
    const float* Vb = Vp + (long)b * sV + h * 64;

    int tid = threadIdx.x;
    int tx = tid & 15, ty = tid >> 4;
    int lrow = tid >> 2;            // 0..63
    int ld0 = (tid & 3) * 16;       // 0,16,32,48

    // load Q tile (natural layout)
    {
        const float* src = Qb + (long)(q0 + lrow) * ldq + ld0;
#pragma unroll
        for (int u = 0; u < 4; u++) {
            float4 v = *(const float4*)(src + u * 4);
            *(float4*)&Qs[lrow * 64 + ld0 + u * 4] = v;
        }
    }

    float m_[4], l_[4], o_[4][4];
#pragma unroll
    for (int i = 0; i < 4; i++) {
        m_[i] = -1e30f; l_[i] = 0.0f;
#pragma unroll
        for (int j = 0; j < 4; j++) o_[i][j] = 0.0f;
    }

    for (int kt = 0; kt < PNC; kt += 64) {
        __syncthreads();  // previous PV read of KP/Vs complete
        // load K tile transposed KP[d][c], V tile natural Vs[c][d]
        {
            const float* ks = Kb + (long)(kt + lrow) * ldk + ld0;
            const float* vs = Vb + (long)(kt + lrow) * ldv + ld0;
#pragma unroll
            for (int u = 0; u < 4; u++) {
                float4 kv = *(const float4*)(ks + u * 4);
                int d = ld0 + u * 4;
                KP[(d + 0) * 64 + lrow] = kv.x;
                KP[(d + 1) * 64 + lrow] = kv.y;
                KP[(d + 2) * 64 + lrow] = kv.z;
                KP[(d + 3) * 64 + lrow] = kv.w;
                float4 vv = *(const float4*)(vs + u * 4);
                *(float4*)&Vs[lrow * 64 + d] = vv;
            }
        }
        __syncthreads();

        // S = Q K^T (rows ty*4.., cols tx*4..)
        float s_[4][4];
#pragma unroll
        for (int i = 0; i < 4; i++)
#pragma unroll
            for (int j = 0; j < 4; j++) s_[i][j] = 0.0f;
#pragma unroll 4
        for (int d = 0; d < 64; d++) {
            float4 kv = *(const float4*)&KP[d * 64 + tx * 4];
            float a0 = Qs[(ty * 4 + 0) * 64 + d];
            float a1 = Qs[(ty * 4 + 1) * 64 + d];
            float a2 = Qs[(ty * 4 + 2) * 64 + d];
            float a3 = Qs[(ty * 4 + 3) * 64 + d];
            s_[0][0] = fmaf(a0, kv.x, s_[0][0]); s_[0][1] = fmaf(a0, kv.y, s_[0][1]);
            s_[0][2] = fmaf(a0, kv.z, s_[0][2]); s_[0][3] = fmaf(a0, kv.w, s_[0][3]);
            s_[1][0] = fmaf(a1, kv.x, s_[1][0]); s_[1][1] = fmaf(a1, kv.y, s_[1][1]);
            s_[1][2] = fmaf(a1, kv.z, s_[1][2]); s_[1][3] = fmaf(a1, kv.w, s_[1][3]);
            s_[2][0] = fmaf(a2, kv.x, s_[2][0]); s_[2][1] = fmaf(a2, kv.y, s_[2][1]);
            s_[2][2] = fmaf(a2, kv.z, s_[2][2]); s_[2][3] = fmaf(a2, kv.w, s_[2][3]);
            s_[3][0] = fmaf(a3, kv.x, s_[3][0]); s_[3][1] = fmaf(a3, kv.y, s_[3][1]);
            s_[3][2] = fmaf(a3, kv.z, s_[3][2]); s_[3][3] = fmaf(a3, kv.w, s_[3][3]);
        }

        // online softmax per row (16 lanes per row within warp: shfl_xor 1,2,4,8)
#pragma unroll
        for (int i = 0; i < 4; i++) {
#pragma unroll
            for (int j = 0; j < 4; j++) s_[i][j] *= 0.125f;
            float mt = fmaxf(fmaxf(s_[i][0], s_[i][1]), fmaxf(s_[i][2], s_[i][3]));
#pragma unroll
            for (int off = 1; off < 16; off <<= 1)
                mt = fmaxf(mt, __shfl_xor_sync(0xffffffffu, mt, off));
            float mnew = fmaxf(m_[i], mt);
            float alpha = __expf(m_[i] - mnew);
            float ps = 0.0f;
#pragma unroll
            for (int j = 0; j < 4; j++) {
                float p = __expf(s_[i][j] - mnew);
                s_[i][j] = p;
                ps += p;
            }
#pragma unroll
            for (int off = 1; off < 16; off <<= 1)
                ps += __shfl_xor_sync(0xffffffffu, ps, off);
            l_[i] = l_[i] * alpha + ps;
            m_[i] = mnew;
#pragma unroll
            for (int j = 0; j < 4; j++) o_[i][j] *= alpha;
        }

        __syncthreads();  // all threads done reading KP as K
        // write P (natural [r][c]) into KP
#pragma unroll
        for (int i = 0; i < 4; i++) {
            float4 pv;
            pv.x = s_[i][0]; pv.y = s_[i][1]; pv.z = s_[i][2]; pv.w = s_[i][3];
            *(float4*)&KP[(ty * 4 + i) * 64 + tx * 4] = pv;
        }
        __syncthreads();

        // O += P V (rows ty*4.., d-cols tx*4..)
#pragma unroll 4
        for (int c = 0; c < 64; c++) {
            float4 vv = *(const float4*)&Vs[c * 64 + tx * 4];
            float p0 = KP[(ty * 4 + 0) * 64 + c];
            float p1 = KP[(ty * 4 + 1) * 64 + c];
            float p2 = KP[(ty * 4 + 2) * 64 + c];
            float p3 = KP[(ty * 4 + 3) * 64 + c];
            o_[0][0] = fmaf(p0, vv.x, o_[0][0]); o_[0][1] = fmaf(p0, vv.y, o_[0][1]);
            o_[0][2] = fmaf(p0, vv.z, o_[0][2]); o_[0][3] = fmaf(p0, vv.w, o_[0][3]);
            o_[1][0] = fmaf(p1, vv.x, o_[1][0]); o_[1][1] = fmaf(p1, vv.y, o_[1][1]);
            o_[1][2] = fmaf(p1, vv.z, o_[1][2]); o_[1][3] = fmaf(p1, vv.w, o_[1][3]);
            o_[2][0] = fmaf(p2, vv.x, o_[2][0]); o_[2][1] = fmaf(p2, vv.y, o_[2][1]);
            o_[2][2] = fmaf(p2, vv.z, o_[2][2]); o_[2][3] = fmaf(p2, vv.w, o_[2][3]);
            o_[3][0] = fmaf(p3, vv.x, o_[3][0]); o_[3][1] = fmaf(p3, vv.y, o_[3][1]);
            o_[3][2] = fmaf(p3, vv.z, o_[3][2]); o_[3][3] = fmaf(p3, vv.w, o_[3][3]);
        }
    }

    // epilogue: O row / l, write to [b, q0+r, h*64 + d]
#pragma unroll
    for (int i = 0; i < 4; i++) {
        float inv = 1.0f / l_[i];
        float4 v;
        v.x = o_[i][0] * inv; v.y = o_[i][1] * inv;
        v.z = o_[i][2] * inv; v.w = o_[i][3] * inv;
        *(float4*)(O + (long)b * sO + (long)(q0 + ty * 4 + i) * PD + h * 64 + tx * 4) = v;
    }
}

// ---------------- launch ----------------
extern "C" void kernel_launch(void* const* d_in, const int* in_sizes, int n_in,
                              void* d_out, int out_size) {
    const float* x         = (const float*)d_in[0];
    const float* coords    = (const float*)d_in[1];
    const void*  is_ctx    = d_in[2];               // dtype detected on device
    const float* rope      = (const float*)d_in[3];
    const float* ctx_in_w  = (const float*)d_in[4];
    const float* ctx_in_b  = (const float*)d_in[5];
    const float* ctx_out_w = (const float*)d_in[6];
    const float* ctx_out_b = (const float*)d_in[7];
    const float* tgt_in_w  = (const float*)d_in[8];
    const float* tgt_in_b  = (const float*)d_in[9];
    const float* tgt_out_w = (const float*)d_in[10];
    const float* tgt_out_b = (const float*)d_in[11];
    float* out = (float*)d_out;

    float *xr, *qkv_ctx, *kv_tgt, *q_tgt, *o_ctx, *o_tgt;
    int* perm;
    cudaGetSymbolAddress((void**)&xr,      g_xr);
    cudaGetSymbolAddress((void**)&perm,    g_perm);
    cudaGetSymbolAddress((void**)&qkv_ctx, g_qkv_ctx);
    cudaGetSymbolAddress((void**)&kv_tgt,  g_kv_tgt);
    cudaGetSymbolAddress((void**)&q_tgt,   g_q_tgt);
    cudaGetSymbolAddress((void**)&o_ctx,   g_o_ctx);
    cudaGetSymbolAddress((void**)&o_tgt,   g_o_tgt);

    build_perm<<<PB, 32>>>(is_ctx, perm);
    rope_gather<<<PB * PK, 512>>>(x, coords, rope, perm, xr);

    dim3 blk(256);
    const long sXR = (long)PK * PD;   // per-batch stride of xr (2048 rows, ctx = first 1024)

    // ctx tokens -> ctx q,k,v (N = 3072)
    gemm_nt<<<dim3(24, 8, PB), blk>>>(xr, sXR, ctx_in_w, ctx_in_b,
                                      qkv_ctx, (long)PNC * 3072, 3072, PD, nullptr, 0);
    // ctx tokens -> tgt k,v (N = 2048; skip first 1024 rows of tgt_in_w)
    gemm_nt<<<dim3(16, 8, PB), blk>>>(xr, sXR, tgt_in_w + (long)PD * PD, tgt_in_b + PD,
                                      kv_tgt, (long)PNC * 2048, 2048, PD, nullptr, 0);
    // tgt tokens -> tgt q (N = 1024)
    gemm_nt<<<dim3(8, 8, PB), blk>>>(xr + (long)PNC * PD, sXR, tgt_in_w, tgt_in_b,
                                     q_tgt, (long)PNC * PD, PD, PD, nullptr, 0);

    // ctx self-attention
    attn<<<dim3(PNC / 64, PH, PB), blk>>>(
        qkv_ctx,        (long)PNC * 3072, 3072,
        qkv_ctx + 1024, (long)PNC * 3072, 3072,
        qkv_ctx + 2048, (long)PNC * 3072, 3072,
        o_ctx, (long)PNC * PD);
    // tgt cross-attention (kv from ctx tokens, tgt weights)
    attn<<<dim3(PNC / 64, PH, PB), blk>>>(
        q_tgt,         (long)PNC * PD,   PD,
        kv_tgt,        (long)PNC * 2048, 2048,
        kv_tgt + 1024, (long)PNC * 2048, 2048,
        o_tgt, (long)PNC * PD);

    // output projections with fused scatter to original token order
    gemm_nt<<<dim3(8, 8, PB), blk>>>(o_ctx, (long)PNC * PD, ctx_out_w, ctx_out_b,
                                     out, 0, PD, PD, perm, 0);
    gemm_nt<<<dim3(8, 8, PB), blk>>>(o_tgt, (long)PNC * PD, tgt_out_w, tgt_out_b,
                                     out, 0, PD, PD, perm, PNC);
}

// round 5
// speedup vs baseline: 1.6512x; 1.6512x over previous
#include <cuda_runtime.h>
#include <cuda_bf16.h>
#include <cstdint>

// Problem constants
#define PB   4
#define PK   2048
#define PD   1024
#define PH   16
#define PNC  1024   // NCTX = K/2

#define KCH   48        // K' = 3072 in chunks of 64
#define PANEL 8192      // bf16 elems per 128x64 tile panel (16KB)

// ---------------- scratch (device globals: allocation-free) ----------------
__device__ __align__(256) float g_xr[PB * PK * PD];
__device__ __align__(256) int   g_perm[PB * PK];
__device__ __align__(256) float g_qkv_ctx[PB * PNC * 3072];
__device__ __align__(256) float g_kv_tgt[PB * PNC * 2048];
__device__ __align__(256) float g_q_tgt[PB * PNC * PD];
__device__ __align__(256) float g_o_ctx[PB * PNC * PD];
__device__ __align__(256) float g_o_tgt[PB * PNC * PD];
// split-bf16 swizzled tile panels
__device__ __align__(256) __nv_bfloat16 g_a2 [64 * KCH * PANEL];
__device__ __align__(256) __nv_bfloat16 g_wc [24 * KCH * PANEL];
__device__ __align__(256) __nv_bfloat16 g_wt [24 * KCH * PANEL];
__device__ __align__(256) __nv_bfloat16 g_wco[ 8 * KCH * PANEL];
__device__ __align__(256) __nv_bfloat16 g_wto[ 8 * KCH * PANEL];
__device__ __align__(256) __nv_bfloat16 g_oc2[32 * KCH * PANEL];
__device__ __align__(256) __nv_bfloat16 g_ot2[32 * KCH * PANEL];

// ---------------- PTX helpers (base-PTX only: no 'a'-gated features) -------
__device__ __forceinline__ uint32_t smem_u32(const void* p) {
    uint32_t a;
    asm("{ .reg .u64 t; cvta.to.shared.u64 t, %1; cvt.u32.u64 %0, t; }" : "=r"(a) : "l"(p));
    return a;
}

__device__ __forceinline__ void cp_async16(uint32_t s, const void* g) {
    asm volatile("cp.async.cg.shared.global [%0], [%1], 16;" :: "r"(s), "l"(g));
}
#define CP_COMMIT() asm volatile("cp.async.commit_group;" ::: "memory")
#define CP_WAIT(n)  asm volatile("cp.async.wait_group %0;" :: "n"(n) : "memory")

__device__ __forceinline__ void ldmat_x4(uint32_t* r, uint32_t addr) {
    asm volatile("ldmatrix.sync.aligned.m8n8.x4.shared.b16 {%0,%1,%2,%3}, [%4];"
                 : "=r"(r[0]), "=r"(r[1]), "=r"(r[2]), "=r"(r[3]) : "r"(addr));
}

__device__ __forceinline__ void mma16816(float* c, const uint32_t* a,
                                         uint32_t b0, uint32_t b1) {
    asm volatile(
        "mma.sync.aligned.m16n8k16.row.col.f32.bf16.bf16.f32 "
        "{%0,%1,%2,%3}, {%4,%5,%6,%7}, {%8,%9}, {%0,%1,%2,%3};"
        : "+f"(c[0]), "+f"(c[1]), "+f"(c[2]), "+f"(c[3])
        : "r"(a[0]), "r"(a[1]), "r"(a[2]), "r"(a[3]), "r"(b0), "r"(b1));
}

// ---------------- perm (dtype-agnostic detection) ----------------
__global__ void build_perm(const void* __restrict__ is_ctx_raw,
                           int* __restrict__ perm) {
    const unsigned char* u8  = (const unsigned char*)is_ctx_raw;
    const unsigned int*  u32 = (const unsigned int*)is_ctx_raw;
    int b = blockIdx.x;
    int lane = threadIdx.x;

    int s = 0;
    for (int i = lane; i < 2048; i += 32) s += (int)u8[i];
#pragma unroll
    for (int off = 16; off; off >>= 1) s += __shfl_xor_sync(0xffffffffu, s, off);
    bool one_byte = (s == 1024) || (s == 255 * 1024);

    int cbase = 0, tbase = PNC;
    for (int j0 = 0; j0 < PK; j0 += 32) {
        int j = j0 + lane;
        int c = one_byte ? (u8[b * PK + j] != 0) : (u32[b * PK + j] != 0u);
        unsigned mask = __ballot_sync(0xffffffffu, c);
        int pre = __popc(mask & ((1u << lane) - 1u));
        int slot = c ? (cbase + pre) : (tbase + lane - pre);
        perm[b * PK + slot] = j;
        int nc = __popc(mask);
        cbase += nc;
        tbase += 32 - nc;
    }
}

// ---------------- RoPE + gather ----------------
__global__ __launch_bounds__(512) void rope_gather(
    const float* __restrict__ x, const float* __restrict__ coords,
    const float* __restrict__ rope) {
    int s = blockIdx.x & (PK - 1);
    int b = blockIdx.x >> 11;
    int j = g_perm[b * PK + s];
    long tokin = (long)b * PK + j;

    float cy = coords[tokin * 2 + 0];
    float cx = coords[tokin * 2 + 1];
    int ypos = (int)fminf(fmaxf(cy / 224.0f * 1023.0f, 0.0f), 1023.0f);
    int xpos = (int)fminf(fmaxf(cx / 224.0f * 1023.0f, 0.0f), 1023.0f);

    int t = threadIdx.x;
    int i = t & 255;
    int pos = (t < 256) ? xpos : ypos;
    int base = (t < 256) ? (2 * i) : (512 + 2 * i);

    float c  = rope[((long)pos * 256 + i) * 2 + 0];
    float sn = rope[((long)pos * 256 + i) * 2 + 1];
    float2 p = *(const float2*)(x + tokin * PD + base);
    float2 r;
    r.x = p.x * c - p.y * sn;
    r.y = p.x * sn + p.y * c;
    *(float2*)(g_xr + ((long)b * PK + s) * PD + base) = r;
}

// ---------------- split-bf16 conversion into SW128 swizzled panels ----------
// src: fp32 [mb_count*128, 1024] row-major.
// dst: panels [mb][48][8192].  K' pattern: X: [Ah|Al|Ah]; W: [Wh|Wh|Wl].
__global__ __launch_bounds__(256) void convert_split(
    const float* __restrict__ src, __nv_bfloat16* __restrict__ dst, int is_w) {
    int mb = blockIdx.x >> 5;
    int kb = blockIdx.x & 31;
    bool lo = (kb >= 16);
    int kc0 = (kb & 15) * 64;

    long pan1, pan2;
    if (!is_w) {
        pan1 = (long)mb * KCH + kb;
        pan2 = (kb < 16) ? ((long)mb * KCH + 32 + kb) : -1;
    } else {
        pan1 = (kb < 16) ? ((long)mb * KCH + kb) : ((long)mb * KCH + 16 + kb);
        pan2 = (kb < 16) ? ((long)mb * KCH + 16 + kb) : -1;
    }

    int t = threadIdx.x;
#pragma unroll
    for (int q = 0; q < 4; q++) {
        int ch = t + q * 256;              // 16B chunk id, 0..1023
        int r = ch >> 3;
        int c0 = (ch & 7) * 8;
        const float* sp = src + ((long)mb * 128 + r) * 1024 + kc0 + c0;
        float4 f0 = *(const float4*)sp;
        float4 f1 = *(const float4*)(sp + 4);
        float vals[8] = {f0.x, f0.y, f0.z, f0.w, f1.x, f1.y, f1.z, f1.w};
        union { __nv_bfloat16 h[8]; uint4 u; } pk;
#pragma unroll
        for (int e = 0; e < 8; e++) {
            __nv_bfloat16 hi = __float2bfloat16(vals[e]);
            if (lo) {
                pk.h[e] = __float2bfloat16(vals[e] - __bfloat162float(hi));
            } else {
                pk.h[e] = hi;
            }
        }
        uint32_t off = (uint32_t)(r * 128 + c0 * 2);
        uint32_t sw = off ^ ((off >> 3) & 0x70);
        *(uint4*)((char*)(dst + pan1 * PANEL) + sw) = pk.u;
        if (pan2 >= 0) {
            *(uint4*)((char*)(dst + pan2 * PANEL) + sw) = pk.u;
        }
    }
}

// ---------------- HMMA bf16 GEMM over pre-swizzled panels --------------------
// C[m,n] = sum_k' A2[m,k'] W2[n,k'] + bias[n].  Tile 128x128, K'=3072.
// 8 warps: wm = wid&3 (32 rows each), wn = wid>>2 (64 cols each).
// Each warp: 2 m-tiles x 8 n-tiles of mma.m16n8k16.
__global__ __launch_bounds__(256) void gemm_mma(
    const __nv_bfloat16* __restrict__ Apan, int mb_group, int mb_stride,
    const __nv_bfloat16* __restrict__ Wpan,
    const float* __restrict__ bias,
    float* __restrict__ C, int ldc,
    const int* __restrict__ perm, int slotOff) {
    extern __shared__ char dsm[];
    uint32_t base = smem_u32(dsm);
    uint32_t tiles = (base + 1023u) & ~1023u;

    int tid = threadIdx.x;
    int wid = tid >> 5;
    int lid = tid & 31;
    int wm = wid & 3;
    int wn = wid >> 2;

    int by = blockIdx.y;
    int b = by / mb_group;
    int l = by % mb_group;
    const char* pA = (const char*)(Apan + ((long)(b * mb_stride + l) * KCH) * PANEL);
    const char* pW = (const char*)(Wpan + ((long)blockIdx.x * KCH) * PANEL);

    float acc[2][8][4];
#pragma unroll
    for (int mt = 0; mt < 2; mt++)
#pragma unroll
        for (int nt = 0; nt < 8; nt++)
#pragma unroll
            for (int e = 0; e < 4; e++) acc[mt][nt][e] = 0.0f;

    // ldmatrix lane addressing (panels are SW128-swizzled, 128B rows)
    int rA0 = wm * 32 + (lid & 15);
    int rB0 = wn * 64 + (lid & 15);
    int cb  = (lid >> 4) * 16;          // byte offset of k-half within row
    uint32_t xm = (uint32_t)((lid & 7) << 4);

    // prologue: stage 0 <- chunk 0
    {
        uint32_t sa = tiles;
#pragma unroll
        for (int q = 0; q < 4; q++) {
            int ch = tid + q * 256;
            cp_async16(sa + ch * 16, pA + ch * 16);
            cp_async16(sa + 16384 + ch * 16, pW + ch * 16);
        }
        CP_COMMIT();
    }

    for (int kb = 0; kb < KCH; kb++) {
        if (kb + 1 < KCH) {
            uint32_t sa = tiles + (uint32_t)((kb + 1) & 1) * 32768u;
            const char* gA = pA + (long)(kb + 1) * 16384;
            const char* gW = pW + (long)(kb + 1) * 16384;
#pragma unroll
            for (int q = 0; q < 4; q++) {
                int ch = tid + q * 256;
                cp_async16(sa + ch * 16, gA + ch * 16);
                cp_async16(sa + 16384 + ch * 16, gW + ch * 16);
            }
            CP_COMMIT();
            CP_WAIT(1);
        } else {
            CP_WAIT(0);
        }
        __syncthreads();

        uint32_t sA = tiles + (uint32_t)(kb & 1) * 32768u;
        uint32_t sB = sA + 16384u;
#pragma unroll
        for (int ks = 0; ks < 4; ks++) {
            uint32_t colb = (uint32_t)(cb + ks * 32) ^ xm;
            uint32_t af[2][4];
            uint32_t bf[4][4];
#pragma unroll
            for (int mt = 0; mt < 2; mt++)
                ldmat_x4(af[mt], sA + (uint32_t)(rA0 + mt * 16) * 128u + colb);
#pragma unroll
            for (int np = 0; np < 4; np++)
                ldmat_x4(bf[np], sB + (uint32_t)(rB0 + np * 16) * 128u + colb);
#pragma unroll
            for (int mt = 0; mt < 2; mt++) {
#pragma unroll
                for (int nt = 0; nt < 8; nt++) {
                    int np = nt >> 1;
                    int sel = nt & 1;
                    mma16816(acc[mt][nt], af[mt], bf[np][sel], bf[np][sel + 2]);
                }
            }
        }
        __syncthreads();
    }

    // epilogue: direct register -> gmem with bias (+ optional perm scatter)
    int n0 = blockIdx.x * 128;
#pragma unroll
    for (int nt = 0; nt < 8; nt++) {
        int cc = wn * 64 + nt * 8 + (lid & 3) * 2;
        float2 bv;
        bv.x = bias[n0 + cc];
        bv.y = bias[n0 + cc + 1];
#pragma unroll
        for (int mt = 0; mt < 2; mt++) {
            int r0 = wm * 32 + mt * 16 + (lid >> 2);
            float2 v0, v1;
            v0.x = acc[mt][nt][0] + bv.x;
            v0.y = acc[mt][nt][1] + bv.y;
            v1.x = acc[mt][nt][2] + bv.x;
            v1.y = acc[mt][nt][3] + bv.y;
            if (perm != nullptr) {
                int tok0 = perm[b * PK + l * 128 + r0 + slotOff];
                int tok1 = perm[b * PK + l * 128 + r0 + 8 + slotOff];
                *(float2*)(C + ((long)b * PK + tok0) * PD + n0 + cc) = v0;
                *(float2*)(C + ((long)b * PK + tok1) * PD + n0 + cc) = v1;
            } else {
                long row = (long)by * 128 + r0;
                *(float2*)(C + row * ldc + n0 + cc) = v0;
                *(float2*)(C + (row + 8) * ldc + n0 + cc) = v1;
            }
        }
    }
}

// ---------------- attention (fp32 flash, unchanged) ----------------
__global__ __launch_bounds__(256) void attn(
    const float* __restrict__ Q, long sQ, int ldq,
    const float* __restrict__ Kp, long sK, int ldk,
    const float* __restrict__ Vp, long sV, int ldv,
    float* __restrict__ O, long sO) {
    __shared__ float Qs[64 * 64];
    __shared__ float KP[64 * 64];
    __shared__ float Vs[64 * 64];

    int b = blockIdx.z;
    int h = blockIdx.y;
    int q0 = blockIdx.x * 64;
    const float* Qb = Q + (long)b * sQ + h * 64;
    const float* Kb = Kp + (long)b * sK + h * 64;
    const float* Vb = Vp + (long)b * sV + h * 64;

    int tid = threadIdx.x;
    int tx = tid & 15;
    int ty = tid >> 4;
    int lrow = tid >> 2;
    int ld0 = (tid & 3) * 16;

    {
        const float* src = Qb + (long)(q0 + lrow) * ldq + ld0;
#pragma unroll
        for (int u = 0; u < 4; u++) {
            float4 v = *(const float4*)(src + u * 4);
            *(float4*)&Qs[lrow * 64 + ld0 + u * 4] = v;
        }
    }

    float m_[4], l_[4], o_[4][4];
#pragma unroll
    for (int i = 0; i < 4; i++) {
        m_[i] = -1e30f;
        l_[i] = 0.0f;
#pragma unroll
        for (int j = 0; j < 4; j++) o_[i][j] = 0.0f;
    }

    for (int kt = 0; kt < PNC; kt += 64) {
        __syncthreads();
        {
            const float* ks = Kb + (long)(kt + lrow) * ldk + ld0;
            const float* vs = Vb + (long)(kt + lrow) * ldv + ld0;
#pragma unroll
            for (int u = 0; u < 4; u++) {
                float4 kv = *(const float4*)(ks + u * 4);
                int d = ld0 + u * 4;
                KP[(d + 0) * 64 + lrow] = kv.x;
                KP[(d + 1) * 64 + lrow] = kv.y;
                KP[(d + 2) * 64 + lrow] = kv.z;
                KP[(d + 3) * 64 + lrow] = kv.w;
                float4 vv = *(const float4*)(vs + u * 4);
                *(float4*)&Vs[lrow * 64 + d] = vv;
            }
        }
        __syncthreads();

        float s_[4][4];
#pragma unroll
        for (int i = 0; i < 4; i++) {
#pragma unroll
            for (int j = 0; j < 4; j++) s_[i][j] = 0.0f;
        }
#pragma unroll 4
        for (int d = 0; d < 64; d++) {
            float4 kv = *(const float4*)&KP[d * 64 + tx * 4];
            float a0 = Qs[(ty * 4 + 0) * 64 + d];
            float a1 = Qs[(ty * 4 + 1) * 64 + d];
            float a2 = Qs[(ty * 4 + 2) * 64 + d];
            float a3 = Qs[(ty * 4 + 3) * 64 + d];
            s_[0][0] = fmaf(a0, kv.x, s_[0][0]); s_[0][1] = fmaf(a0, kv.y, s_[0][1]);
            s_[0][2] = fmaf(a0, kv.z, s_[0][2]); s_[0][3] = fmaf(a0, kv.w, s_[0][3]);
            s_[1][0] = fmaf(a1, kv.x, s_[1][0]); s_[1][1] = fmaf(a1, kv.y, s_[1][1]);
            s_[1][2] = fmaf(a1, kv.z, s_[1][2]); s_[1][3] = fmaf(a1, kv.w, s_[1][3]);
            s_[2][0] = fmaf(a2, kv.x, s_[2][0]); s_[2][1] = fmaf(a2, kv.y, s_[2][1]);
            s_[2][2] = fmaf(a2, kv.z, s_[2][2]); s_[2][3] = fmaf(a2, kv.w, s_[2][3]);
            s_[3][0] = fmaf(a3, kv.x, s_[3][0]); s_[3][1] = fmaf(a3, kv.y, s_[3][1]);
            s_[3][2] = fmaf(a3, kv.z, s_[3][2]); s_[3][3] = fmaf(a3, kv.w, s_[3][3]);
        }

#pragma unroll
        for (int i = 0; i < 4; i++) {
#pragma unroll
            for (int j = 0; j < 4; j++) s_[i][j] *= 0.125f;
            float mt = fmaxf(fmaxf(s_[i][0], s_[i][1]), fmaxf(s_[i][2], s_[i][3]));
#pragma unroll
            for (int off = 1; off < 16; off <<= 1) {
                mt = fmaxf(mt, __shfl_xor_sync(0xffffffffu, mt, off));
            }
            float mnew = fmaxf(m_[i], mt);
            float alpha = __expf(m_[i] - mnew);
            float ps = 0.0f;
#pragma unroll
            for (int j = 0; j < 4; j++) {
                float p = __expf(s_[i][j] - mnew);
                s_[i][j] = p;
                ps += p;
            }
#pragma unroll
            for (int off = 1; off < 16; off <<= 1) {
                ps += __shfl_xor_sync(0xffffffffu, ps, off);
            }
            l_[i] = l_[i] * alpha + ps;
            m_[i] = mnew;
#pragma unroll
            for (int j = 0; j < 4; j++) o_[i][j] *= alpha;
        }

        __syncthreads();
#pragma unroll
        for (int i = 0; i < 4; i++) {
            float4 pv;
            pv.x = s_[i][0]; pv.y = s_[i][1]; pv.z = s_[i][2]; pv.w = s_[i][3];
            *(float4*)&KP[(ty * 4 + i) * 64 + tx * 4] = pv;
        }
        __syncthreads();

#pragma unroll 4
        for (int c = 0; c < 64; c++) {
            float4 vv = *(const float4*)&Vs[c * 64 + tx * 4];
            float p0 = KP[(ty * 4 + 0) * 64 + c];
            float p1 = KP[(ty * 4 + 1) * 64 + c];
            float p2 = KP[(ty * 4 + 2) * 64 + c];
            float p3 = KP[(ty * 4 + 3) * 64 + c];
            o_[0][0] = fmaf(p0, vv.x, o_[0][0]); o_[0][1] = fmaf(p0, vv.y, o_[0][1]);
            o_[0][2] = fmaf(p0, vv.z, o_[0][2]); o_[0][3] = fmaf(p0, vv.w, o_[0][3]);
            o_[1][0] = fmaf(p1, vv.x, o_[1][0]); o_[1][1] = fmaf(p1, vv.y, o_[1][1]);
            o_[1][2] = fmaf(p1, vv.z, o_[1][2]); o_[1][3] = fmaf(p1, vv.w, o_[1][3]);
            o_[2][0] = fmaf(p2, vv.x, o_[2][0]); o_[2][1] = fmaf(p2, vv.y, o_[2][1]);
            o_[2][2] = fmaf(p2, vv.z, o_[2][2]); o_[2][3] = fmaf(p2, vv.w, o_[2][3]);
            o_[3][0] = fmaf(p3, vv.x, o_[3][0]); o_[3][1] = fmaf(p3, vv.y, o_[3][1]);
            o_[3][2] = fmaf(p3, vv.z, o_[3][2]); o_[3][3] = fmaf(p3, vv.w, o_[3][3]);
        }
    }

#pragma unroll
    for (int i = 0; i < 4; i++) {
        float inv = 1.0f / l_[i];
        float4 v;
        v.x = o_[i][0] * inv; v.y = o_[i][1] * inv;
        v.z = o_[i][2] * inv; v.w = o_[i][3] * inv;
        *(float4*)(O + (long)b * sO + (long)(q0 + ty * 4 + i) * PD + h * 64 + tx * 4) = v;
    }
}

// ---------------- launch ----------------
extern "C" void kernel_launch(void* const* d_in, const int* in_sizes, int n_in,
                              void* d_out, int out_size) {
    const float* x         = (const float*)d_in[0];
    const float* coords    = (const float*)d_in[1];
    const void*  is_ctx    = d_in[2];
    const float* rope      = (const float*)d_in[3];
    const float* ctx_in_w  = (const float*)d_in[4];
    const float* ctx_in_b  = (const float*)d_in[5];
    const float* ctx_out_w = (const float*)d_in[6];
    const float* ctx_out_b = (const float*)d_in[7];
    const float* tgt_in_w  = (const float*)d_in[8];
    const float* tgt_in_b  = (const float*)d_in[9];
    const float* tgt_out_w = (const float*)d_in[10];
    const float* tgt_out_b = (const float*)d_in[11];
    float* out = (float*)d_out;

    float* xr = 0;      cudaGetSymbolAddress((void**)&xr, g_xr);
    int* perm = 0;      cudaGetSymbolAddress((void**)&perm, g_perm);
    float* qkv_ctx = 0; cudaGetSymbolAddress((void**)&qkv_ctx, g_qkv_ctx);
    float* kv_tgt = 0;  cudaGetSymbolAddress((void**)&kv_tgt, g_kv_tgt);
    float* q_tgt = 0;   cudaGetSymbolAddress((void**)&q_tgt, g_q_tgt);
    float* o_ctx = 0;   cudaGetSymbolAddress((void**)&o_ctx, g_o_ctx);
    float* o_tgt = 0;   cudaGetSymbolAddress((void**)&o_tgt, g_o_tgt);
    __nv_bfloat16* a2 = 0;  cudaGetSymbolAddress((void**)&a2, g_a2);
    __nv_bfloat16* wc = 0;  cudaGetSymbolAddress((void**)&wc, g_wc);
    __nv_bfloat16* wt = 0;  cudaGetSymbolAddress((void**)&wt, g_wt);
    __nv_bfloat16* wco = 0; cudaGetSymbolAddress((void**)&wco, g_wco);
    __nv_bfloat16* wto = 0; cudaGetSymbolAddress((void**)&wto, g_wto);
    __nv_bfloat16* oc2 = 0; cudaGetSymbolAddress((void**)&oc2, g_oc2);
    __nv_bfloat16* ot2 = 0; cudaGetSymbolAddress((void**)&ot2, g_ot2);

    const int GSM = 66560;   // 1KB align pad + 2 x 32KB stages
    cudaFuncSetAttribute(gemm_mma, cudaFuncAttributeMaxDynamicSharedMemorySize, GSM);

    build_perm<<<PB, 32>>>(is_ctx, perm);
    rope_gather<<<PB * PK, 512>>>(x, coords, rope);

    // conversions to split-bf16 swizzled panels
    convert_split<<<64 * 32, 256>>>(xr,        a2,  0);
    convert_split<<<24 * 32, 256>>>(ctx_in_w,  wc,  1);
    convert_split<<<24 * 32, 256>>>(tgt_in_w,  wt,  1);
    convert_split<<< 8 * 32, 256>>>(ctx_out_w, wco, 1);
    convert_split<<< 8 * 32, 256>>>(tgt_out_w, wto, 1);

    // projections on HMMA tensor cores (K' = 3072)
    gemm_mma<<<dim3(24, 32), 256, GSM>>>(a2, 8, 16, wc, ctx_in_b,
                                         qkv_ctx, 3072, nullptr, 0);
    gemm_mma<<<dim3(16, 32), 256, GSM>>>(a2, 8, 16, wt + (long)8 * KCH * PANEL,
                                         tgt_in_b + 1024, kv_tgt, 2048, nullptr, 0);
    gemm_mma<<<dim3(8, 32), 256, GSM>>>(a2 + (long)8 * KCH * PANEL, 8, 16, wt,
                                        tgt_in_b, q_tgt, 1024, nullptr, 0);

    // attention (fp32)
    attn<<<dim3(PNC / 64, PH, PB), 256>>>(
        qkv_ctx,        (long)PNC * 3072, 3072,
        qkv_ctx + 1024, (long)PNC * 3072, 3072,
        qkv_ctx + 2048, (long)PNC * 3072, 3072,
        o_ctx, (long)PNC * PD);
    attn<<<dim3(PNC / 64, PH, PB), 256>>>(
        q_tgt,         (long)PNC * PD,   PD,
        kv_tgt,        (long)PNC * 2048, 2048,
        kv_tgt + 1024, (long)PNC * 2048, 2048,
        o_tgt, (long)PNC * PD);

    // output projections (convert attn outputs, then HMMA + fused scatter)
    convert_split<<<32 * 32, 256>>>(o_ctx, oc2, 0);
    convert_split<<<32 * 32, 256>>>(o_tgt, ot2, 0);
    gemm_mma<<<dim3(8, 32), 256, GSM>>>(oc2, 8, 8, wco, ctx_out_b,
                                        out, PD, perm, 0);
    gemm_mma<<<dim3(8, 32), 256, GSM>>>(ot2, 8, 8, wto, tgt_out_b,
                                        out, PD, perm, PNC);
}

// round 6
// speedup vs baseline: 2.7831x; 1.6855x over previous
#include <cuda_runtime.h>
#include <cuda_bf16.h>
#include <cstdint>

// Problem constants
#define PB   4
#define PK   2048
#define PD   1024
#define PH   16
#define PNC  1024   // NCTX = K/2

#define KCH   48        // K' = 3072 in chunks of 64
#define PANEL 8192      // bf16 elems per 128x64 tile panel (16KB)
#define APAN  4096      // bf16 elems per 64x64 attention panel (8KB)
#define ATT_T (PB * PH * 16 * APAN)

// ---------------- scratch (device globals: allocation-free) ----------------
__device__ __align__(256) float g_xr[PB * PK * PD];
__device__ __align__(256) int   g_perm[PB * PK];
__device__ __align__(256) float g_qkv_ctx[PB * PNC * 3072];
__device__ __align__(256) float g_kv_tgt[PB * PNC * 2048];
__device__ __align__(256) float g_q_tgt[PB * PNC * PD];
__device__ __align__(256) float g_o_ctx[PB * PNC * PD];
__device__ __align__(256) float g_o_tgt[PB * PNC * PD];
// split-bf16 swizzled tile panels (GEMM)
__device__ __align__(256) __nv_bfloat16 g_a2 [64 * KCH * PANEL];
__device__ __align__(256) __nv_bfloat16 g_wc [24 * KCH * PANEL];
__device__ __align__(256) __nv_bfloat16 g_wt [24 * KCH * PANEL];
__device__ __align__(256) __nv_bfloat16 g_wco[ 8 * KCH * PANEL];
__device__ __align__(256) __nv_bfloat16 g_wto[ 8 * KCH * PANEL];
__device__ __align__(256) __nv_bfloat16 g_oc2[32 * KCH * PANEL];
__device__ __align__(256) __nv_bfloat16 g_ot2[32 * KCH * PANEL];
// attention split-bf16 panels: 0..5 ctx {Qh,Ql,Kh,Kl,Vh,Vl}, 6..11 tgt
__device__ __align__(256) __nv_bfloat16 g_ap[12ll * ATT_T];

// ---------------- PTX helpers (base-PTX only) ----------------
__device__ __forceinline__ uint32_t smem_u32(const void* p) {
    uint32_t a;
    asm("{ .reg .u64 t; cvta.to.shared.u64 t, %1; cvt.u32.u64 %0, t; }" : "=r"(a) : "l"(p));
    return a;
}

__device__ __forceinline__ void cp_async16(uint32_t s, const void* g) {
    asm volatile("cp.async.cg.shared.global [%0], [%1], 16;" :: "r"(s), "l"(g));
}
#define CP_COMMIT() asm volatile("cp.async.commit_group;" ::: "memory")
#define CP_WAIT(n)  asm volatile("cp.async.wait_group %0;" :: "n"(n) : "memory")

__device__ __forceinline__ void ldmat_x4(uint32_t* r, uint32_t addr) {
    asm volatile("ldmatrix.sync.aligned.m8n8.x4.shared.b16 {%0,%1,%2,%3}, [%4];"
                 : "=r"(r[0]), "=r"(r[1]), "=r"(r[2]), "=r"(r[3]) : "r"(addr));
}

__device__ __forceinline__ void ldmat_x4_trans(uint32_t* r, uint32_t addr) {
    asm volatile("ldmatrix.sync.aligned.m8n8.x4.trans.shared.b16 {%0,%1,%2,%3}, [%4];"
                 : "=r"(r[0]), "=r"(r[1]), "=r"(r[2]), "=r"(r[3]) : "r"(addr));
}

__device__ __forceinline__ void mma16816(float* c, const uint32_t* a,
                                         uint32_t b0, uint32_t b1) {
    asm volatile(
        "mma.sync.aligned.m16n8k16.row.col.f32.bf16.bf16.f32 "
        "{%0,%1,%2,%3}, {%4,%5,%6,%7}, {%8,%9}, {%0,%1,%2,%3};"
        : "+f"(c[0]), "+f"(c[1]), "+f"(c[2]), "+f"(c[3])
        : "r"(a[0]), "r"(a[1]), "r"(a[2]), "r"(a[3]), "r"(b0), "r"(b1));
}

// pack two f32 into bf16x2 (lo in low 16 bits)
__device__ __forceinline__ uint32_t pack_bf16x2(float lo, float hi) {
    uint32_t r;
    asm("cvt.rn.bf16x2.f32 %0, %1, %2;" : "=r"(r) : "f"(hi), "f"(lo));
    return r;
}

// ---------------- perm (dtype-agnostic detection) ----------------
__global__ void build_perm(const void* __restrict__ is_ctx_raw,
                           int* __restrict__ perm) {
    const unsigned char* u8  = (const unsigned char*)is_ctx_raw;
    const unsigned int*  u32 = (const unsigned int*)is_ctx_raw;
    int b = blockIdx.x;
    int lane = threadIdx.x;

    int s = 0;
    for (int i = lane; i < 2048; i += 32) s += (int)u8[i];
#pragma unroll
    for (int off = 16; off; off >>= 1) s += __shfl_xor_sync(0xffffffffu, s, off);
    bool one_byte = (s == 1024) || (s == 255 * 1024);

    int cbase = 0, tbase = PNC;
    for (int j0 = 0; j0 < PK; j0 += 32) {
        int j = j0 + lane;
        int c = one_byte ? (u8[b * PK + j] != 0) : (u32[b * PK + j] != 0u);
        unsigned mask = __ballot_sync(0xffffffffu, c);
        int pre = __popc(mask & ((1u << lane) - 1u));
        int slot = c ? (cbase + pre) : (tbase + lane - pre);
        perm[b * PK + slot] = j;
        int nc = __popc(mask);
        cbase += nc;
        tbase += 32 - nc;
    }
}

// ---------------- RoPE + gather ----------------
__global__ __launch_bounds__(512) void rope_gather(
    const float* __restrict__ x, const float* __restrict__ coords,
    const float* __restrict__ rope) {
    int s = blockIdx.x & (PK - 1);
    int b = blockIdx.x >> 11;
    int j = g_perm[b * PK + s];
    long tokin = (long)b * PK + j;

    float cy = coords[tokin * 2 + 0];
    float cx = coords[tokin * 2 + 1];
    int ypos = (int)fminf(fmaxf(cy / 224.0f * 1023.0f, 0.0f), 1023.0f);
    int xpos = (int)fminf(fmaxf(cx / 224.0f * 1023.0f, 0.0f), 1023.0f);

    int t = threadIdx.x;
    int i = t & 255;
    int pos = (t < 256) ? xpos : ypos;
    int base = (t < 256) ? (2 * i) : (512 + 2 * i);

    float c  = rope[((long)pos * 256 + i) * 2 + 0];
    float sn = rope[((long)pos * 256 + i) * 2 + 1];
    float2 p = *(const float2*)(x + tokin * PD + base);
    float2 r;
    r.x = p.x * c - p.y * sn;
    r.y = p.x * sn + p.y * c;
    *(float2*)(g_xr + ((long)b * PK + s) * PD + base) = r;
}

// ---------------- split-bf16 conversion into SW128 swizzled GEMM panels -----
__global__ __launch_bounds__(256) void convert_split(
    const float* __restrict__ src, __nv_bfloat16* __restrict__ dst, int is_w) {
    int mb = blockIdx.x >> 5;
    int kb = blockIdx.x & 31;
    bool lo = (kb >= 16);
    int kc0 = (kb & 15) * 64;

    long pan1, pan2;
    if (!is_w) {
        pan1 = (long)mb * KCH + kb;
        pan2 = (kb < 16) ? ((long)mb * KCH + 32 + kb) : -1;
    } else {
        pan1 = (kb < 16) ? ((long)mb * KCH + kb) : ((long)mb * KCH + 16 + kb);
        pan2 = (kb < 16) ? ((long)mb * KCH + 16 + kb) : -1;
    }

    int t = threadIdx.x;
#pragma unroll
    for (int q = 0; q < 4; q++) {
        int ch = t + q * 256;
        int r = ch >> 3;
        int c0 = (ch & 7) * 8;
        const float* sp = src + ((long)mb * 128 + r) * 1024 + kc0 + c0;
        float4 f0 = *(const float4*)sp;
        float4 f1 = *(const float4*)(sp + 4);
        float vals[8] = {f0.x, f0.y, f0.z, f0.w, f1.x, f1.y, f1.z, f1.w};
        union { __nv_bfloat16 h[8]; uint4 u; } pk;
#pragma unroll
        for (int e = 0; e < 8; e++) {
            __nv_bfloat16 hi = __float2bfloat16(vals[e]);
            if (lo) {
                pk.h[e] = __float2bfloat16(vals[e] - __bfloat162float(hi));
            } else {
                pk.h[e] = hi;
            }
        }
        uint32_t off = (uint32_t)(r * 128 + c0 * 2);
        uint32_t sw = off ^ ((off >> 3) & 0x70);
        *(uint4*)((char*)(dst + pan1 * PANEL) + sw) = pk.u;
        if (pan2 >= 0) {
            *(uint4*)((char*)(dst + pan2 * PANEL) + sw) = pk.u;
        }
    }
}

// ---------------- conversion fp32 -> attention hi/lo panels -----------------
// src row-major [b][1024 tok][ld]; panel (b,h,kt): 64 rows x 64 cols swizzled.
__global__ __launch_bounds__(256) void convert_attn(
    const float* __restrict__ src, int ld, int colOff, float scale,
    __nv_bfloat16* __restrict__ dhi, __nv_bfloat16* __restrict__ dlo) {
    int kt = blockIdx.x, h = blockIdx.y, b = blockIdx.z;
    long pan = (((long)b * PH + h) * 16 + kt) * APAN;
    int t = threadIdx.x;
#pragma unroll
    for (int q = 0; q < 2; q++) {
        int ch = t + q * 256;           // 0..511
        int r = ch >> 3;
        int c0 = (ch & 7) * 8;
        const float* sp = src + ((long)b * PNC + kt * 64 + r) * ld + colOff + h * 64 + c0;
        float4 f0 = *(const float4*)sp;
        float4 f1 = *(const float4*)(sp + 4);
        float vals[8] = {f0.x, f0.y, f0.z, f0.w, f1.x, f1.y, f1.z, f1.w};
        union { __nv_bfloat16 h2[8]; uint4 u; } ph, pl;
#pragma unroll
        for (int e = 0; e < 8; e++) {
            float v = vals[e] * scale;
            __nv_bfloat16 hi = __float2bfloat16(v);
            ph.h2[e] = hi;
            pl.h2[e] = __float2bfloat16(v - __bfloat162float(hi));
        }
        uint32_t off = (uint32_t)(r * 128 + c0 * 2);
        uint32_t sw = off ^ ((off >> 3) & 0x70);
        *(uint4*)((char*)(dhi + pan) + sw) = ph.u;
        *(uint4*)((char*)(dlo + pan) + sw) = pl.u;
    }
}

// ---------------- HMMA bf16 GEMM over pre-swizzled panels --------------------
__global__ __launch_bounds__(256) void gemm_mma(
    const __nv_bfloat16* __restrict__ Apan, int mb_group, int mb_stride,
    const __nv_bfloat16* __restrict__ Wpan,
    const float* __restrict__ bias,
    float* __restrict__ C, int ldc,
    const int* __restrict__ perm, int slotOff) {
    extern __shared__ char dsm[];
    uint32_t base = smem_u32(dsm);
    uint32_t tiles = (base + 1023u) & ~1023u;

    int tid = threadIdx.x;
    int wid = tid >> 5;
    int lid = tid & 31;
    int wm = wid & 3;
    int wn = wid >> 2;

    int by = blockIdx.y;
    int b = by / mb_group;
    int l = by % mb_group;
    const char* pA = (const char*)(Apan + ((long)(b * mb_stride + l) * KCH) * PANEL);
    const char* pW = (const char*)(Wpan + ((long)blockIdx.x * KCH) * PANEL);

    float acc[2][8][4];
#pragma unroll
    for (int mt = 0; mt < 2; mt++)
#pragma unroll
        for (int nt = 0; nt < 8; nt++)
#pragma unroll
            for (int e = 0; e < 4; e++) acc[mt][nt][e] = 0.0f;

    int rA0 = wm * 32 + (lid & 15);
    int rB0 = wn * 64 + (lid & 15);
    int cb  = (lid >> 4) * 16;
    uint32_t xm = (uint32_t)((lid & 7) << 4);

    {
        uint32_t sa = tiles;
#pragma unroll
        for (int q = 0; q < 4; q++) {
            int ch = tid + q * 256;
            cp_async16(sa + ch * 16, pA + ch * 16);
            cp_async16(sa + 16384 + ch * 16, pW + ch * 16);
        }
        CP_COMMIT();
    }

    for (int kb = 0; kb < KCH; kb++) {
        if (kb + 1 < KCH) {
            uint32_t sa = tiles + (uint32_t)((kb + 1) & 1) * 32768u;
            const char* gA = pA + (long)(kb + 1) * 16384;
            const char* gW = pW + (long)(kb + 1) * 16384;
#pragma unroll
            for (int q = 0; q < 4; q++) {
                int ch = tid + q * 256;
                cp_async16(sa + ch * 16, gA + ch * 16);
                cp_async16(sa + 16384 + ch * 16, gW + ch * 16);
            }
            CP_COMMIT();
            CP_WAIT(1);
        } else {
            CP_WAIT(0);
        }
        __syncthreads();

        uint32_t sA = tiles + (uint32_t)(kb & 1) * 32768u;
        uint32_t sB = sA + 16384u;
#pragma unroll
        for (int ks = 0; ks < 4; ks++) {
            uint32_t colb = (uint32_t)(cb + ks * 32) ^ xm;
            uint32_t af[2][4];
            uint32_t bf[4][4];
#pragma unroll
            for (int mt = 0; mt < 2; mt++)
                ldmat_x4(af[mt], sA + (uint32_t)(rA0 + mt * 16) * 128u + colb);
#pragma unroll
            for (int np = 0; np < 4; np++)
                ldmat_x4(bf[np], sB + (uint32_t)(rB0 + np * 16) * 128u + colb);
#pragma unroll
            for (int mt = 0; mt < 2; mt++) {
#pragma unroll
                for (int nt = 0; nt < 8; nt++) {
                    int np = nt >> 1;
                    int sel = nt & 1;
                    mma16816(acc[mt][nt], af[mt], bf[np][sel], bf[np][sel + 2]);
                }
            }
        }
        __syncthreads();
    }

    int n0 = blockIdx.x * 128;
#pragma unroll
    for (int nt = 0; nt < 8; nt++) {
        int cc = wn * 64 + nt * 8 + (lid & 3) * 2;
        float2 bv;
        bv.x = bias[n0 + cc];
        bv.y = bias[n0 + cc + 1];
#pragma unroll
        for (int mt = 0; mt < 2; mt++) {
            int r0 = wm * 32 + mt * 16 + (lid >> 2);
            float2 v0, v1;
            v0.x = acc[mt][nt][0] + bv.x;
            v0.y = acc[mt][nt][1] + bv.y;
            v1.x = acc[mt][nt][2] + bv.x;
            v1.y = acc[mt][nt][3] + bv.y;
            if (perm != nullptr) {
                int tok0 = perm[b * PK + l * 128 + r0 + slotOff];
                int tok1 = perm[b * PK + l * 128 + r0 + 8 + slotOff];
                *(float2*)(C + ((long)b * PK + tok0) * PD + n0 + cc) = v0;
                *(float2*)(C + ((long)b * PK + tok1) * PD + n0 + cc) = v1;
            } else {
                long row = (long)by * 128 + r0;
                *(float2*)(C + row * ldc + n0 + cc) = v0;
                *(float2*)(C + (row + 8) * ldc + n0 + cc) = v1;
            }
        }
    }
}

// ---------------- HMMA flash attention (split-bf16, 3-term) -----------------
// block = (qtile 128, h, b), 8 warps x m16. Keys = 1024 in 16 tiles of 64.
__global__ __launch_bounds__(256) void attn_mma(
    const __nv_bfloat16* __restrict__ Aqh, const __nv_bfloat16* __restrict__ Aql,
    const __nv_bfloat16* __restrict__ Akh, const __nv_bfloat16* __restrict__ Akl,
    const __nv_bfloat16* __restrict__ Avh, const __nv_bfloat16* __restrict__ Avl,
    float* __restrict__ O) {
    extern __shared__ char dsm[];
    uint32_t base = smem_u32(dsm);
    uint32_t sQ = (base + 1023u) & ~1023u;     // Qh 16KB | Ql 16KB
    uint32_t sT = sQ + 32768u;                  // 2 stages x [Kh|Kl|Vh|Vl] 8KB each

    int tid = threadIdx.x, wid = tid >> 5, lid = tid & 31;
    int qt = blockIdx.x, h = blockIdx.y, b = blockIdx.z;
    long pb = ((long)b * PH + h) * 16;

    const char* pQh = (const char*)(Aqh + (pb + qt * 2) * APAN);
    const char* pQl = (const char*)(Aql + (pb + qt * 2) * APAN);
    const char* pKh = (const char*)(Akh + pb * APAN);
    const char* pKl = (const char*)(Akl + pb * APAN);
    const char* pVh = (const char*)(Avh + pb * APAN);
    const char* pVl = (const char*)(Avl + pb * APAN);

    // prologue: Q (32KB) + tile 0 (32KB)
#pragma unroll
    for (int q = 0; q < 8; q++) {
        int ch = tid + q * 256;
        int idx = ch & 1023;
        if (q < 4) cp_async16(sQ + idx * 16, pQh + idx * 16);
        else       cp_async16(sQ + 16384 + idx * 16, pQl + idx * 16);
    }
#pragma unroll
    for (int q = 0; q < 8; q++) {
        int ch = tid + q * 256;
        int idx = ch & 511;
        const char* s = (q < 2) ? pKh : (q < 4) ? pKl : (q < 6) ? pVh : pVl;
        cp_async16(sT + ch * 16, s + idx * 16);
    }
    CP_COMMIT();
    CP_WAIT(0);
    __syncthreads();

    int cb = (lid >> 4) * 16;
    uint32_t xm = (uint32_t)((lid & 7) << 4);

    // cache Q fragments (A-frags) in registers
    uint32_t qra = sQ + (uint32_t)(wid >> 2) * 8192u
                 + (uint32_t)(((wid & 3) * 16 + (lid & 15)) * 128);
    uint32_t qhf[4][4], qlf[4][4];
#pragma unroll
    for (int ks = 0; ks < 4; ks++) {
        uint32_t col = (uint32_t)(ks * 32 + cb) ^ xm;
        ldmat_x4(qhf[ks], qra + col);
        ldmat_x4(qlf[ks], qra + 16384u + col);
    }

    float m0 = -1e30f, m1 = -1e30f, l0 = 0.0f, l1 = 0.0f;
    float oa[8][4];
#pragma unroll
    for (int nt = 0; nt < 8; nt++)
#pragma unroll
        for (int e = 0; e < 4; e++) oa[nt][e] = 0.0f;

    for (int kt = 0; kt < 16; kt++) {
        uint32_t st = sT + (uint32_t)(kt & 1) * 32768u;
        if (kt + 1 < 16) {
            uint32_t sn = sT + (uint32_t)((kt + 1) & 1) * 32768u;
            long off = (long)(kt + 1) * 8192;
#pragma unroll
            for (int q = 0; q < 8; q++) {
                int ch = tid + q * 256;
                int idx = ch & 511;
                const char* s = (q < 2) ? pKh : (q < 4) ? pKl : (q < 6) ? pVh : pVl;
                cp_async16(sn + ch * 16, s + off + idx * 16);
            }
            CP_COMMIT();
        }

        // ---- S = Qs K^T (3-term split) ----
        float sc[8][4];
#pragma unroll
        for (int nt = 0; nt < 8; nt++)
#pragma unroll
            for (int e = 0; e < 4; e++) sc[nt][e] = 0.0f;

#pragma unroll
        for (int ks = 0; ks < 4; ks++) {
            uint32_t col = (uint32_t)(ks * 32 + cb) ^ xm;
            uint32_t bh_[4][4], bl_[4][4];
#pragma unroll
            for (int np = 0; np < 4; np++) {
                uint32_t ra = (uint32_t)((np * 16 + (lid & 15)) * 128);
                ldmat_x4(bh_[np], st + ra + col);
                ldmat_x4(bl_[np], st + 8192u + ra + col);
            }
#pragma unroll
            for (int nt = 0; nt < 8; nt++) {
                int np = nt >> 1, sel = nt & 1;
                mma16816(sc[nt], qhf[ks], bh_[np][sel], bh_[np][sel + 2]);
                mma16816(sc[nt], qlf[ks], bh_[np][sel], bh_[np][sel + 2]);
                mma16816(sc[nt], qhf[ks], bl_[np][sel], bl_[np][sel + 2]);
            }
        }

        // ---- online softmax (rows lid>>2 and lid>>2 + 8) ----
        float mt0 = -1e30f, mt1 = -1e30f;
#pragma unroll
        for (int nt = 0; nt < 8; nt++) {
            mt0 = fmaxf(mt0, fmaxf(sc[nt][0], sc[nt][1]));
            mt1 = fmaxf(mt1, fmaxf(sc[nt][2], sc[nt][3]));
        }
        mt0 = fmaxf(mt0, __shfl_xor_sync(0xffffffffu, mt0, 1));
        mt0 = fmaxf(mt0, __shfl_xor_sync(0xffffffffu, mt0, 2));
        mt1 = fmaxf(mt1, __shfl_xor_sync(0xffffffffu, mt1, 1));
        mt1 = fmaxf(mt1, __shfl_xor_sync(0xffffffffu, mt1, 2));

        float mn0 = fmaxf(m0, mt0), mn1 = fmaxf(m1, mt1);
        float a0 = __expf(m0 - mn0), a1 = __expf(m1 - mn1);

        uint32_t php[8][2], plp[8][2];
        float ps0 = 0.0f, ps1 = 0.0f;
#pragma unroll
        for (int nt = 0; nt < 8; nt++) {
            float p00 = __expf(sc[nt][0] - mn0);
            float p01 = __expf(sc[nt][1] - mn0);
            float p10 = __expf(sc[nt][2] - mn1);
            float p11 = __expf(sc[nt][3] - mn1);
            ps0 += p00 + p01;
            ps1 += p10 + p11;
            php[nt][0] = pack_bf16x2(p00, p01);
            php[nt][1] = pack_bf16x2(p10, p11);
            float q00 = __bfloat162float(__float2bfloat16(p00));
            float q01 = __bfloat162float(__float2bfloat16(p01));
            float q10 = __bfloat162float(__float2bfloat16(p10));
            float q11 = __bfloat162float(__float2bfloat16(p11));
            plp[nt][0] = pack_bf16x2(p00 - q00, p01 - q01);
            plp[nt][1] = pack_bf16x2(p10 - q10, p11 - q11);
        }
        ps0 += __shfl_xor_sync(0xffffffffu, ps0, 1);
        ps0 += __shfl_xor_sync(0xffffffffu, ps0, 2);
        ps1 += __shfl_xor_sync(0xffffffffu, ps1, 1);
        ps1 += __shfl_xor_sync(0xffffffffu, ps1, 2);

        l0 = l0 * a0 + ps0;
        l1 = l1 * a1 + ps1;
        m0 = mn0;
        m1 = mn1;
#pragma unroll
        for (int nt = 0; nt < 8; nt++) {
            oa[nt][0] *= a0; oa[nt][1] *= a0;
            oa[nt][2] *= a1; oa[nt][3] *= a1;
        }

        // ---- O += P V (3-term split; V via trans ldmatrix) ----
#pragma unroll
        for (int ks = 0; ks < 4; ks++) {
            uint32_t ah[4] = {php[2 * ks][0], php[2 * ks][1],
                              php[2 * ks + 1][0], php[2 * ks + 1][1]};
            uint32_t al[4] = {plp[2 * ks][0], plp[2 * ks][1],
                              plp[2 * ks + 1][0], plp[2 * ks + 1][1]};
            uint32_t vh_[4][4], vl_[4][4];
            uint32_t ra = (uint32_t)((ks * 16 + (lid & 15)) * 128);
#pragma unroll
            for (int np = 0; np < 4; np++) {
                uint32_t col = (uint32_t)(np * 32 + cb) ^ xm;
                ldmat_x4_trans(vh_[np], st + 16384u + ra + col);
                ldmat_x4_trans(vl_[np], st + 24576u + ra + col);
            }
#pragma unroll
            for (int nt = 0; nt < 8; nt++) {
                int np = nt >> 1, s2 = (nt & 1) * 2;
                mma16816(oa[nt], ah, vh_[np][s2], vh_[np][s2 + 1]);
                mma16816(oa[nt], ah, vl_[np][s2], vl_[np][s2 + 1]);
                mma16816(oa[nt], al, vh_[np][s2], vh_[np][s2 + 1]);
            }
        }

        if (kt + 1 < 16) CP_WAIT(0);
        __syncthreads();
    }

    // epilogue
    float i0 = 1.0f / l0, i1 = 1.0f / l1;
    int r0 = qt * 128 + wid * 16 + (lid >> 2);
    int c0 = h * 64 + (lid & 3) * 2;
#pragma unroll
    for (int nt = 0; nt < 8; nt++) {
        float2 v0, v1;
        v0.x = oa[nt][0] * i0; v0.y = oa[nt][1] * i0;
        v1.x = oa[nt][2] * i1; v1.y = oa[nt][3] * i1;
        *(float2*)(O + ((long)b * PNC + r0) * PD + c0 + nt * 8) = v0;
        *(float2*)(O + ((long)b * PNC + r0 + 8) * PD + c0 + nt * 8) = v1;
    }
}

// ---------------- launch ----------------
extern "C" void kernel_launch(void* const* d_in, const int* in_sizes, int n_in,
                              void* d_out, int out_size) {
    const float* x         = (const float*)d_in[0];
    const float* coords    = (const float*)d_in[1];
    const void*  is_ctx    = d_in[2];
    const float* rope      = (const float*)d_in[3];
    const float* ctx_in_w  = (const float*)d_in[4];
    const float* ctx_in_b  = (const float*)d_in[5];
    const float* ctx_out_w = (const float*)d_in[6];
    const float* ctx_out_b = (const float*)d_in[7];
    const float* tgt_in_w  = (const float*)d_in[8];
    const float* tgt_in_b  = (const float*)d_in[9];
    const float* tgt_out_w = (const float*)d_in[10];
    const float* tgt_out_b = (const float*)d_in[11];
    float* out = (float*)d_out;

    float* xr = 0;      cudaGetSymbolAddress((void**)&xr, g_xr);
    int* perm = 0;      cudaGetSymbolAddress((void**)&perm, g_perm);
    float* qkv_ctx = 0; cudaGetSymbolAddress((void**)&qkv_ctx, g_qkv_ctx);
    float* kv_tgt = 0;  cudaGetSymbolAddress((void**)&kv_tgt, g_kv_tgt);
    float* q_tgt = 0;   cudaGetSymbolAddress((void**)&q_tgt, g_q_tgt);
    float* o_ctx = 0;   cudaGetSymbolAddress((void**)&o_ctx, g_o_ctx);
    float* o_tgt = 0;   cudaGetSymbolAddress((void**)&o_tgt, g_o_tgt);
    __nv_bfloat16* a2 = 0;  cudaGetSymbolAddress((void**)&a2, g_a2);
    __nv_bfloat16* wc = 0;  cudaGetSymbolAddress((void**)&wc, g_wc);
    __nv_bfloat16* wt = 0;  cudaGetSymbolAddress((void**)&wt, g_wt);
    __nv_bfloat16* wco = 0; cudaGetSymbolAddress((void**)&wco, g_wco);
    __nv_bfloat16* wto = 0; cudaGetSymbolAddress((void**)&wto, g_wto);
    __nv_bfloat16* oc2 = 0; cudaGetSymbolAddress((void**)&oc2, g_oc2);
    __nv_bfloat16* ot2 = 0; cudaGetSymbolAddress((void**)&ot2, g_ot2);
    __nv_bfloat16* ap = 0;  cudaGetSymbolAddress((void**)&ap, g_ap);

    const int GSM = 66560;    // gemm: pad + 2 x 32KB
    const int ASM = 99328;    // attn: pad + 32KB Q + 2 x 32KB stages
    cudaFuncSetAttribute(gemm_mma, cudaFuncAttributeMaxDynamicSharedMemorySize, GSM);
    cudaFuncSetAttribute(attn_mma, cudaFuncAttributeMaxDynamicSharedMemorySize, ASM);

    build_perm<<<PB, 32>>>(is_ctx, perm);
    rope_gather<<<PB * PK, 512>>>(x, coords, rope);

    // conversions to split-bf16 swizzled GEMM panels
    convert_split<<<64 * 32, 256>>>(xr,        a2,  0);
    convert_split<<<24 * 32, 256>>>(ctx_in_w,  wc,  1);
    convert_split<<<24 * 32, 256>>>(tgt_in_w,  wt,  1);
    convert_split<<< 8 * 32, 256>>>(ctx_out_w, wco, 1);
    convert_split<<< 8 * 32, 256>>>(tgt_out_w, wto, 1);

    // projections on HMMA tensor cores (K' = 3072)
    gemm_mma<<<dim3(24, 32), 256, GSM>>>(a2, 8, 16, wc, ctx_in_b,
                                         qkv_ctx, 3072, nullptr, 0);
    gemm_mma<<<dim3(16, 32), 256, GSM>>>(a2, 8, 16, wt + (long)8 * KCH * PANEL,
                                         tgt_in_b + 1024, kv_tgt, 2048, nullptr, 0);
    gemm_mma<<<dim3(8, 32), 256, GSM>>>(a2 + (long)8 * KCH * PANEL, 8, 16, wt,
                                        tgt_in_b, q_tgt, 1024, nullptr, 0);

    // convert q/k/v to attention hi/lo panels (Q pre-scaled by 1/8)
    dim3 cg(16, PH, PB);
    convert_attn<<<cg, 256>>>(qkv_ctx, 3072, 0,    0.125f, ap + 0ll * ATT_T, ap + 1ll * ATT_T);
    convert_attn<<<cg, 256>>>(qkv_ctx, 3072, 1024, 1.0f,   ap + 2ll * ATT_T, ap + 3ll * ATT_T);
    convert_attn<<<cg, 256>>>(qkv_ctx, 3072, 2048, 1.0f,   ap + 4ll * ATT_T, ap + 5ll * ATT_T);
    convert_attn<<<cg, 256>>>(q_tgt,   1024, 0,    0.125f, ap + 6ll * ATT_T, ap + 7ll * ATT_T);
    convert_attn<<<cg, 256>>>(kv_tgt,  2048, 0,    1.0f,   ap + 8ll * ATT_T, ap + 9ll * ATT_T);
    convert_attn<<<cg, 256>>>(kv_tgt,  2048, 1024, 1.0f,   ap + 10ll * ATT_T, ap + 11ll * ATT_T);

    // HMMA attention
    attn_mma<<<dim3(8, PH, PB), 256, ASM>>>(
        ap + 0ll * ATT_T, ap + 1ll * ATT_T, ap + 2ll * ATT_T,
        ap + 3ll * ATT_T, ap + 4ll * ATT_T, ap + 5ll * ATT_T, o_ctx);
    attn_mma<<<dim3(8, PH, PB), 256, ASM>>>(
        ap + 6ll * ATT_T, ap + 7ll * ATT_T, ap + 8ll * ATT_T,
        ap + 9ll * ATT_T, ap + 10ll * ATT_T, ap + 11ll * ATT_T, o_tgt);

    // output projections (convert attn outputs, then HMMA + fused scatter)
    convert_split<<<32 * 32, 256>>>(o_ctx, oc2, 0);
    convert_split<<<32 * 32, 256>>>(o_tgt, ot2, 0);
    gemm_mma<<<dim3(8, 32), 256, GSM>>>(oc2, 8, 8, wco, ctx_out_b,
                                        out, PD, perm, 0);
    gemm_mma<<<dim3(8, 32), 256, GSM>>>(ot2, 8, 8, wto, tgt_out_b,
                                        out, PD, perm, PNC);
}

// round 7
// speedup vs baseline: 2.9128x; 1.0466x over previous
#include <cuda_runtime.h>
#include <cuda_bf16.h>
#include <cstdint>

// Problem constants
#define PB   4
#define PK   2048
#define PD   1024
#define PH   16
#define PNC  1024   // NCTX = K/2

#define KCH   48        // K' = 3072 in chunks of 64
#define PANEL 8192      // bf16 elems per 128x64 tile panel (16KB)
#define APAN  4096      // bf16 elems per 64x64 attention panel (8KB)
#define ATT_T (PB * PH * 16 * APAN)

// ---------------- scratch (device globals: allocation-free) ----------------
__device__ __align__(256) int g_perm[PB * PK];
// split-bf16 swizzled tile panels (GEMM)
__device__ __align__(256) __nv_bfloat16 g_a2 [64 * KCH * PANEL];
__device__ __align__(256) __nv_bfloat16 g_wc [24 * KCH * PANEL];
__device__ __align__(256) __nv_bfloat16 g_wt [24 * KCH * PANEL];
__device__ __align__(256) __nv_bfloat16 g_wco[ 8 * KCH * PANEL];
__device__ __align__(256) __nv_bfloat16 g_wto[ 8 * KCH * PANEL];
__device__ __align__(256) __nv_bfloat16 g_oc2[32 * KCH * PANEL];
__device__ __align__(256) __nv_bfloat16 g_ot2[32 * KCH * PANEL];
// attention split-bf16 panels: 0..5 ctx {Qh,Ql,Kh,Kl,Vh,Vl}, 6..11 tgt
__device__ __align__(256) __nv_bfloat16 g_ap[12ll * ATT_T];

// ---------------- PTX helpers (base-PTX only) ----------------
__device__ __forceinline__ uint32_t smem_u32(const void* p) {
    uint32_t a;
    asm("{ .reg .u64 t; cvta.to.shared.u64 t, %1; cvt.u32.u64 %0, t; }" : "=r"(a) : "l"(p));
    return a;
}

__device__ __forceinline__ void cp_async16(uint32_t s, const void* g) {
    asm volatile("cp.async.cg.shared.global [%0], [%1], 16;" :: "r"(s), "l"(g));
}
#define CP_COMMIT() asm volatile("cp.async.commit_group;" ::: "memory")
#define CP_WAIT(n)  asm volatile("cp.async.wait_group %0;" :: "n"(n) : "memory")

__device__ __forceinline__ void ldmat_x4(uint32_t* r, uint32_t addr) {
    asm volatile("ldmatrix.sync.aligned.m8n8.x4.shared.b16 {%0,%1,%2,%3}, [%4];"
                 : "=r"(r[0]), "=r"(r[1]), "=r"(r[2]), "=r"(r[3]) : "r"(addr));
}

__device__ __forceinline__ void ldmat_x4_trans(uint32_t* r, uint32_t addr) {
    asm volatile("ldmatrix.sync.aligned.m8n8.x4.trans.shared.b16 {%0,%1,%2,%3}, [%4];"
                 : "=r"(r[0]), "=r"(r[1]), "=r"(r[2]), "=r"(r[3]) : "r"(addr));
}

__device__ __forceinline__ void mma16816(float* c, const uint32_t* a,
                                         uint32_t b0, uint32_t b1) {
    asm volatile(
        "mma.sync.aligned.m16n8k16.row.col.f32.bf16.bf16.f32 "
        "{%0,%1,%2,%3}, {%4,%5,%6,%7}, {%8,%9}, {%0,%1,%2,%3};"
        : "+f"(c[0]), "+f"(c[1]), "+f"(c[2]), "+f"(c[3])
        : "r"(a[0]), "r"(a[1]), "r"(a[2]), "r"(a[3]), "r"(b0), "r"(b1));
}

// pack two f32 into bf16x2 (first arg -> low 16 bits)
__device__ __forceinline__ uint32_t pack_bf16x2(float lo, float hi) {
    uint32_t r;
    asm("cvt.rn.bf16x2.f32 %0, %1, %2;" : "=r"(r) : "f"(hi), "f"(lo));
    return r;
}

// split (vx,vy) into hi bf16x2 + residual lo bf16x2
__device__ __forceinline__ void split2(float vx, float vy,
                                       uint32_t& uhi, uint32_t& ulo) {
    uhi = pack_bf16x2(vx, vy);
    float hx = __uint_as_float(uhi << 16);
    float hy = __uint_as_float(uhi & 0xFFFF0000u);
    ulo = pack_bf16x2(vx - hx, vy - hy);
}

__device__ __forceinline__ uint32_t sw128(uint32_t off) {
    return off ^ ((off >> 3) & 0x70);
}

// ---------------- perm (dtype-agnostic detection) ----------------
__global__ void build_perm(const void* __restrict__ is_ctx_raw,
                           int* __restrict__ perm) {
    const unsigned char* u8  = (const unsigned char*)is_ctx_raw;
    const unsigned int*  u32 = (const unsigned int*)is_ctx_raw;
    int b = blockIdx.x;
    int lane = threadIdx.x;

    int s = 0;
    for (int i = lane; i < 2048; i += 32) s += (int)u8[i];
#pragma unroll
    for (int off = 16; off; off >>= 1) s += __shfl_xor_sync(0xffffffffu, s, off);
    bool one_byte = (s == 1024) || (s == 255 * 1024);

    int cbase = 0, tbase = PNC;
    for (int j0 = 0; j0 < PK; j0 += 32) {
        int j = j0 + lane;
        int c = one_byte ? (u8[b * PK + j] != 0) : (u32[b * PK + j] != 0u);
        unsigned mask = __ballot_sync(0xffffffffu, c);
        int pre = __popc(mask & ((1u << lane) - 1u));
        int slot = c ? (cbase + pre) : (tbase + lane - pre);
        perm[b * PK + slot] = j;
        int nc = __popc(mask);
        cbase += nc;
        tbase += 32 - nc;
    }
}

// ---------------- RoPE + gather -> a2 panels directly -----------------------
// block = one output slot (token); writes split-bf16 straight into SW128 panels.
__global__ __launch_bounds__(512) void rope_gather(
    const float* __restrict__ x, const float* __restrict__ coords,
    const float* __restrict__ rope) {
    int s = blockIdx.x & (PK - 1);
    int b = blockIdx.x >> 11;
    int j = g_perm[b * PK + s];
    long tokin = (long)b * PK + j;

    float cy = coords[tokin * 2 + 0];
    float cx = coords[tokin * 2 + 1];
    int ypos = (int)fminf(fmaxf(cy / 224.0f * 1023.0f, 0.0f), 1023.0f);
    int xpos = (int)fminf(fmaxf(cx / 224.0f * 1023.0f, 0.0f), 1023.0f);

    int t = threadIdx.x;
    int i = t & 255;
    int pos = (t < 256) ? xpos : ypos;
    int base = (t < 256) ? (2 * i) : (512 + 2 * i);

    float c  = rope[((long)pos * 256 + i) * 2 + 0];
    float sn = rope[((long)pos * 256 + i) * 2 + 1];
    float2 p = *(const float2*)(x + tokin * PD + base);
    float rx = p.x * c - p.y * sn;
    float ry = p.x * sn + p.y * c;

    uint32_t uhi, ulo;
    split2(rx, ry, uhi, ulo);

    int mbp = b * 16 + (s >> 7);
    int rowp = s & 127;
    int ck = base >> 6;
    uint32_t sw = sw128((uint32_t)(rowp * 128 + (base & 63) * 2));
    long pb = (long)mbp * KCH;
    *(uint32_t*)((char*)(g_a2 + (pb + ck) * PANEL) + sw)      = uhi;
    *(uint32_t*)((char*)(g_a2 + (pb + 16 + ck) * PANEL) + sw) = ulo;
    *(uint32_t*)((char*)(g_a2 + (pb + 32 + ck) * PANEL) + sw) = uhi;
}

// ---------------- split-bf16 conversion of WEIGHTS into SW128 panels --------
// dst panels [mb][48][8192], K' pattern: [Wh|Wh|Wl].
__global__ __launch_bounds__(256) void convert_split(
    const float* __restrict__ src, __nv_bfloat16* __restrict__ dst) {
    int mb = blockIdx.x >> 5;
    int kb = blockIdx.x & 31;
    bool lo = (kb >= 16);
    int kc0 = (kb & 15) * 64;

    long pan1 = (kb < 16) ? ((long)mb * KCH + kb) : ((long)mb * KCH + 16 + kb);
    long pan2 = (kb < 16) ? ((long)mb * KCH + 16 + kb) : -1;

    int t = threadIdx.x;
#pragma unroll
    for (int q = 0; q < 4; q++) {
        int ch = t + q * 256;
        int r = ch >> 3;
        int c0 = (ch & 7) * 8;
        const float* sp = src + ((long)mb * 128 + r) * 1024 + kc0 + c0;
        float4 f0 = *(const float4*)sp;
        float4 f1 = *(const float4*)(sp + 4);
        float vals[8] = {f0.x, f0.y, f0.z, f0.w, f1.x, f1.y, f1.z, f1.w};
        union { __nv_bfloat16 h[8]; uint4 u; } pk;
#pragma unroll
        for (int e = 0; e < 8; e++) {
            __nv_bfloat16 hi = __float2bfloat16(vals[e]);
            if (lo) {
                pk.h[e] = __float2bfloat16(vals[e] - __bfloat162float(hi));
            } else {
                pk.h[e] = hi;
            }
        }
        uint32_t sw = sw128((uint32_t)(r * 128 + c0 * 2));
        *(uint4*)((char*)(dst + pan1 * PANEL) + sw) = pk.u;
        if (pan2 >= 0) {
            *(uint4*)((char*)(dst + pan2 * PANEL) + sw) = pk.u;
        }
    }
}

// ---------------- HMMA bf16 GEMM over pre-swizzled panels --------------------
// If apDst != null: write attention hi/lo panels (group g = ncol/1024; group 0
// scaled by qscale). Else: fp32 out (+ optional perm row-scatter).
__global__ __launch_bounds__(256, 2) void gemm_mma(
    const __nv_bfloat16* __restrict__ Apan, int mb_group, int mb_stride,
    const __nv_bfloat16* __restrict__ Wpan,
    const float* __restrict__ bias,
    float* __restrict__ C, int ldc,
    const int* __restrict__ perm, int slotOff,
    __nv_bfloat16* __restrict__ apDst, float qscale) {
    extern __shared__ char dsm[];
    uint32_t base = smem_u32(dsm);
    uint32_t tiles = (base + 1023u) & ~1023u;

    int tid = threadIdx.x;
    int wid = tid >> 5;
    int lid = tid & 31;
    int wm = wid & 3;
    int wn = wid >> 2;

    int by = blockIdx.y;
    int b = by / mb_group;
    int l = by % mb_group;
    const char* pA = (const char*)(Apan + ((long)(b * mb_stride + l) * KCH) * PANEL);
    const char* pW = (const char*)(Wpan + ((long)blockIdx.x * KCH) * PANEL);

    float acc[2][8][4];
#pragma unroll
    for (int mt = 0; mt < 2; mt++)
#pragma unroll
        for (int nt = 0; nt < 8; nt++)
#pragma unroll
            for (int e = 0; e < 4; e++) acc[mt][nt][e] = 0.0f;

    int rA0 = wm * 32 + (lid & 15);
    int rB0 = wn * 64 + (lid & 15);
    int cb  = (lid >> 4) * 16;
    uint32_t xm = (uint32_t)((lid & 7) << 4);

    {
        uint32_t sa = tiles;
#pragma unroll
        for (int q = 0; q < 4; q++) {
            int ch = tid + q * 256;
            cp_async16(sa + ch * 16, pA + ch * 16);
            cp_async16(sa + 16384 + ch * 16, pW + ch * 16);
        }
        CP_COMMIT();
    }

    for (int kb = 0; kb < KCH; kb++) {
        if (kb + 1 < KCH) {
            uint32_t sa = tiles + (uint32_t)((kb + 1) & 1) * 32768u;
            const char* gA = pA + (long)(kb + 1) * 16384;
            const char* gW = pW + (long)(kb + 1) * 16384;
#pragma unroll
            for (int q = 0; q < 4; q++) {
                int ch = tid + q * 256;
                cp_async16(sa + ch * 16, gA + ch * 16);
                cp_async16(sa + 16384 + ch * 16, gW + ch * 16);
            }
            CP_COMMIT();
            CP_WAIT(1);
        } else {
            CP_WAIT(0);
        }
        __syncthreads();

        uint32_t sA = tiles + (uint32_t)(kb & 1) * 32768u;
        uint32_t sB = sA + 16384u;
#pragma unroll
        for (int ks = 0; ks < 4; ks++) {
            uint32_t colb = (uint32_t)(cb + ks * 32) ^ xm;
            uint32_t af[2][4];
            uint32_t bf[4][4];
#pragma unroll
            for (int mt = 0; mt < 2; mt++)
                ldmat_x4(af[mt], sA + (uint32_t)(rA0 + mt * 16) * 128u + colb);
#pragma unroll
            for (int np = 0; np < 4; np++)
                ldmat_x4(bf[np], sB + (uint32_t)(rB0 + np * 16) * 128u + colb);
#pragma unroll
            for (int mt = 0; mt < 2; mt++) {
#pragma unroll
                for (int nt = 0; nt < 8; nt++) {
                    int np = nt >> 1;
                    int sel = nt & 1;
                    mma16816(acc[mt][nt], af[mt], bf[np][sel], bf[np][sel + 2]);
                }
            }
        }
        __syncthreads();
    }

    int n0 = blockIdx.x * 128;
    if (apDst != nullptr) {
        // write attention hi/lo panels
#pragma unroll
        for (int nt = 0; nt < 8; nt++) {
            int cc = wn * 64 + nt * 8 + (lid & 3) * 2;
            int ng = n0 + cc;
            int g = ng >> 10;
            int head = (ng >> 6) & 15;
            float sc = (g == 0) ? qscale : 1.0f;
            float bx = bias[ng];
            float by2 = bias[ng + 1];
            __nv_bfloat16* hiB = apDst + (long)(2 * g) * ATT_T;
            __nv_bfloat16* loB = apDst + (long)(2 * g + 1) * ATT_T;
            uint32_t swc = sw128((uint32_t)((nt * 8 + (lid & 3) * 2) * 2));
#pragma unroll
            for (int mt = 0; mt < 2; mt++) {
                int r0 = wm * 32 + mt * 16 + (lid >> 2);
#pragma unroll
                for (int half = 0; half < 2; half++) {
                    int tr = l * 128 + r0 + half * 8;
                    int kt = tr >> 6;
                    int row = tr & 63;
                    float vx = (acc[mt][nt][half * 2 + 0] + bx) * sc;
                    float vy = (acc[mt][nt][half * 2 + 1] + by2) * sc;
                    uint32_t uhi, ulo;
                    split2(vx, vy, uhi, ulo);
                    long pan = (((long)b * PH + head) * 16 + kt) * APAN;
                    uint32_t sw = (uint32_t)(row * 128) + swc;
                    sw = (sw & ~0x7Fu) | sw128(sw & 0x7Fu) ;
                    // note: row*128 has no low-7 bits set beyond offset; recompute cleanly:
                    sw = sw128((uint32_t)(row * 128 + (nt * 8 + (lid & 3) * 2) * 2));
                    *(uint32_t*)((char*)(hiB + pan) + sw) = uhi;
                    *(uint32_t*)((char*)(loB + pan) + sw) = ulo;
                }
            }
        }
    } else {
#pragma unroll
        for (int nt = 0; nt < 8; nt++) {
            int cc = wn * 64 + nt * 8 + (lid & 3) * 2;
            float2 bv;
            bv.x = bias[n0 + cc];
            bv.y = bias[n0 + cc + 1];
#pragma unroll
            for (int mt = 0; mt < 2; mt++) {
                int r0 = wm * 32 + mt * 16 + (lid >> 2);
                float2 v0, v1;
                v0.x = acc[mt][nt][0] + bv.x;
                v0.y = acc[mt][nt][1] + bv.y;
                v1.x = acc[mt][nt][2] + bv.x;
                v1.y = acc[mt][nt][3] + bv.y;
                if (perm != nullptr) {
                    int tok0 = perm[b * PK + l * 128 + r0 + slotOff];
                    int tok1 = perm[b * PK + l * 128 + r0 + 8 + slotOff];
                    *(float2*)(C + ((long)b * PK + tok0) * PD + n0 + cc) = v0;
                    *(float2*)(C + ((long)b * PK + tok1) * PD + n0 + cc) = v1;
                } else {
                    long row = (long)by * 128 + r0;
                    *(float2*)(C + row * ldc + n0 + cc) = v0;
                    *(float2*)(C + (row + 8) * ldc + n0 + cc) = v1;
                }
            }
        }
    }
}

// ---------------- HMMA flash attention (split-bf16, 3-term) -----------------
// block = (qtile 128, h, b). Output written directly as split GEMM A-panels.
__global__ __launch_bounds__(256) void attn_mma(
    const __nv_bfloat16* __restrict__ Aqh, const __nv_bfloat16* __restrict__ Aql,
    const __nv_bfloat16* __restrict__ Akh, const __nv_bfloat16* __restrict__ Akl,
    const __nv_bfloat16* __restrict__ Avh, const __nv_bfloat16* __restrict__ Avl,
    __nv_bfloat16* __restrict__ Opan) {
    extern __shared__ char dsm[];
    uint32_t base = smem_u32(dsm);
    uint32_t sQ = (base + 1023u) & ~1023u;
    uint32_t sT = sQ + 32768u;

    int tid = threadIdx.x, wid = tid >> 5, lid = tid & 31;
    int qt = blockIdx.x, h = blockIdx.y, b = blockIdx.z;
    long pb = ((long)b * PH + h) * 16;

    const char* pQh = (const char*)(Aqh + (pb + qt * 2) * APAN);
    const char* pQl = (const char*)(Aql + (pb + qt * 2) * APAN);
    const char* pKh = (const char*)(Akh + pb * APAN);
    const char* pKl = (const char*)(Akl + pb * APAN);
    const char* pVh = (const char*)(Avh + pb * APAN);
    const char* pVl = (const char*)(Avl + pb * APAN);

#pragma unroll
    for (int q = 0; q < 8; q++) {
        int ch = tid + q * 256;
        int idx = ch & 1023;
        if (q < 4) cp_async16(sQ + idx * 16, pQh + idx * 16);
        else       cp_async16(sQ + 16384 + idx * 16, pQl + idx * 16);
    }
#pragma unroll
    for (int q = 0; q < 8; q++) {
        int ch = tid + q * 256;
        int idx = ch & 511;
        const char* s = (q < 2) ? pKh : (q < 4) ? pKl : (q < 6) ? pVh : pVl;
        cp_async16(sT + ch * 16, s + idx * 16);
    }
    CP_COMMIT();
    CP_WAIT(0);
    __syncthreads();

    int cb = (lid >> 4) * 16;
    uint32_t xm = (uint32_t)((lid & 7) << 4);

    uint32_t qra = sQ + (uint32_t)(wid >> 2) * 8192u
                 + (uint32_t)(((wid & 3) * 16 + (lid & 15)) * 128);
    uint32_t qhf[4][4], qlf[4][4];
#pragma unroll
    for (int ks = 0; ks < 4; ks++) {
        uint32_t col = (uint32_t)(ks * 32 + cb) ^ xm;
        ldmat_x4(qhf[ks], qra + col);
        ldmat_x4(qlf[ks], qra + 16384u + col);
    }

    float m0 = -1e30f, m1 = -1e30f, l0 = 0.0f, l1 = 0.0f;
    float oa[8][4];
#pragma unroll
    for (int nt = 0; nt < 8; nt++)
#pragma unroll
        for (int e = 0; e < 4; e++) oa[nt][e] = 0.0f;

    for (int kt = 0; kt < 16; kt++) {
        uint32_t st = sT + (uint32_t)(kt & 1) * 32768u;
        if (kt + 1 < 16) {
            uint32_t sn = sT + (uint32_t)((kt + 1) & 1) * 32768u;
            long off = (long)(kt + 1) * 8192;
#pragma unroll
            for (int q = 0; q < 8; q++) {
                int ch = tid + q * 256;
                int idx = ch & 511;
                const char* s = (q < 2) ? pKh : (q < 4) ? pKl : (q < 6) ? pVh : pVl;
                cp_async16(sn + ch * 16, s + off + idx * 16);
            }
            CP_COMMIT();
        }

        float sc[8][4];
#pragma unroll
        for (int nt = 0; nt < 8; nt++)
#pragma unroll
            for (int e = 0; e < 4; e++) sc[nt][e] = 0.0f;

#pragma unroll
        for (int ks = 0; ks < 4; ks++) {
            uint32_t col = (uint32_t)(ks * 32 + cb) ^ xm;
            uint32_t bh_[4][4], bl_[4][4];
#pragma unroll
            for (int np = 0; np < 4; np++) {
                uint32_t ra = (uint32_t)((np * 16 + (lid & 15)) * 128);
                ldmat_x4(bh_[np], st + ra + col);
                ldmat_x4(bl_[np], st + 8192u + ra + col);
            }
#pragma unroll
            for (int nt = 0; nt < 8; nt++) {
                int np = nt >> 1, sel = nt & 1;
                mma16816(sc[nt], qhf[ks], bh_[np][sel], bh_[np][sel + 2]);
                mma16816(sc[nt], qlf[ks], bh_[np][sel], bh_[np][sel + 2]);
                mma16816(sc[nt], qhf[ks], bl_[np][sel], bl_[np][sel + 2]);
            }
        }

        float mt0 = -1e30f, mt1 = -1e30f;
#pragma unroll
        for (int nt = 0; nt < 8; nt++) {
            mt0 = fmaxf(mt0, fmaxf(sc[nt][0], sc[nt][1]));
            mt1 = fmaxf(mt1, fmaxf(sc[nt][2], sc[nt][3]));
        }
        mt0 = fmaxf(mt0, __shfl_xor_sync(0xffffffffu, mt0, 1));
        mt0 = fmaxf(mt0, __shfl_xor_sync(0xffffffffu, mt0, 2));
        mt1 = fmaxf(mt1, __shfl_xor_sync(0xffffffffu, mt1, 1));
        mt1 = fmaxf(mt1, __shfl_xor_sync(0xffffffffu, mt1, 2));

        float mn0 = fmaxf(m0, mt0), mn1 = fmaxf(m1, mt1);
        float a0 = __expf(m0 - mn0), a1 = __expf(m1 - mn1);

        uint32_t php[8][2], plp[8][2];
        float ps0 = 0.0f, ps1 = 0.0f;
#pragma unroll
        for (int nt = 0; nt < 8; nt++) {
            float p00 = __expf(sc[nt][0] - mn0);
            float p01 = __expf(sc[nt][1] - mn0);
            float p10 = __expf(sc[nt][2] - mn1);
            float p11 = __expf(sc[nt][3] - mn1);
            ps0 += p00 + p01;
            ps1 += p10 + p11;
            uint32_t u0, u1, l0p, l1p;
            split2(p00, p01, u0, l0p);
            split2(p10, p11, u1, l1p);
            php[nt][0] = u0;  php[nt][1] = u1;
            plp[nt][0] = l0p; plp[nt][1] = l1p;
        }
        ps0 += __shfl_xor_sync(0xffffffffu, ps0, 1);
        ps0 += __shfl_xor_sync(0xffffffffu, ps0, 2);
        ps1 += __shfl_xor_sync(0xffffffffu, ps1, 1);
        ps1 += __shfl_xor_sync(0xffffffffu, ps1, 2);

        l0 = l0 * a0 + ps0;
        l1 = l1 * a1 + ps1;
        m0 = mn0;
        m1 = mn1;
#pragma unroll
        for (int nt = 0; nt < 8; nt++) {
            oa[nt][0] *= a0; oa[nt][1] *= a0;
            oa[nt][2] *= a1; oa[nt][3] *= a1;
        }

#pragma unroll
        for (int ks = 0; ks < 4; ks++) {
            uint32_t ah[4] = {php[2 * ks][0], php[2 * ks][1],
                              php[2 * ks + 1][0], php[2 * ks + 1][1]};
            uint32_t al[4] = {plp[2 * ks][0], plp[2 * ks][1],
                              plp[2 * ks + 1][0], plp[2 * ks + 1][1]};
            uint32_t vh_[4][4], vl_[4][4];
            uint32_t ra = (uint32_t)((ks * 16 + (lid & 15)) * 128);
#pragma unroll
            for (int np = 0; np < 4; np++) {
                uint32_t col = (uint32_t)(np * 32 + cb) ^ xm;
                ldmat_x4_trans(vh_[np], st + 16384u + ra + col);
                ldmat_x4_trans(vl_[np], st + 24576u + ra + col);
            }
#pragma unroll
            for (int nt = 0; nt < 8; nt++) {
                int np = nt >> 1, s2 = (nt & 1) * 2;
                mma16816(oa[nt], ah, vh_[np][s2], vh_[np][s2 + 1]);
                mma16816(oa[nt], ah, vl_[np][s2], vl_[np][s2 + 1]);
                mma16816(oa[nt], al, vh_[np][s2], vh_[np][s2 + 1]);
            }
        }

        if (kt + 1 < 16) CP_WAIT(0);
        __syncthreads();
    }

    // epilogue: write split A-panels [mb = b*8+qt][48 chunks]; hi -> h & 32+h, lo -> 16+h
    float i0 = 1.0f / l0, i1 = 1.0f / l1;
    int rl = wid * 16 + (lid >> 2);
    long panB = ((long)b * 8 + qt) * KCH;
    __nv_bfloat16* c_hi  = Opan + (panB + h) * (long)PANEL;
    __nv_bfloat16* c_lo  = Opan + (panB + 16 + h) * (long)PANEL;
    __nv_bfloat16* c_hi2 = Opan + (panB + 32 + h) * (long)PANEL;
#pragma unroll
    for (int nt = 0; nt < 8; nt++) {
        int col = nt * 8 + (lid & 3) * 2;
        uint32_t sw0 = sw128((uint32_t)(rl * 128 + col * 2));
        uint32_t sw1 = sw128((uint32_t)((rl + 8) * 128 + col * 2));
        uint32_t uhi0, ulo0, uhi1, ulo1;
        split2(oa[nt][0] * i0, oa[nt][1] * i0, uhi0, ulo0);
        split2(oa[nt][2] * i1, oa[nt][3] * i1, uhi1, ulo1);
        *(uint32_t*)((char*)c_hi  + sw0) = uhi0;
        *(uint32_t*)((char*)c_lo  + sw0) = ulo0;
        *(uint32_t*)((char*)c_hi2 + sw0) = uhi0;
        *(uint32_t*)((char*)c_hi  + sw1) = uhi1;
        *(uint32_t*)((char*)c_lo  + sw1) = ulo1;
        *(uint32_t*)((char*)c_hi2 + sw1) = uhi1;
    }
}

// ---------------- launch ----------------
extern "C" void kernel_launch(void* const* d_in, const int* in_sizes, int n_in,
                              void* d_out, int out_size) {
    const float* x         = (const float*)d_in[0];
    const float* coords    = (const float*)d_in[1];
    const void*  is_ctx    = d_in[2];
    const float* rope      = (const float*)d_in[3];
    const float* ctx_in_w  = (const float*)d_in[4];
    const float* ctx_in_b  = (const float*)d_in[5];
    const float* ctx_out_w = (const float*)d_in[6];
    const float* ctx_out_b = (const float*)d_in[7];
    const float* tgt_in_w  = (const float*)d_in[8];
    const float* tgt_in_b  = (const float*)d_in[9];
    const float* tgt_out_w = (const float*)d_in[10];
    const float* tgt_out_b = (const float*)d_in[11];
    float* out = (float*)d_out;

    int* perm = 0;          cudaGetSymbolAddress((void**)&perm, g_perm);
    __nv_bfloat16* a2 = 0;  cudaGetSymbolAddress((void**)&a2, g_a2);
    __nv_bfloat16* wc = 0;  cudaGetSymbolAddress((void**)&wc, g_wc);
    __nv_bfloat16* wt = 0;  cudaGetSymbolAddress((void**)&wt, g_wt);
    __nv_bfloat16* wco = 0; cudaGetSymbolAddress((void**)&wco, g_wco);
    __nv_bfloat16* wto = 0; cudaGetSymbolAddress((void**)&wto, g_wto);
    __nv_bfloat16* oc2 = 0; cudaGetSymbolAddress((void**)&oc2, g_oc2);
    __nv_bfloat16* ot2 = 0; cudaGetSymbolAddress((void**)&ot2, g_ot2);
    __nv_bfloat16* ap = 0;  cudaGetSymbolAddress((void**)&ap, g_ap);

    const int GSM = 66560;
    const int ASM = 99328;
    cudaFuncSetAttribute(gemm_mma, cudaFuncAttributeMaxDynamicSharedMemorySize, GSM);
    cudaFuncSetAttribute(attn_mma, cudaFuncAttributeMaxDynamicSharedMemorySize, ASM);

    build_perm<<<PB, 32>>>(is_ctx, perm);
    rope_gather<<<PB * PK, 512>>>(x, coords, rope);

    // weight conversions
    convert_split<<<24 * 32, 256>>>(ctx_in_w,  wc);
    convert_split<<<24 * 32, 256>>>(tgt_in_w,  wt);
    convert_split<<< 8 * 32, 256>>>(ctx_out_w, wco);
    convert_split<<< 8 * 32, 256>>>(tgt_out_w, wto);

    // projections -> attention panels directly
    gemm_mma<<<dim3(24, 32), 256, GSM>>>(a2, 8, 16, wc, ctx_in_b,
                                         nullptr, 0, nullptr, 0,
                                         ap, 0.125f);
    gemm_mma<<<dim3(16, 32), 256, GSM>>>(a2, 8, 16, wt + (long)8 * KCH * PANEL,
                                         tgt_in_b + 1024,
                                         nullptr, 0, nullptr, 0,
                                         ap + 8ll * ATT_T, 1.0f);
    gemm_mma<<<dim3(8, 32), 256, GSM>>>(a2 + (long)8 * KCH * PANEL, 8, 16, wt,
                                        tgt_in_b,
                                        nullptr, 0, nullptr, 0,
                                        ap + 6ll * ATT_T, 0.125f);

    // HMMA attention -> split A-panels directly
    attn_mma<<<dim3(8, PH, PB), 256, ASM>>>(
        ap + 0ll * ATT_T, ap + 1ll * ATT_T, ap + 2ll * ATT_T,
        ap + 3ll * ATT_T, ap + 4ll * ATT_T, ap + 5ll * ATT_T, oc2);
    attn_mma<<<dim3(8, PH, PB), 256, ASM>>>(
        ap + 6ll * ATT_T, ap + 7ll * ATT_T, ap + 8ll * ATT_T,
        ap + 9ll * ATT_T, ap + 10ll * ATT_T, ap + 11ll * ATT_T, ot2);

    // output projections + fused scatter to original token order
    gemm_mma<<<dim3(8, 32), 256, GSM>>>(oc2, 8, 8, wco, ctx_out_b,
                                        out, PD, perm, 0, nullptr, 0.0f);
    gemm_mma<<<dim3(8, 32), 256, GSM>>>(ot2, 8, 8, wto, tgt_out_b,
                                        out, PD, perm, PNC, nullptr, 0.0f);
}

// round 8
// speedup vs baseline: 3.4585x; 1.1873x over previous
#include <cuda_runtime.h>
#include <cuda_fp16.h>
#include <cstdint>

// Problem constants
#define PB   4
#define PK   2048
#define PD   1024
#define PH   16
#define PNC  1024   // NCTX = K/2

#define PANEL 8192      // fp16 elems per 128x64 tile panel (16KB)
#define APAN  4096      // fp16 elems per 64x64 attention panel (8KB)
#define ATT_T (PB * PH * 16 * APAN)

// ---------------- scratch (device globals: allocation-free) ----------------
__device__ __align__(256) int g_perm[PB * PK];
// split-fp16 swizzled tile panels. A panels: 32 chunks (16 hi + 16 lo).
// W panels: 16 chunks (hi only).
__device__ __align__(256) __half g_a2 [64ll * 32 * PANEL];
__device__ __align__(256) __half g_wc [24ll * 16 * PANEL];
__device__ __align__(256) __half g_wt [24ll * 16 * PANEL];
__device__ __align__(256) __half g_wco[ 8ll * 16 * PANEL];
__device__ __align__(256) __half g_wto[ 8ll * 16 * PANEL];
__device__ __align__(256) __half g_oc2[32ll * 32 * PANEL];
__device__ __align__(256) __half g_ot2[32ll * 32 * PANEL];
// attention panels: 0..5 ctx {Qh,Ql,Kh,Kl,Vh,Vl}, 6..11 tgt (Vl written, unused)
__device__ __align__(256) __half g_ap[12ll * ATT_T];

// ---------------- PTX helpers (base-PTX only) ----------------
__device__ __forceinline__ uint32_t smem_u32(const void* p) {
    uint32_t a;
    asm("{ .reg .u64 t; cvta.to.shared.u64 t, %1; cvt.u32.u64 %0, t; }" : "=r"(a) : "l"(p));
    return a;
}

__device__ __forceinline__ void cp_async16(uint32_t s, const void* g) {
    asm volatile("cp.async.cg.shared.global [%0], [%1], 16;" :: "r"(s), "l"(g));
}
#define CP_COMMIT() asm volatile("cp.async.commit_group;" ::: "memory")
#define CP_WAIT(n)  asm volatile("cp.async.wait_group %0;" :: "n"(n) : "memory")

__device__ __forceinline__ void ldmat_x4(uint32_t* r, uint32_t addr) {
    asm volatile("ldmatrix.sync.aligned.m8n8.x4.shared.b16 {%0,%1,%2,%3}, [%4];"
                 : "=r"(r[0]), "=r"(r[1]), "=r"(r[2]), "=r"(r[3]) : "r"(addr));
}

__device__ __forceinline__ void ldmat_x4_trans(uint32_t* r, uint32_t addr) {
    asm volatile("ldmatrix.sync.aligned.m8n8.x4.trans.shared.b16 {%0,%1,%2,%3}, [%4];"
                 : "=r"(r[0]), "=r"(r[1]), "=r"(r[2]), "=r"(r[3]) : "r"(addr));
}

__device__ __forceinline__ void mma16816(float* c, const uint32_t* a,
                                         uint32_t b0, uint32_t b1) {
    asm volatile(
        "mma.sync.aligned.m16n8k16.row.col.f32.f16.f16.f32 "
        "{%0,%1,%2,%3}, {%4,%5,%6,%7}, {%8,%9}, {%0,%1,%2,%3};"
        : "+f"(c[0]), "+f"(c[1]), "+f"(c[2]), "+f"(c[3])
        : "r"(a[0]), "r"(a[1]), "r"(a[2]), "r"(a[3]), "r"(b0), "r"(b1));
}

// pack two f32 into fp16x2 (first arg -> low 16 bits)
__device__ __forceinline__ uint32_t packh2(float lo, float hi) {
    __half2 h = __floats2half2_rn(lo, hi);
    return *(uint32_t*)&h;
}

// split (vx,vy) into hi fp16x2 + residual lo fp16x2
__device__ __forceinline__ void split2h(float vx, float vy,
                                        uint32_t& uhi, uint32_t& ulo) {
    __half2 h = __floats2half2_rn(vx, vy);
    uhi = *(uint32_t*)&h;
    float hx = __half2float(__low2half(h));
    float hy = __half2float(__high2half(h));
    ulo = packh2(vx - hx, vy - hy);
}

__device__ __forceinline__ uint32_t sw128(uint32_t off) {
    return off ^ ((off >> 3) & 0x70);
}

// ---------------- perm (dtype-agnostic detection) ----------------
__global__ void build_perm(const void* __restrict__ is_ctx_raw,
                           int* __restrict__ perm) {
    const unsigned char* u8  = (const unsigned char*)is_ctx_raw;
    const unsigned int*  u32 = (const unsigned int*)is_ctx_raw;
    int b = blockIdx.x;
    int lane = threadIdx.x;

    int s = 0;
    for (int i = lane; i < 2048; i += 32) s += (int)u8[i];
#pragma unroll
    for (int off = 16; off; off >>= 1) s += __shfl_xor_sync(0xffffffffu, s, off);
    bool one_byte = (s == 1024) || (s == 255 * 1024);

    int cbase = 0, tbase = PNC;
    for (int j0 = 0; j0 < PK; j0 += 32) {
        int j = j0 + lane;
        int c = one_byte ? (u8[b * PK + j] != 0) : (u32[b * PK + j] != 0u);
        unsigned mask = __ballot_sync(0xffffffffu, c);
        int pre = __popc(mask & ((1u << lane) - 1u));
        int slot = c ? (cbase + pre) : (tbase + lane - pre);
        perm[b * PK + slot] = j;
        int nc = __popc(mask);
        cbase += nc;
        tbase += 32 - nc;
    }
}

// ---------------- RoPE + gather -> a2 panels directly -----------------------
__global__ __launch_bounds__(512) void rope_gather(
    const float* __restrict__ x, const float* __restrict__ coords,
    const float* __restrict__ rope) {
    int s = blockIdx.x & (PK - 1);
    int b = blockIdx.x >> 11;
    int j = g_perm[b * PK + s];
    long tokin = (long)b * PK + j;

    float cy = coords[tokin * 2 + 0];
    float cx = coords[tokin * 2 + 1];
    int ypos = (int)fminf(fmaxf(cy / 224.0f * 1023.0f, 0.0f), 1023.0f);
    int xpos = (int)fminf(fmaxf(cx / 224.0f * 1023.0f, 0.0f), 1023.0f);

    int t = threadIdx.x;
    int i = t & 255;
    int pos = (t < 256) ? xpos : ypos;
    int base = (t < 256) ? (2 * i) : (512 + 2 * i);

    float c  = rope[((long)pos * 256 + i) * 2 + 0];
    float sn = rope[((long)pos * 256 + i) * 2 + 1];
    float2 p = *(const float2*)(x + tokin * PD + base);
    float rx = p.x * c - p.y * sn;
    float ry = p.x * sn + p.y * c;

    uint32_t uhi, ulo;
    split2h(rx, ry, uhi, ulo);

    int mbp = b * 16 + (s >> 7);
    int rowp = s & 127;
    int ck = base >> 6;
    uint32_t sw = sw128((uint32_t)(rowp * 128 + (base & 63) * 2));
    long pb = (long)mbp * 32;
    *(uint32_t*)((char*)(g_a2 + (pb + ck) * PANEL) + sw)      = uhi;
    *(uint32_t*)((char*)(g_a2 + (pb + 16 + ck) * PANEL) + sw) = ulo;
}

// ---------------- fp16-hi conversion of WEIGHTS into SW128 panels -----------
// dst panels [mb][16][PANEL] (hi only).
__global__ __launch_bounds__(256) void convert_w(
    const float* __restrict__ src, __half* __restrict__ dst) {
    int mb = blockIdx.x >> 4;
    int kb = blockIdx.x & 15;
    int kc0 = kb * 64;
    long pan = (long)mb * 16 + kb;

    int t = threadIdx.x;
#pragma unroll
    for (int q = 0; q < 4; q++) {
        int ch = t + q * 256;
        int r = ch >> 3;
        int c0 = (ch & 7) * 8;
        const float* sp = src + ((long)mb * 128 + r) * 1024 + kc0 + c0;
        float4 f0 = *(const float4*)sp;
        float4 f1 = *(const float4*)(sp + 4);
        float vals[8] = {f0.x, f0.y, f0.z, f0.w, f1.x, f1.y, f1.z, f1.w};
        union { __half h[8]; uint4 u; } pk;
#pragma unroll
        for (int e = 0; e < 8; e++) pk.h[e] = __float2half_rn(vals[e]);
        uint32_t sw = sw128((uint32_t)(r * 128 + c0 * 2));
        *(uint4*)((char*)(dst + pan * PANEL) + sw) = pk.u;
    }
}

// ---------------- fp16 HMMA GEMM: C = (Ah+Al) * Wh^T + bias -----------------
// A panels: 32 chunks/tile (16 hi + 16 lo). W panels: 16 chunks. K = 1024.
// smem stage = [Ah 16KB | Al 16KB | Wh 16KB] = 48KB, double buffered.
__global__ __launch_bounds__(256, 2) void gemm_mma(
    const __half* __restrict__ Apan, int mb_group, int mb_stride,
    const __half* __restrict__ Wpan,
    const float* __restrict__ bias,
    float* __restrict__ C, int ldc,
    const int* __restrict__ perm, int slotOff,
    __half* __restrict__ apDst, float qscale) {
    extern __shared__ char dsm[];
    uint32_t base = smem_u32(dsm);
    uint32_t tiles = (base + 1023u) & ~1023u;

    int tid = threadIdx.x;
    int wid = tid >> 5;
    int lid = tid & 31;
    int wm = wid & 3;
    int wn = wid >> 2;

    int by = blockIdx.y;
    int b = by / mb_group;
    int l = by % mb_group;
    const char* pA = (const char*)(Apan + ((long)(b * mb_stride + l) * 32) * PANEL);
    const char* pW = (const char*)(Wpan + ((long)blockIdx.x * 16) * PANEL);

    float acc[2][8][4];
#pragma unroll
    for (int mt = 0; mt < 2; mt++)
#pragma unroll
        for (int nt = 0; nt < 8; nt++)
#pragma unroll
            for (int e = 0; e < 4; e++) acc[mt][nt][e] = 0.0f;

    int rA0 = wm * 32 + (lid & 15);
    int rB0 = wn * 64 + (lid & 15);
    int cb  = (lid >> 4) * 16;
    uint32_t xm = (uint32_t)((lid & 7) << 4);

    // prologue: stage 0 <- chunk 0 (Ah[0], Al[0], Wh[0])
    {
        uint32_t sa = tiles;
#pragma unroll
        for (int q = 0; q < 12; q++) {
            int ch = tid + q * 256;           // 0..3071
            int reg = ch >> 10;
            int idx = ch & 1023;
            const char* src = (reg == 0) ? (pA + idx * 16)
                            : (reg == 1) ? (pA + 16 * 16384 + idx * 16)
                                         : (pW + idx * 16);
            cp_async16(sa + ch * 16, src);
        }
        CP_COMMIT();
    }

    for (int kb = 0; kb < 16; kb++) {
        if (kb + 1 < 16) {
            uint32_t sa = tiles + (uint32_t)((kb + 1) & 1) * 49152u;
            const char* gAh = pA + (long)(kb + 1) * 16384;
            const char* gAl = pA + (long)(16 + kb + 1) * 16384;
            const char* gW  = pW + (long)(kb + 1) * 16384;
#pragma unroll
            for (int q = 0; q < 12; q++) {
                int ch = tid + q * 256;
                int reg = ch >> 10;
                int idx = ch & 1023;
                const char* src = (reg == 0) ? (gAh + idx * 16)
                                : (reg == 1) ? (gAl + idx * 16)
                                             : (gW + idx * 16);
                cp_async16(sa + ch * 16, src);
            }
            CP_COMMIT();
            CP_WAIT(1);
        } else {
            CP_WAIT(0);
        }
        __syncthreads();

        uint32_t sA = tiles + (uint32_t)(kb & 1) * 49152u;
        uint32_t sW = sA + 32768u;
#pragma unroll
        for (int half = 0; half < 2; half++) {
            uint32_t aB = sA + (uint32_t)half * 16384u;
#pragma unroll
            for (int ks = 0; ks < 4; ks++) {
                uint32_t colb = (uint32_t)(cb + ks * 32) ^ xm;
                uint32_t af[2][4];
                uint32_t bf[4][4];
#pragma unroll
                for (int mt = 0; mt < 2; mt++)
                    ldmat_x4(af[mt], aB + (uint32_t)(rA0 + mt * 16) * 128u + colb);
#pragma unroll
                for (int np = 0; np < 4; np++)
                    ldmat_x4(bf[np], sW + (uint32_t)(rB0 + np * 16) * 128u + colb);
#pragma unroll
                for (int mt = 0; mt < 2; mt++) {
#pragma unroll
                    for (int nt = 0; nt < 8; nt++) {
                        int np = nt >> 1;
                        int sel = nt & 1;
                        mma16816(acc[mt][nt], af[mt], bf[np][sel], bf[np][sel + 2]);
                    }
                }
            }
        }
        __syncthreads();
    }

    int n0 = blockIdx.x * 128;
    if (apDst != nullptr) {
        // write attention hi/lo panels (group g = output-col / 1024)
#pragma unroll
        for (int nt = 0; nt < 8; nt++) {
            int cc = wn * 64 + nt * 8 + (lid & 3) * 2;
            int ng = n0 + cc;
            int g = ng >> 10;
            int head = (ng >> 6) & 15;
            float sc = (g == 0) ? qscale : 1.0f;
            float bx = bias[ng];
            float by2 = bias[ng + 1];
            __half* hiB = apDst + (long)(2 * g) * ATT_T;
            __half* loB = apDst + (long)(2 * g + 1) * ATT_T;
#pragma unroll
            for (int mt = 0; mt < 2; mt++) {
                int r0 = wm * 32 + mt * 16 + (lid >> 2);
#pragma unroll
                for (int half = 0; half < 2; half++) {
                    int tr = l * 128 + r0 + half * 8;
                    int kt = tr >> 6;
                    int row = tr & 63;
                    float vx = (acc[mt][nt][half * 2 + 0] + bx) * sc;
                    float vy = (acc[mt][nt][half * 2 + 1] + by2) * sc;
                    uint32_t uhi, ulo;
                    split2h(vx, vy, uhi, ulo);
                    long pan = (((long)b * PH + head) * 16 + kt) * APAN;
                    uint32_t sw = sw128((uint32_t)(row * 128 + (nt * 8 + (lid & 3) * 2) * 2));
                    *(uint32_t*)((char*)(hiB + pan) + sw) = uhi;
                    *(uint32_t*)((char*)(loB + pan) + sw) = ulo;
                }
            }
        }
    } else {
#pragma unroll
        for (int nt = 0; nt < 8; nt++) {
            int cc = wn * 64 + nt * 8 + (lid & 3) * 2;
            float2 bv;
            bv.x = bias[n0 + cc];
            bv.y = bias[n0 + cc + 1];
#pragma unroll
            for (int mt = 0; mt < 2; mt++) {
                int r0 = wm * 32 + mt * 16 + (lid >> 2);
                float2 v0, v1;
                v0.x = acc[mt][nt][0] + bv.x;
                v0.y = acc[mt][nt][1] + bv.y;
                v1.x = acc[mt][nt][2] + bv.x;
                v1.y = acc[mt][nt][3] + bv.y;
                if (perm != nullptr) {
                    int tok0 = perm[b * PK + l * 128 + r0 + slotOff];
                    int tok1 = perm[b * PK + l * 128 + r0 + 8 + slotOff];
                    *(float2*)(C + ((long)b * PK + tok0) * PD + n0 + cc) = v0;
                    *(float2*)(C + ((long)b * PK + tok1) * PD + n0 + cc) = v1;
                } else {
                    long row = (long)by * 128 + r0;
                    *(float2*)(C + row * ldc + n0 + cc) = v0;
                    *(float2*)(C + (row + 8) * ldc + n0 + cc) = v1;
                }
            }
        }
    }
}

// ---------------- fp16 HMMA flash attention -----------------
// QK 3-term (Qh.Kh + Ql.Kh + Qh.Kl), PV 2-term (Ph.Vh + Pl.Vh).
// block = (qtile 128, h, b). Output -> split GEMM A-panels (32 chunks).
__global__ __launch_bounds__(256) void attn_mma(
    const __half* __restrict__ Aqh, const __half* __restrict__ Aql,
    const __half* __restrict__ Akh, const __half* __restrict__ Akl,
    const __half* __restrict__ Avh,
    __half* __restrict__ Opan) {
    extern __shared__ char dsm[];
    uint32_t base = smem_u32(dsm);
    uint32_t sQ = (base + 1023u) & ~1023u;     // Qh 16KB | Ql 16KB
    uint32_t sT = sQ + 32768u;                 // 2 stages x [Kh|Kl|Vh] 8KB each

    int tid = threadIdx.x, wid = tid >> 5, lid = tid & 31;
    int qt = blockIdx.x, h = blockIdx.y, b = blockIdx.z;
    long pb = ((long)b * PH + h) * 16;

    const char* pQh = (const char*)(Aqh + (pb + qt * 2) * APAN);
    const char* pQl = (const char*)(Aql + (pb + qt * 2) * APAN);
    const char* pKh = (const char*)(Akh + pb * APAN);
    const char* pKl = (const char*)(Akl + pb * APAN);
    const char* pVh = (const char*)(Avh + pb * APAN);

#pragma unroll
    for (int q = 0; q < 8; q++) {
        int ch = tid + q * 256;
        int idx = ch & 1023;
        if (q < 4) cp_async16(sQ + idx * 16, pQh + idx * 16);
        else       cp_async16(sQ + 16384 + idx * 16, pQl + idx * 16);
    }
#pragma unroll
    for (int q = 0; q < 6; q++) {
        int ch = tid + q * 256;       // 0..1535
        int idx = ch & 511;
        const char* s = (q < 2) ? pKh : (q < 4) ? pKl : pVh;
        cp_async16(sT + ch * 16, s + idx * 16);
    }
    CP_COMMIT();
    CP_WAIT(0);
    __syncthreads();

    int cb = (lid >> 4) * 16;
    uint32_t xm = (uint32_t)((lid & 7) << 4);

    uint32_t qra = sQ + (uint32_t)(wid >> 2) * 8192u
                 + (uint32_t)(((wid & 3) * 16 + (lid & 15)) * 128);
    uint32_t qhf[4][4], qlf[4][4];
#pragma unroll
    for (int ks = 0; ks < 4; ks++) {
        uint32_t col = (uint32_t)(ks * 32 + cb) ^ xm;
        ldmat_x4(qhf[ks], qra + col);
        ldmat_x4(qlf[ks], qra + 16384u + col);
    }

    float m0 = -1e30f, m1 = -1e30f, l0 = 0.0f, l1 = 0.0f;
    float oa[8][4];
#pragma unroll
    for (int nt = 0; nt < 8; nt++)
#pragma unroll
        for (int e = 0; e < 4; e++) oa[nt][e] = 0.0f;

    for (int kt = 0; kt < 16; kt++) {
        uint32_t st = sT + (uint32_t)(kt & 1) * 24576u;
        if (kt + 1 < 16) {
            uint32_t sn = sT + (uint32_t)((kt + 1) & 1) * 24576u;
            long off = (long)(kt + 1) * 8192;
#pragma unroll
            for (int q = 0; q < 6; q++) {
                int ch = tid + q * 256;
                int idx = ch & 511;
                const char* s = (q < 2) ? pKh : (q < 4) ? pKl : pVh;
                cp_async16(sn + ch * 16, s + off + idx * 16);
            }
            CP_COMMIT();
        }

        float sc[8][4];
#pragma unroll
        for (int nt = 0; nt < 8; nt++)
#pragma unroll
            for (int e = 0; e < 4; e++) sc[nt][e] = 0.0f;

#pragma unroll
        for (int ks = 0; ks < 4; ks++) {
            uint32_t col = (uint32_t)(ks * 32 + cb) ^ xm;
            uint32_t bh_[4][4], bl_[4][4];
#pragma unroll
            for (int np = 0; np < 4; np++) {
                uint32_t ra = (uint32_t)((np * 16 + (lid & 15)) * 128);
                ldmat_x4(bh_[np], st + ra + col);
                ldmat_x4(bl_[np], st + 8192u + ra + col);
            }
#pragma unroll
            for (int nt = 0; nt < 8; nt++) {
                int np = nt >> 1, sel = nt & 1;
                mma16816(sc[nt], qhf[ks], bh_[np][sel], bh_[np][sel + 2]);
                mma16816(sc[nt], qlf[ks], bh_[np][sel], bh_[np][sel + 2]);
                mma16816(sc[nt], qhf[ks], bl_[np][sel], bl_[np][sel + 2]);
            }
        }

        float mt0 = -1e30f, mt1 = -1e30f;
#pragma unroll
        for (int nt = 0; nt < 8; nt++) {
            mt0 = fmaxf(mt0, fmaxf(sc[nt][0], sc[nt][1]));
            mt1 = fmaxf(mt1, fmaxf(sc[nt][2], sc[nt][3]));
        }
        mt0 = fmaxf(mt0, __shfl_xor_sync(0xffffffffu, mt0, 1));
        mt0 = fmaxf(mt0, __shfl_xor_sync(0xffffffffu, mt0, 2));
        mt1 = fmaxf(mt1, __shfl_xor_sync(0xffffffffu, mt1, 1));
        mt1 = fmaxf(mt1, __shfl_xor_sync(0xffffffffu, mt1, 2));

        float mn0 = fmaxf(m0, mt0), mn1 = fmaxf(m1, mt1);
        float a0 = __expf(m0 - mn0), a1 = __expf(m1 - mn1);

        uint32_t php[8][2], plp[8][2];
        float ps0 = 0.0f, ps1 = 0.0f;
#pragma unroll
        for (int nt = 0; nt < 8; nt++) {
            float p00 = __expf(sc[nt][0] - mn0);
            float p01 = __expf(sc[nt][1] - mn0);
            float p10 = __expf(sc[nt][2] - mn1);
            float p11 = __expf(sc[nt][3] - mn1);
            ps0 += p00 + p01;
            ps1 += p10 + p11;
            uint32_t u0, u1, w0, w1;
            split2h(p00, p01, u0, w0);
            split2h(p10, p11, u1, w1);
            php[nt][0] = u0;  php[nt][1] = u1;
            plp[nt][0] = w0;  plp[nt][1] = w1;
        }
        ps0 += __shfl_xor_sync(0xffffffffu, ps0, 1);
        ps0 += __shfl_xor_sync(0xffffffffu, ps0, 2);
        ps1 += __shfl_xor_sync(0xffffffffu, ps1, 1);
        ps1 += __shfl_xor_sync(0xffffffffu, ps1, 2);

        l0 = l0 * a0 + ps0;
        l1 = l1 * a1 + ps1;
        m0 = mn0;
        m1 = mn1;
#pragma unroll
        for (int nt = 0; nt < 8; nt++) {
            oa[nt][0] *= a0; oa[nt][1] *= a0;
            oa[nt][2] *= a1; oa[nt][3] *= a1;
        }

#pragma unroll
        for (int ks = 0; ks < 4; ks++) {
            uint32_t ah[4] = {php[2 * ks][0], php[2 * ks][1],
                              php[2 * ks + 1][0], php[2 * ks + 1][1]};
            uint32_t al[4] = {plp[2 * ks][0], plp[2 * ks][1],
                              plp[2 * ks + 1][0], plp[2 * ks + 1][1]};
            uint32_t vh_[4][4];
            uint32_t ra = (uint32_t)((ks * 16 + (lid & 15)) * 128);
#pragma unroll
            for (int np = 0; np < 4; np++) {
                uint32_t col = (uint32_t)(np * 32 + cb) ^ xm;
                ldmat_x4_trans(vh_[np], st + 16384u + ra + col);
            }
#pragma unroll
            for (int nt = 0; nt < 8; nt++) {
                int np = nt >> 1, s2 = (nt & 1) * 2;
                mma16816(oa[nt], ah, vh_[np][s2], vh_[np][s2 + 1]);
                mma16816(oa[nt], al, vh_[np][s2], vh_[np][s2 + 1]);
            }
        }

        if (kt + 1 < 16) CP_WAIT(0);
        __syncthreads();
    }

    // epilogue: split A-panels [mb = b*8+qt][32 chunks]; hi -> h, lo -> 16+h
    float i0 = 1.0f / l0, i1 = 1.0f / l1;
    int rl = wid * 16 + (lid >> 2);
    long panB = ((long)b * 8 + qt) * 32;
    __half* c_hi = Opan + (panB + h) * (long)PANEL;
    __half* c_lo = Opan + (panB + 16 + h) * (long)PANEL;
#pragma unroll
    for (int nt = 0; nt < 8; nt++) {
        int col = nt * 8 + (lid & 3) * 2;
        uint32_t sw0 = sw128((uint32_t)(rl * 128 + col * 2));
        uint32_t sw1 = sw128((uint32_t)((rl + 8) * 128 + col * 2));
        uint32_t uhi0, ulo0, uhi1, ulo1;
        split2h(oa[nt][0] * i0, oa[nt][1] * i0, uhi0, ulo0);
        split2h(oa[nt][2] * i1, oa[nt][3] * i1, uhi1, ulo1);
        *(uint32_t*)((char*)c_hi + sw0) = uhi0;
        *(uint32_t*)((char*)c_lo + sw0) = ulo0;
        *(uint32_t*)((char*)c_hi + sw1) = uhi1;
        *(uint32_t*)((char*)c_lo + sw1) = ulo1;
    }
}

// ---------------- launch ----------------
extern "C" void kernel_launch(void* const* d_in, const int* in_sizes, int n_in,
                              void* d_out, int out_size) {
    const float* x         = (const float*)d_in[0];
    const float* coords    = (const float*)d_in[1];
    const void*  is_ctx    = d_in[2];
    const float* rope      = (const float*)d_in[3];
    const float* ctx_in_w  = (const float*)d_in[4];
    const float* ctx_in_b  = (const float*)d_in[5];
    const float* ctx_out_w = (const float*)d_in[6];
    const float* ctx_out_b = (const float*)d_in[7];
    const float* tgt_in_w  = (const float*)d_in[8];
    const float* tgt_in_b  = (const float*)d_in[9];
    const float* tgt_out_w = (const float*)d_in[10];
    const float* tgt_out_b = (const float*)d_in[11];
    float* out = (float*)d_out;

    int* perm = 0;     cudaGetSymbolAddress((void**)&perm, g_perm);
    __half* a2 = 0;    cudaGetSymbolAddress((void**)&a2, g_a2);
    __half* wc = 0;    cudaGetSymbolAddress((void**)&wc, g_wc);
    __half* wt = 0;    cudaGetSymbolAddress((void**)&wt, g_wt);
    __half* wco = 0;   cudaGetSymbolAddress((void**)&wco, g_wco);
    __half* wto = 0;   cudaGetSymbolAddress((void**)&wto, g_wto);
    __half* oc2 = 0;   cudaGetSymbolAddress((void**)&oc2, g_oc2);
    __half* ot2 = 0;   cudaGetSymbolAddress((void**)&ot2, g_ot2);
    __half* ap = 0;    cudaGetSymbolAddress((void**)&ap, g_ap);

    const int GSM = 1024 + 2 * 49152;   // 99328
    const int ASM = 1024 + 32768 + 2 * 24576;  // 82944
    cudaFuncSetAttribute(gemm_mma, cudaFuncAttributeMaxDynamicSharedMemorySize, GSM);
    cudaFuncSetAttribute(attn_mma, cudaFuncAttributeMaxDynamicSharedMemorySize, ASM);

    build_perm<<<PB, 32>>>(is_ctx, perm);
    rope_gather<<<PB * PK, 512>>>(x, coords, rope);

    // weight conversions (hi fp16 only, 16 chunks per 128-row tile)
    convert_w<<<24 * 16, 256>>>(ctx_in_w,  wc);
    convert_w<<<24 * 16, 256>>>(tgt_in_w,  wt);
    convert_w<<< 8 * 16, 256>>>(ctx_out_w, wco);
    convert_w<<< 8 * 16, 256>>>(tgt_out_w, wto);

    // projections -> attention panels directly
    gemm_mma<<<dim3(24, 32), 256, GSM>>>(a2, 8, 16, wc, ctx_in_b,
                                         nullptr, 0, nullptr, 0,
                                         ap, 0.125f);
    gemm_mma<<<dim3(16, 32), 256, GSM>>>(a2, 8, 16, wt + 8ll * 16 * PANEL,
                                         tgt_in_b + 1024,
                                         nullptr, 0, nullptr, 0,
                                         ap + 8ll * ATT_T, 1.0f);
    gemm_mma<<<dim3(8, 32), 256, GSM>>>(a2 + 8ll * 32 * PANEL, 8, 16, wt,
                                        tgt_in_b,
                                        nullptr, 0, nullptr, 0,
                                        ap + 6ll * ATT_T, 0.125f);

    // HMMA attention -> split A-panels directly
    attn_mma<<<dim3(8, PH, PB), 256, ASM>>>(
        ap + 0ll * ATT_T, ap + 1ll * ATT_T, ap + 2ll * ATT_T,
        ap + 3ll * ATT_T, ap + 4ll * ATT_T, oc2);
    attn_mma<<<dim3(8, PH, PB), 256, ASM>>>(
        ap + 6ll * ATT_T, ap + 7ll * ATT_T, ap + 8ll * ATT_T,
        ap + 9ll * ATT_T, ap + 10ll * ATT_T, ot2);

    // output projections + fused scatter to original token order
    gemm_mma<<<dim3(8, 32), 256, GSM>>>(oc2, 8, 8, wco, ctx_out_b,
                                        out, PD, perm, 0, nullptr, 0.0f);
    gemm_mma<<<dim3(8, 32), 256, GSM>>>(ot2, 8, 8, wto, tgt_out_b,
                                        out, PD, perm, PNC, nullptr, 0.0f);
}

// round 9
// speedup vs baseline: 3.9876x; 1.1530x over previous
#include <cuda_runtime.h>
#include <cuda_fp16.h>
#include <cstdint>

// Problem constants
#define PB   4
#define PK   2048
#define PD   1024
#define PH   16
#define PNC  1024   // NCTX = K/2

#define PANEL 8192      // fp16 elems per 128x64 tile panel (16KB)
#define APAN  4096      // fp16 elems per 64x64 attention panel (8KB)
#define ATT_T (PB * PH * 16 * APAN)

// ---------------- scratch (device globals: allocation-free) ----------------
__device__ __align__(256) int g_perm[PB * PK];
// split-fp16 swizzled tile panels. A panels: 32 chunks (16 hi + 16 lo).
// W panels: 16 chunks (hi only).
__device__ __align__(256) __half g_a2 [64ll * 32 * PANEL];
__device__ __align__(256) __half g_wc [24ll * 16 * PANEL];
__device__ __align__(256) __half g_wt [24ll * 16 * PANEL];
__device__ __align__(256) __half g_wco[ 8ll * 16 * PANEL];
__device__ __align__(256) __half g_wto[ 8ll * 16 * PANEL];
__device__ __align__(256) __half g_oc2[32ll * 32 * PANEL];
__device__ __align__(256) __half g_ot2[32ll * 32 * PANEL];
// attention panels: 0..5 ctx {Qh,Ql,Kh,Kl,Vh,Vl}, 6..11 tgt
__device__ __align__(256) __half g_ap[12ll * ATT_T];

// ---------------- PTX helpers (base-PTX only) ----------------
__device__ __forceinline__ uint32_t smem_u32(const void* p) {
    uint32_t a;
    asm("{ .reg .u64 t; cvta.to.shared.u64 t, %1; cvt.u32.u64 %0, t; }" : "=r"(a) : "l"(p));
    return a;
}

__device__ __forceinline__ void cp_async16(uint32_t s, const void* g) {
    asm volatile("cp.async.cg.shared.global [%0], [%1], 16;" :: "r"(s), "l"(g));
}
#define CP_COMMIT() asm volatile("cp.async.commit_group;" ::: "memory")
#define CP_WAIT(n)  asm volatile("cp.async.wait_group %0;" :: "n"(n) : "memory")

__device__ __forceinline__ void ldmat_x4(uint32_t* r, uint32_t addr) {
    asm volatile("ldmatrix.sync.aligned.m8n8.x4.shared.b16 {%0,%1,%2,%3}, [%4];"
                 : "=r"(r[0]), "=r"(r[1]), "=r"(r[2]), "=r"(r[3]) : "r"(addr));
}

__device__ __forceinline__ void ldmat_x4_trans(uint32_t* r, uint32_t addr) {
    asm volatile("ldmatrix.sync.aligned.m8n8.x4.trans.shared.b16 {%0,%1,%2,%3}, [%4];"
                 : "=r"(r[0]), "=r"(r[1]), "=r"(r[2]), "=r"(r[3]) : "r"(addr));
}

__device__ __forceinline__ void mma16816(float* c, const uint32_t* a,
                                         uint32_t b0, uint32_t b1) {
    asm volatile(
        "mma.sync.aligned.m16n8k16.row.col.f32.f16.f16.f32 "
        "{%0,%1,%2,%3}, {%4,%5,%6,%7}, {%8,%9}, {%0,%1,%2,%3};"
        : "+f"(c[0]), "+f"(c[1]), "+f"(c[2]), "+f"(c[3])
        : "r"(a[0]), "r"(a[1]), "r"(a[2]), "r"(a[3]), "r"(b0), "r"(b1));
}

__device__ __forceinline__ uint32_t packh2(float lo, float hi) {
    __half2 h = __floats2half2_rn(lo, hi);
    return *(uint32_t*)&h;
}

__device__ __forceinline__ void split2h(float vx, float vy,
                                        uint32_t& uhi, uint32_t& ulo) {
    __half2 h = __floats2half2_rn(vx, vy);
    uhi = *(uint32_t*)&h;
    float hx = __half2float(__low2half(h));
    float hy = __half2float(__high2half(h));
    ulo = packh2(vx - hx, vy - hy);
}

__device__ __forceinline__ uint32_t sw128(uint32_t off) {
    return off ^ ((off >> 3) & 0x70);
}

// ---------------- perm (dtype-agnostic detection) ----------------
__global__ void build_perm(const void* __restrict__ is_ctx_raw) {
    const unsigned char* u8  = (const unsigned char*)is_ctx_raw;
    const unsigned int*  u32 = (const unsigned int*)is_ctx_raw;
    int b = blockIdx.x;
    int lane = threadIdx.x;

    int s = 0;
    for (int i = lane; i < 2048; i += 32) s += (int)u8[i];
#pragma unroll
    for (int off = 16; off; off >>= 1) s += __shfl_xor_sync(0xffffffffu, s, off);
    bool one_byte = (s == 1024) || (s == 255 * 1024);

    int cbase = 0, tbase = PNC;
    for (int j0 = 0; j0 < PK; j0 += 32) {
        int j = j0 + lane;
        int c = one_byte ? (u8[b * PK + j] != 0) : (u32[b * PK + j] != 0u);
        unsigned mask = __ballot_sync(0xffffffffu, c);
        int pre = __popc(mask & ((1u << lane) - 1u));
        int slot = c ? (cbase + pre) : (tbase + lane - pre);
        g_perm[b * PK + slot] = j;
        int nc = __popc(mask);
        cbase += nc;
        tbase += 32 - nc;
    }
}

// ---------------- RoPE + gather -> a2 panels directly -----------------------
__global__ __launch_bounds__(512) void rope_gather(
    const float* __restrict__ x, const float* __restrict__ coords,
    const float* __restrict__ rope) {
    int s = blockIdx.x & (PK - 1);
    int b = blockIdx.x >> 11;
    int j = g_perm[b * PK + s];
    long tokin = (long)b * PK + j;

    float cy = coords[tokin * 2 + 0];
    float cx = coords[tokin * 2 + 1];
    int ypos = (int)fminf(fmaxf(cy / 224.0f * 1023.0f, 0.0f), 1023.0f);
    int xpos = (int)fminf(fmaxf(cx / 224.0f * 1023.0f, 0.0f), 1023.0f);

    int t = threadIdx.x;
    int i = t & 255;
    int pos = (t < 256) ? xpos : ypos;
    int base = (t < 256) ? (2 * i) : (512 + 2 * i);

    float c  = rope[((long)pos * 256 + i) * 2 + 0];
    float sn = rope[((long)pos * 256 + i) * 2 + 1];
    float2 p = *(const float2*)(x + tokin * PD + base);
    float rx = p.x * c - p.y * sn;
    float ry = p.x * sn + p.y * c;

    uint32_t uhi, ulo;
    split2h(rx, ry, uhi, ulo);

    int mbp = b * 16 + (s >> 7);
    int rowp = s & 127;
    int ck = base >> 6;
    uint32_t sw = sw128((uint32_t)(rowp * 128 + (base & 63) * 2));
    long pb = (long)mbp * 32;
    *(uint32_t*)((char*)(g_a2 + (pb + ck) * PANEL) + sw)      = uhi;
    *(uint32_t*)((char*)(g_a2 + (pb + 16 + ck) * PANEL) + sw) = ulo;
}

// ---------------- merged fp16-hi conversion of ALL weights ------------------
// 64 global mb tiles: 0..23 -> g_wc, 24..47 -> g_wt, 48..55 -> g_wco, 56..63 -> g_wto
__global__ __launch_bounds__(256) void convert_w_all(
    const float* __restrict__ s_ci, const float* __restrict__ s_ti,
    const float* __restrict__ s_co, const float* __restrict__ s_to) {
    int gm = blockIdx.x >> 4;
    int kb = blockIdx.x & 15;
    const float* src;
    __half* dst;
    int mb;
    if (gm < 24)      { src = s_ci; dst = g_wc;  mb = gm; }
    else if (gm < 48) { src = s_ti; dst = g_wt;  mb = gm - 24; }
    else if (gm < 56) { src = s_co; dst = g_wco; mb = gm - 48; }
    else              { src = s_to; dst = g_wto; mb = gm - 56; }
    int kc0 = kb * 64;
    long pan = (long)mb * 16 + kb;

    int t = threadIdx.x;
#pragma unroll
    for (int q = 0; q < 4; q++) {
        int ch = t + q * 256;
        int r = ch >> 3;
        int c0 = (ch & 7) * 8;
        const float* sp = src + ((long)mb * 128 + r) * 1024 + kc0 + c0;
        float4 f0 = *(const float4*)sp;
        float4 f1 = *(const float4*)(sp + 4);
        float vals[8] = {f0.x, f0.y, f0.z, f0.w, f1.x, f1.y, f1.z, f1.w};
        union { __half h[8]; uint4 u; } pk;
#pragma unroll
        for (int e = 0; e < 8; e++) pk.h[e] = __float2half_rn(vals[e]);
        uint32_t sw = sw128((uint32_t)(r * 128 + c0 * 2));
        *(uint4*)((char*)(dst + pan * PANEL) + sw) = pk.u;
    }
}

// ---------------- shared GEMM mainloop (fp16, A 2-term) ---------------------
// acc += (Ah+Al) * Wh^T over K=1024. Stage = [Ah 16KB | Al 16KB | Wh 16KB].
__device__ __forceinline__ void gemm_mainloop(
    const char* pA, const char* pW, uint32_t tiles,
    int tid, int rA0, int rB0, int cb, uint32_t xm,
    float acc[2][8][4]) {
    {
        uint32_t sa = tiles;
#pragma unroll
        for (int q = 0; q < 12; q++) {
            int ch = tid + q * 256;
            int reg = ch >> 10;
            int idx = ch & 1023;
            const char* src = (reg == 0) ? (pA + idx * 16)
                            : (reg == 1) ? (pA + 16 * 16384 + idx * 16)
                                         : (pW + idx * 16);
            cp_async16(sa + ch * 16, src);
        }
        CP_COMMIT();
    }

    for (int kb = 0; kb < 16; kb++) {
        if (kb + 1 < 16) {
            uint32_t sa = tiles + (uint32_t)((kb + 1) & 1) * 49152u;
            const char* gAh = pA + (long)(kb + 1) * 16384;
            const char* gAl = pA + (long)(16 + kb + 1) * 16384;
            const char* gW  = pW + (long)(kb + 1) * 16384;
#pragma unroll
            for (int q = 0; q < 12; q++) {
                int ch = tid + q * 256;
                int reg = ch >> 10;
                int idx = ch & 1023;
                const char* src = (reg == 0) ? (gAh + idx * 16)
                                : (reg == 1) ? (gAl + idx * 16)
                                             : (gW + idx * 16);
                cp_async16(sa + ch * 16, src);
            }
            CP_COMMIT();
            CP_WAIT(1);
        } else {
            CP_WAIT(0);
        }
        __syncthreads();

        uint32_t sA = tiles + (uint32_t)(kb & 1) * 49152u;
        uint32_t sW = sA + 32768u;
#pragma unroll
        for (int half = 0; half < 2; half++) {
            uint32_t aB = sA + (uint32_t)half * 16384u;
#pragma unroll
            for (int ks = 0; ks < 4; ks++) {
                uint32_t colb = (uint32_t)(cb + ks * 32) ^ xm;
                uint32_t af[2][4];
                uint32_t bf[4][4];
#pragma unroll
                for (int mt = 0; mt < 2; mt++)
                    ldmat_x4(af[mt], aB + (uint32_t)(rA0 + mt * 16) * 128u + colb);
#pragma unroll
                for (int np = 0; np < 4; np++)
                    ldmat_x4(bf[np], sW + (uint32_t)(rB0 + np * 16) * 128u + colb);
#pragma unroll
                for (int mt = 0; mt < 2; mt++) {
#pragma unroll
                    for (int nt = 0; nt < 8; nt++) {
                        int np = nt >> 1;
                        int sel = nt & 1;
                        mma16816(acc[mt][nt], af[mt], bf[np][sel], bf[np][sel + 2]);
                    }
                }
            }
        }
        __syncthreads();
    }
}

// ---------------- merged projection GEMM -> attention panels ----------------
// grid (48, 32): x<24 ctx qkv, x<40 tgt kv, else tgt q.
__global__ __launch_bounds__(256, 2) void gemm_proj(
    const float* __restrict__ ctx_in_b, const float* __restrict__ tgt_in_b) {
    extern __shared__ char dsm[];
    uint32_t base = smem_u32(dsm);
    uint32_t tiles = (base + 1023u) & ~1023u;

    int tid = threadIdx.x;
    int wid = tid >> 5;
    int lid = tid & 31;
    int wm = wid & 3;
    int wn = wid >> 2;

    int nx = blockIdx.x;
    const __half* Apan;
    const __half* Wpan;
    const float* bias;
    __half* apDst;
    float qscale;
    int nloc;
    if (nx < 24) {
        Apan = g_a2; Wpan = g_wc; bias = ctx_in_b;
        apDst = g_ap; qscale = 0.125f; nloc = nx;
    } else if (nx < 40) {
        Apan = g_a2; Wpan = g_wt + 8ll * 16 * PANEL; bias = tgt_in_b + 1024;
        apDst = g_ap + 8ll * ATT_T; qscale = 1.0f; nloc = nx - 24;
    } else {
        Apan = g_a2 + 8ll * 32 * PANEL; Wpan = g_wt; bias = tgt_in_b;
        apDst = g_ap + 6ll * ATT_T; qscale = 0.125f; nloc = nx - 40;
    }

    int by = blockIdx.y;
    int b = by >> 3;
    int l = by & 7;
    const char* pA = (const char*)(Apan + ((long)(b * 16 + l) * 32) * PANEL);
    const char* pW = (const char*)(Wpan + ((long)nloc * 16) * PANEL);

    float acc[2][8][4];
#pragma unroll
    for (int mt = 0; mt < 2; mt++)
#pragma unroll
        for (int nt = 0; nt < 8; nt++)
#pragma unroll
            for (int e = 0; e < 4; e++) acc[mt][nt][e] = 0.0f;

    int rA0 = wm * 32 + (lid & 15);
    int rB0 = wn * 64 + (lid & 15);
    int cb  = (lid >> 4) * 16;
    uint32_t xm = (uint32_t)((lid & 7) << 4);

    gemm_mainloop(pA, pW, tiles, tid, rA0, rB0, cb, xm, acc);

    int n0 = nloc * 128;
#pragma unroll
    for (int nt = 0; nt < 8; nt++) {
        int cc = wn * 64 + nt * 8 + (lid & 3) * 2;
        int ng = n0 + cc;
        int g = ng >> 10;
        int head = (ng >> 6) & 15;
        float sc = (g == 0) ? qscale : 1.0f;
        float bx = bias[ng];
        float by2 = bias[ng + 1];
        __half* hiB = apDst + (long)(2 * g) * ATT_T;
        __half* loB = apDst + (long)(2 * g + 1) * ATT_T;
#pragma unroll
        for (int mt = 0; mt < 2; mt++) {
            int r0 = wm * 32 + mt * 16 + (lid >> 2);
#pragma unroll
            for (int half = 0; half < 2; half++) {
                int tr = l * 128 + r0 + half * 8;
                int kt = tr >> 6;
                int row = tr & 63;
                float vx = (acc[mt][nt][half * 2 + 0] + bx) * sc;
                float vy = (acc[mt][nt][half * 2 + 1] + by2) * sc;
                uint32_t uhi, ulo;
                split2h(vx, vy, uhi, ulo);
                long pan = (((long)b * PH + head) * 16 + kt) * APAN;
                uint32_t sw = sw128((uint32_t)(row * 128 + (nt * 8 + (lid & 3) * 2) * 2));
                *(uint32_t*)((char*)(hiB + pan) + sw) = uhi;
                *(uint32_t*)((char*)(loB + pan) + sw) = ulo;
            }
        }
    }
}

// ---------------- merged output projection -> d_out (perm scatter) ----------
// grid (8, 64): y<32 ctx, else tgt.
__global__ __launch_bounds__(256, 2) void gemm_out(
    const float* __restrict__ ctx_out_b, const float* __restrict__ tgt_out_b,
    float* __restrict__ C) {
    extern __shared__ char dsm[];
    uint32_t base = smem_u32(dsm);
    uint32_t tiles = (base + 1023u) & ~1023u;

    int tid = threadIdx.x;
    int wid = tid >> 5;
    int lid = tid & 31;
    int wm = wid & 3;
    int wn = wid >> 2;

    int y = blockIdx.y;
    const __half* Apan;
    const __half* Wpan;
    const float* bias;
    int slotOff;
    if (y < 32) {
        Apan = g_oc2; Wpan = g_wco; bias = ctx_out_b; slotOff = 0;
    } else {
        Apan = g_ot2; Wpan = g_wto; bias = tgt_out_b; slotOff = PNC;
        y -= 32;
    }
    int b = y >> 3;
    int l = y & 7;
    const char* pA = (const char*)(Apan + ((long)(b * 8 + l) * 32) * PANEL);
    const char* pW = (const char*)(Wpan + ((long)blockIdx.x * 16) * PANEL);

    float acc[2][8][4];
#pragma unroll
    for (int mt = 0; mt < 2; mt++)
#pragma unroll
        for (int nt = 0; nt < 8; nt++)
#pragma unroll
            for (int e = 0; e < 4; e++) acc[mt][nt][e] = 0.0f;

    int rA0 = wm * 32 + (lid & 15);
    int rB0 = wn * 64 + (lid & 15);
    int cb  = (lid >> 4) * 16;
    uint32_t xm = (uint32_t)((lid & 7) << 4);

    gemm_mainloop(pA, pW, tiles, tid, rA0, rB0, cb, xm, acc);

    int n0 = blockIdx.x * 128;
#pragma unroll
    for (int nt = 0; nt < 8; nt++) {
        int cc = wn * 64 + nt * 8 + (lid & 3) * 2;
        float2 bv;
        bv.x = bias[n0 + cc];
        bv.y = bias[n0 + cc + 1];
#pragma unroll
        for (int mt = 0; mt < 2; mt++) {
            int r0 = wm * 32 + mt * 16 + (lid >> 2);
            float2 v0, v1;
            v0.x = acc[mt][nt][0] + bv.x;
            v0.y = acc[mt][nt][1] + bv.y;
            v1.x = acc[mt][nt][2] + bv.x;
            v1.y = acc[mt][nt][3] + bv.y;
            int tok0 = g_perm[b * PK + l * 128 + r0 + slotOff];
            int tok1 = g_perm[b * PK + l * 128 + r0 + 8 + slotOff];
            *(float2*)(C + ((long)b * PK + tok0) * PD + n0 + cc) = v0;
            *(float2*)(C + ((long)b * PK + tok1) * PD + n0 + cc) = v1;
        }
    }
}

// ---------------- merged fp16 HMMA flash attention --------------------------
// grid (8, 16, 8): z<4 ctx (b=z), else tgt (b=z-4).
// QK 3-term, PV 2-term. Output -> split GEMM A-panels (32 chunks).
__global__ __launch_bounds__(256) void attn_mma() {
    extern __shared__ char dsm[];
    uint32_t base = smem_u32(dsm);
    uint32_t sQ = (base + 1023u) & ~1023u;     // Qh 16KB | Ql 16KB
    uint32_t sT = sQ + 32768u;                 // 2 stages x [Kh|Kl|Vh] 8KB each

    int tid = threadIdx.x, wid = tid >> 5, lid = tid & 31;
    int qt = blockIdx.x, h = blockIdx.y, z = blockIdx.z;
    int b;
    const __half* baseAp;
    __half* Opan;
    if (z < 4) { b = z;     baseAp = g_ap;                 Opan = g_oc2; }
    else       { b = z - 4; baseAp = g_ap + 6ll * ATT_T;   Opan = g_ot2; }

    long pb = ((long)b * PH + h) * 16;
    const char* pQh = (const char*)(baseAp + 0ll * ATT_T + (pb + qt * 2) * APAN);
    const char* pQl = (const char*)(baseAp + 1ll * ATT_T + (pb + qt * 2) * APAN);
    const char* pKh = (const char*)(baseAp + 2ll * ATT_T + pb * APAN);
    const char* pKl = (const char*)(baseAp + 3ll * ATT_T + pb * APAN);
    const char* pVh = (const char*)(baseAp + 4ll * ATT_T + pb * APAN);

#pragma unroll
    for (int q = 0; q < 8; q++) {
        int ch = tid + q * 256;
        int idx = ch & 1023;
        if (q < 4) cp_async16(sQ + idx * 16, pQh + idx * 16);
        else       cp_async16(sQ + 16384 + idx * 16, pQl + idx * 16);
    }
#pragma unroll
    for (int q = 0; q < 6; q++) {
        int ch = tid + q * 256;
        int idx = ch & 511;
        const char* s = (q < 2) ? pKh : (q < 4) ? pKl : pVh;
        cp_async16(sT + ch * 16, s + idx * 16);
    }
    CP_COMMIT();
    CP_WAIT(0);
    __syncthreads();

    int cb = (lid >> 4) * 16;
    uint32_t xm = (uint32_t)((lid & 7) << 4);

    uint32_t qra = sQ + (uint32_t)(wid >> 2) * 8192u
                 + (uint32_t)(((wid & 3) * 16 + (lid & 15)) * 128);
    uint32_t qhf[4][4], qlf[4][4];
#pragma unroll
    for (int ks = 0; ks < 4; ks++) {
        uint32_t col = (uint32_t)(ks * 32 + cb) ^ xm;
        ldmat_x4(qhf[ks], qra + col);
        ldmat_x4(qlf[ks], qra + 16384u + col);
    }

    float m0 = -1e30f, m1 = -1e30f, l0 = 0.0f, l1 = 0.0f;
    float oa[8][4];
#pragma unroll
    for (int nt = 0; nt < 8; nt++)
#pragma unroll
        for (int e = 0; e < 4; e++) oa[nt][e] = 0.0f;

    for (int kt = 0; kt < 16; kt++) {
        uint32_t st = sT + (uint32_t)(kt & 1) * 24576u;
        if (kt + 1 < 16) {
            uint32_t sn = sT + (uint32_t)((kt + 1) & 1) * 24576u;
            long off = (long)(kt + 1) * 8192;
#pragma unroll
            for (int q = 0; q < 6; q++) {
                int ch = tid + q * 256;
                int idx = ch & 511;
                const char* s = (q < 2) ? pKh : (q < 4) ? pKl : pVh;
                cp_async16(sn + ch * 16, s + off + idx * 16);
            }
            CP_COMMIT();
        }

        float sc[8][4];
#pragma unroll
        for (int nt = 0; nt < 8; nt++)
#pragma unroll
            for (int e = 0; e < 4; e++) sc[nt][e] = 0.0f;

#pragma unroll
        for (int ks = 0; ks < 4; ks++) {
            uint32_t col = (uint32_t)(ks * 32 + cb) ^ xm;
            uint32_t bh_[4][4], bl_[4][4];
#pragma unroll
            for (int np = 0; np < 4; np++) {
                uint32_t ra = (uint32_t)((np * 16 + (lid & 15)) * 128);
                ldmat_x4(bh_[np], st + ra + col);
                ldmat_x4(bl_[np], st + 8192u + ra + col);
            }
#pragma unroll
            for (int nt = 0; nt < 8; nt++) {
                int np = nt >> 1, sel = nt & 1;
                mma16816(sc[nt], qhf[ks], bh_[np][sel], bh_[np][sel + 2]);
                mma16816(sc[nt], qlf[ks], bh_[np][sel], bh_[np][sel + 2]);
                mma16816(sc[nt], qhf[ks], bl_[np][sel], bl_[np][sel + 2]);
            }
        }

        float mt0 = -1e30f, mt1 = -1e30f;
#pragma unroll
        for (int nt = 0; nt < 8; nt++) {
            mt0 = fmaxf(mt0, fmaxf(sc[nt][0], sc[nt][1]));
            mt1 = fmaxf(mt1, fmaxf(sc[nt][2], sc[nt][3]));
        }
        mt0 = fmaxf(mt0, __shfl_xor_sync(0xffffffffu, mt0, 1));
        mt0 = fmaxf(mt0, __shfl_xor_sync(0xffffffffu, mt0, 2));
        mt1 = fmaxf(mt1, __shfl_xor_sync(0xffffffffu, mt1, 1));
        mt1 = fmaxf(mt1, __shfl_xor_sync(0xffffffffu, mt1, 2));

        float mn0 = fmaxf(m0, mt0), mn1 = fmaxf(m1, mt1);
        float a0 = __expf(m0 - mn0), a1 = __expf(m1 - mn1);

        uint32_t php[8][2], plp[8][2];
        float ps0 = 0.0f, ps1 = 0.0f;
#pragma unroll
        for (int nt = 0; nt < 8; nt++) {
            float p00 = __expf(sc[nt][0] - mn0);
            float p01 = __expf(sc[nt][1] - mn0);
            float p10 = __expf(sc[nt][2] - mn1);
            float p11 = __expf(sc[nt][3] - mn1);
            ps0 += p00 + p01;
            ps1 += p10 + p11;
            uint32_t u0, u1, w0, w1;
            split2h(p00, p01, u0, w0);
            split2h(p10, p11, u1, w1);
            php[nt][0] = u0;  php[nt][1] = u1;
            plp[nt][0] = w0;  plp[nt][1] = w1;
        }
        ps0 += __shfl_xor_sync(0xffffffffu, ps0, 1);
        ps0 += __shfl_xor_sync(0xffffffffu, ps0, 2);
        ps1 += __shfl_xor_sync(0xffffffffu, ps1, 1);
        ps1 += __shfl_xor_sync(0xffffffffu, ps1, 2);

        l0 = l0 * a0 + ps0;
        l1 = l1 * a1 + ps1;
        m0 = mn0;
        m1 = mn1;
#pragma unroll
        for (int nt = 0; nt < 8; nt++) {
            oa[nt][0] *= a0; oa[nt][1] *= a0;
            oa[nt][2] *= a1; oa[nt][3] *= a1;
        }

#pragma unroll
        for (int ks = 0; ks < 4; ks++) {
            uint32_t ah[4] = {php[2 * ks][0], php[2 * ks][1],
                              php[2 * ks + 1][0], php[2 * ks + 1][1]};
            uint32_t al[4] = {plp[2 * ks][0], plp[2 * ks][1],
                              plp[2 * ks + 1][0], plp[2 * ks + 1][1]};
            uint32_t vh_[4][4];
            uint32_t ra = (uint32_t)((ks * 16 + (lid & 15)) * 128);
#pragma unroll
            for (int np = 0; np < 4; np++) {
                uint32_t col = (uint32_t)(np * 32 + cb) ^ xm;
                ldmat_x4_trans(vh_[np], st + 16384u + ra + col);
            }
#pragma unroll
            for (int nt = 0; nt < 8; nt++) {
                int np = nt >> 1, s2 = (nt & 1) * 2;
                mma16816(oa[nt], ah, vh_[np][s2], vh_[np][s2 + 1]);
                mma16816(oa[nt], al, vh_[np][s2], vh_[np][s2 + 1]);
            }
        }

        if (kt + 1 < 16) CP_WAIT(0);
        __syncthreads();
    }

    // epilogue: split A-panels [mb = b*8+qt][32 chunks]; hi -> h, lo -> 16+h
    float i0 = 1.0f / l0, i1 = 1.0f / l1;
    int rl = wid * 16 + (lid >> 2);
    long panB = ((long)b * 8 + qt) * 32;
    __half* c_hi = Opan + (panB + h) * (long)PANEL;
    __half* c_lo = Opan + (panB + 16 + h) * (long)PANEL;
#pragma unroll
    for (int nt = 0; nt < 8; nt++) {
        int col = nt * 8 + (lid & 3) * 2;
        uint32_t sw0 = sw128((uint32_t)(rl * 128 + col * 2));
        uint32_t sw1 = sw128((uint32_t)((rl + 8) * 128 + col * 2));
        uint32_t uhi0, ulo0, uhi1, ulo1;
        split2h(oa[nt][0] * i0, oa[nt][1] * i0, uhi0, ulo0);
        split2h(oa[nt][2] * i1, oa[nt][3] * i1, uhi1, ulo1);
        *(uint32_t*)((char*)c_hi + sw0) = uhi0;
        *(uint32_t*)((char*)c_lo + sw0) = ulo0;
        *(uint32_t*)((char*)c_hi + sw1) = uhi1;
        *(uint32_t*)((char*)c_lo + sw1) = ulo1;
    }
}

// ---------------- launch ----------------
extern "C" void kernel_launch(void* const* d_in, const int* in_sizes, int n_in,
                              void* d_out, int out_size) {
    const float* x         = (const float*)d_in[0];
    const float* coords    = (const float*)d_in[1];
    const void*  is_ctx    = d_in[2];
    const float* rope      = (const float*)d_in[3];
    const float* ctx_in_w  = (const float*)d_in[4];
    const float* ctx_in_b  = (const float*)d_in[5];
    const float* ctx_out_w = (const float*)d_in[6];
    const float* ctx_out_b = (const float*)d_in[7];
    const float* tgt_in_w  = (const float*)d_in[8];
    const float* tgt_in_b  = (const float*)d_in[9];
    const float* tgt_out_w = (const float*)d_in[10];
    const float* tgt_out_b = (const float*)d_in[11];
    float* out = (float*)d_out;

    const int GSM = 1024 + 2 * 49152;           // 99328
    const int ASM = 1024 + 32768 + 2 * 24576;   // 82944
    cudaFuncSetAttribute(gemm_proj, cudaFuncAttributeMaxDynamicSharedMemorySize, GSM);
    cudaFuncSetAttribute(gemm_out,  cudaFuncAttributeMaxDynamicSharedMemorySize, GSM);
    cudaFuncSetAttribute(attn_mma,  cudaFuncAttributeMaxDynamicSharedMemorySize, ASM);

    build_perm<<<PB, 32>>>(is_ctx);
    rope_gather<<<PB * PK, 512>>>(x, coords, rope);
    convert_w_all<<<64 * 16, 256>>>(ctx_in_w, tgt_in_w, ctx_out_w, tgt_out_w);
    gemm_proj<<<dim3(48, 32), 256, GSM>>>(ctx_in_b, tgt_in_b);
    attn_mma<<<dim3(8, PH, 2 * PB), 256, ASM>>>();
    gemm_out<<<dim3(8, 64), 256, GSM>>>(ctx_out_b, tgt_out_b, out);
}

// round 10
// speedup vs baseline: 4.2016x; 1.0537x over previous
#include <cuda_runtime.h>
#include <cuda_fp16.h>
#include <cstdint>

// Problem constants
#define PB   4
#define PK   2048
#define PD   1024
#define PH   16
#define PNC  1024   // NCTX = K/2

#define PANEL 8192      // fp16 elems per 128x64 tile panel (16KB)
#define APAN  4096      // fp16 elems per 64x64 attention panel (8KB)
#define ATT_T (PB * PH * 16 * APAN)

// ---------------- scratch (device globals: allocation-free) ----------------
__device__ __align__(256) int g_perm[PB * PK];
// split-fp16 swizzled tile panels. A panels: 32 chunks (16 hi + 16 lo).
// W panels: 16 chunks (hi only).
__device__ __align__(256) __half g_a2 [64ll * 32 * PANEL];
__device__ __align__(256) __half g_wc [24ll * 16 * PANEL];
__device__ __align__(256) __half g_wt [24ll * 16 * PANEL];
__device__ __align__(256) __half g_wco[ 8ll * 16 * PANEL];
__device__ __align__(256) __half g_wto[ 8ll * 16 * PANEL];
__device__ __align__(256) __half g_oc2[32ll * 32 * PANEL];
__device__ __align__(256) __half g_ot2[32ll * 32 * PANEL];
// attention panels: 0..5 ctx {Qh,Ql,Kh,Kl,Vh,Vl}, 6..11 tgt
__device__ __align__(256) __half g_ap[12ll * ATT_T];

// ---------------- PTX helpers (base-PTX only) ----------------
__device__ __forceinline__ uint32_t smem_u32(const void* p) {
    uint32_t a;
    asm("{ .reg .u64 t; cvta.to.shared.u64 t, %1; cvt.u32.u64 %0, t; }" : "=r"(a) : "l"(p));
    return a;
}

__device__ __forceinline__ void cp_async16(uint32_t s, const void* g) {
    asm volatile("cp.async.cg.shared.global [%0], [%1], 16;" :: "r"(s), "l"(g));
}
#define CP_COMMIT() asm volatile("cp.async.commit_group;" ::: "memory")
#define CP_WAIT(n)  asm volatile("cp.async.wait_group %0;" :: "n"(n) : "memory")

__device__ __forceinline__ void ldmat_x4(uint32_t* r, uint32_t addr) {
    asm volatile("ldmatrix.sync.aligned.m8n8.x4.shared.b16 {%0,%1,%2,%3}, [%4];"
                 : "=r"(r[0]), "=r"(r[1]), "=r"(r[2]), "=r"(r[3]) : "r"(addr));
}

__device__ __forceinline__ void ldmat_x4_trans(uint32_t* r, uint32_t addr) {
    asm volatile("ldmatrix.sync.aligned.m8n8.x4.trans.shared.b16 {%0,%1,%2,%3}, [%4];"
                 : "=r"(r[0]), "=r"(r[1]), "=r"(r[2]), "=r"(r[3]) : "r"(addr));
}

__device__ __forceinline__ void mma16816(float* c, const uint32_t* a,
                                         uint32_t b0, uint32_t b1) {
    asm volatile(
        "mma.sync.aligned.m16n8k16.row.col.f32.f16.f16.f32 "
        "{%0,%1,%2,%3}, {%4,%5,%6,%7}, {%8,%9}, {%0,%1,%2,%3};"
        : "+f"(c[0]), "+f"(c[1]), "+f"(c[2]), "+f"(c[3])
        : "r"(a[0]), "r"(a[1]), "r"(a[2]), "r"(a[3]), "r"(b0), "r"(b1));
}

__device__ __forceinline__ uint32_t packh2(float lo, float hi) {
    __half2 h = __floats2half2_rn(lo, hi);
    return *(uint32_t*)&h;
}

__device__ __forceinline__ void split2h(float vx, float vy,
                                        uint32_t& uhi, uint32_t& ulo) {
    __half2 h = __floats2half2_rn(vx, vy);
    uhi = *(uint32_t*)&h;
    float hx = __half2float(__low2half(h));
    float hy = __half2float(__high2half(h));
    ulo = packh2(vx - hx, vy - hy);
}

__device__ __forceinline__ uint32_t sw128(uint32_t off) {
    return off ^ ((off >> 3) & 0x70);
}

// ---------------- perm (dtype-agnostic detection) ----------------
__global__ void build_perm(const void* __restrict__ is_ctx_raw) {
    const unsigned char* u8  = (const unsigned char*)is_ctx_raw;
    const unsigned int*  u32 = (const unsigned int*)is_ctx_raw;
    int b = blockIdx.x;
    int lane = threadIdx.x;

    int s = 0;
    for (int i = lane; i < 2048; i += 32) s += (int)u8[i];
#pragma unroll
    for (int off = 16; off; off >>= 1) s += __shfl_xor_sync(0xffffffffu, s, off);
    bool one_byte = (s == 1024) || (s == 255 * 1024);

    int cbase = 0, tbase = PNC;
    for (int j0 = 0; j0 < PK; j0 += 32) {
        int j = j0 + lane;
        int c = one_byte ? (u8[b * PK + j] != 0) : (u32[b * PK + j] != 0u);
        unsigned mask = __ballot_sync(0xffffffffu, c);
        int pre = __popc(mask & ((1u << lane) - 1u));
        int slot = c ? (cbase + pre) : (tbase + lane - pre);
        g_perm[b * PK + slot] = j;
        int nc = __popc(mask);
        cbase += nc;
        tbase += 32 - nc;
    }
}

// ---------------- RoPE + gather -> a2 panels directly -----------------------
__global__ __launch_bounds__(512) void rope_gather(
    const float* __restrict__ x, const float* __restrict__ coords,
    const float* __restrict__ rope) {
    int s = blockIdx.x & (PK - 1);
    int b = blockIdx.x >> 11;
    int j = g_perm[b * PK + s];
    long tokin = (long)b * PK + j;

    float cy = coords[tokin * 2 + 0];
    float cx = coords[tokin * 2 + 1];
    int ypos = (int)fminf(fmaxf(cy / 224.0f * 1023.0f, 0.0f), 1023.0f);
    int xpos = (int)fminf(fmaxf(cx / 224.0f * 1023.0f, 0.0f), 1023.0f);

    int t = threadIdx.x;
    int i = t & 255;
    int pos = (t < 256) ? xpos : ypos;
    int base = (t < 256) ? (2 * i) : (512 + 2 * i);

    float c  = rope[((long)pos * 256 + i) * 2 + 0];
    float sn = rope[((long)pos * 256 + i) * 2 + 1];
    float2 p = *(const float2*)(x + tokin * PD + base);
    float rx = p.x * c - p.y * sn;
    float ry = p.x * sn + p.y * c;

    uint32_t uhi, ulo;
    split2h(rx, ry, uhi, ulo);

    int mbp = b * 16 + (s >> 7);
    int rowp = s & 127;
    int ck = base >> 6;
    uint32_t sw = sw128((uint32_t)(rowp * 128 + (base & 63) * 2));
    long pb = (long)mbp * 32;
    *(uint32_t*)((char*)(g_a2 + (pb + ck) * PANEL) + sw)      = uhi;
    *(uint32_t*)((char*)(g_a2 + (pb + 16 + ck) * PANEL) + sw) = ulo;
}

// ---------------- merged fp16-hi conversion of ALL weights ------------------
__global__ __launch_bounds__(256) void convert_w_all(
    const float* __restrict__ s_ci, const float* __restrict__ s_ti,
    const float* __restrict__ s_co, const float* __restrict__ s_to) {
    int gm = blockIdx.x >> 4;
    int kb = blockIdx.x & 15;
    const float* src;
    __half* dst;
    int mb;
    if (gm < 24)      { src = s_ci; dst = g_wc;  mb = gm; }
    else if (gm < 48) { src = s_ti; dst = g_wt;  mb = gm - 24; }
    else if (gm < 56) { src = s_co; dst = g_wco; mb = gm - 48; }
    else              { src = s_to; dst = g_wto; mb = gm - 56; }
    int kc0 = kb * 64;
    long pan = (long)mb * 16 + kb;

    int t = threadIdx.x;
#pragma unroll
    for (int q = 0; q < 4; q++) {
        int ch = t + q * 256;
        int r = ch >> 3;
        int c0 = (ch & 7) * 8;
        const float* sp = src + ((long)mb * 128 + r) * 1024 + kc0 + c0;
        float4 f0 = *(const float4*)sp;
        float4 f1 = *(const float4*)(sp + 4);
        float vals[8] = {f0.x, f0.y, f0.z, f0.w, f1.x, f1.y, f1.z, f1.w};
        union { __half h[8]; uint4 u; } pk;
#pragma unroll
        for (int e = 0; e < 8; e++) pk.h[e] = __float2half_rn(vals[e]);
        uint32_t sw = sw128((uint32_t)(r * 128 + c0 * 2));
        *(uint4*)((char*)(dst + pan * PANEL) + sw) = pk.u;
    }
}

// ---------------- shared GEMM mainloop (fp16, A 2-term) ---------------------
// acc += (Ah+Al) * Wh^T over K=1024. Stage = [Ah 16KB | Al 16KB | Wh 16KB].
// W fragments hoisted across the Ah/Al halves (32 ldmatrix/chunk vs 48).
__device__ __forceinline__ void gemm_mainloop(
    const char* pA, const char* pW, uint32_t tiles,
    int tid, int rA0, int rB0, int cb, uint32_t xm,
    float acc[2][8][4]) {
    {
        uint32_t sa = tiles;
#pragma unroll
        for (int q = 0; q < 12; q++) {
            int ch = tid + q * 256;
            int reg = ch >> 10;
            int idx = ch & 1023;
            const char* src = (reg == 0) ? (pA + idx * 16)
                            : (reg == 1) ? (pA + 16 * 16384 + idx * 16)
                                         : (pW + idx * 16);
            cp_async16(sa + ch * 16, src);
        }
        CP_COMMIT();
    }

    for (int kb = 0; kb < 16; kb++) {
        if (kb + 1 < 16) {
            uint32_t sa = tiles + (uint32_t)((kb + 1) & 1) * 49152u;
            const char* gAh = pA + (long)(kb + 1) * 16384;
            const char* gAl = pA + (long)(16 + kb + 1) * 16384;
            const char* gW  = pW + (long)(kb + 1) * 16384;
#pragma unroll
            for (int q = 0; q < 12; q++) {
                int ch = tid + q * 256;
                int reg = ch >> 10;
                int idx = ch & 1023;
                const char* src = (reg == 0) ? (gAh + idx * 16)
                                : (reg == 1) ? (gAl + idx * 16)
                                             : (gW + idx * 16);
                cp_async16(sa + ch * 16, src);
            }
            CP_COMMIT();
            CP_WAIT(1);
        } else {
            CP_WAIT(0);
        }
        __syncthreads();

        uint32_t sA = tiles + (uint32_t)(kb & 1) * 49152u;
        uint32_t sW = sA + 32768u;
#pragma unroll
        for (int ks = 0; ks < 4; ks++) {
            uint32_t colb = (uint32_t)(cb + ks * 32) ^ xm;
            uint32_t bf[4][4];
#pragma unroll
            for (int np = 0; np < 4; np++)
                ldmat_x4(bf[np], sW + (uint32_t)(rB0 + np * 16) * 128u + colb);
#pragma unroll
            for (int half = 0; half < 2; half++) {
                uint32_t aB = sA + (uint32_t)half * 16384u;
                uint32_t af[2][4];
#pragma unroll
                for (int mt = 0; mt < 2; mt++)
                    ldmat_x4(af[mt], aB + (uint32_t)(rA0 + mt * 16) * 128u + colb);
#pragma unroll
                for (int mt = 0; mt < 2; mt++) {
#pragma unroll
                    for (int nt = 0; nt < 8; nt++) {
                        int np = nt >> 1;
                        int sel = nt & 1;
                        mma16816(acc[mt][nt], af[mt], bf[np][sel], bf[np][sel + 2]);
                    }
                }
            }
        }
        __syncthreads();
    }
}

// ---------------- merged projection GEMM -> attention panels ----------------
// grid (48, 32): x<24 ctx qkv, x<40 tgt kv, else tgt q.
__global__ __launch_bounds__(256, 2) void gemm_proj(
    const float* __restrict__ ctx_in_b, const float* __restrict__ tgt_in_b) {
    extern __shared__ char dsm[];
    uint32_t base = smem_u32(dsm);
    uint32_t tiles = (base + 1023u) & ~1023u;

    int tid = threadIdx.x;
    int wid = tid >> 5;
    int lid = tid & 31;
    int wm = wid & 3;
    int wn = wid >> 2;

    int nx = blockIdx.x;
    const __half* Apan;
    const __half* Wpan;
    const float* bias;
    __half* apDst;
    float qscale;
    int nloc;
    if (nx < 24) {
        Apan = g_a2; Wpan = g_wc; bias = ctx_in_b;
        apDst = g_ap; qscale = 0.125f; nloc = nx;
    } else if (nx < 40) {
        Apan = g_a2; Wpan = g_wt + 8ll * 16 * PANEL; bias = tgt_in_b + 1024;
        apDst = g_ap + 8ll * ATT_T; qscale = 1.0f; nloc = nx - 24;
    } else {
        Apan = g_a2 + 8ll * 32 * PANEL; Wpan = g_wt; bias = tgt_in_b;
        apDst = g_ap + 6ll * ATT_T; qscale = 0.125f; nloc = nx - 40;
    }

    int by = blockIdx.y;
    int b = by >> 3;
    int l = by & 7;
    const char* pA = (const char*)(Apan + ((long)(b * 16 + l) * 32) * PANEL);
    const char* pW = (const char*)(Wpan + ((long)nloc * 16) * PANEL);

    float acc[2][8][4];
#pragma unroll
    for (int mt = 0; mt < 2; mt++)
#pragma unroll
        for (int nt = 0; nt < 8; nt++)
#pragma unroll
            for (int e = 0; e < 4; e++) acc[mt][nt][e] = 0.0f;

    int rA0 = wm * 32 + (lid & 15);
    int rB0 = wn * 64 + (lid & 15);
    int cb  = (lid >> 4) * 16;
    uint32_t xm = (uint32_t)((lid & 7) << 4);

    gemm_mainloop(pA, pW, tiles, tid, rA0, rB0, cb, xm, acc);

    int n0 = nloc * 128;
#pragma unroll
    for (int nt = 0; nt < 8; nt++) {
        int cc = wn * 64 + nt * 8 + (lid & 3) * 2;
        int ng = n0 + cc;
        int g = ng >> 10;
        int head = (ng >> 6) & 15;
        float sc = (g == 0) ? qscale : 1.0f;
        float bx = bias[ng];
        float by2 = bias[ng + 1];
        __half* hiB = apDst + (long)(2 * g) * ATT_T;
        __half* loB = apDst + (long)(2 * g + 1) * ATT_T;
#pragma unroll
        for (int mt = 0; mt < 2; mt++) {
            int r0 = wm * 32 + mt * 16 + (lid >> 2);
#pragma unroll
            for (int half = 0; half < 2; half++) {
                int tr = l * 128 + r0 + half * 8;
                int kt = tr >> 6;
                int row = tr & 63;
                float vx = (acc[mt][nt][half * 2 + 0] + bx) * sc;
                float vy = (acc[mt][nt][half * 2 + 1] + by2) * sc;
                uint32_t uhi, ulo;
                split2h(vx, vy, uhi, ulo);
                long pan = (((long)b * PH + head) * 16 + kt) * APAN;
                uint32_t sw = sw128((uint32_t)(row * 128 + (nt * 8 + (lid & 3) * 2) * 2));
                *(uint32_t*)((char*)(hiB + pan) + sw) = uhi;
                *(uint32_t*)((char*)(loB + pan) + sw) = ulo;
            }
        }
    }
}

// ---------------- merged output projection -> d_out (perm scatter) ----------
// grid (8, 64): y<32 ctx, else tgt.
__global__ __launch_bounds__(256, 2) void gemm_out(
    const float* __restrict__ ctx_out_b, const float* __restrict__ tgt_out_b,
    float* __restrict__ C) {
    extern __shared__ char dsm[];
    uint32_t base = smem_u32(dsm);
    uint32_t tiles = (base + 1023u) & ~1023u;

    int tid = threadIdx.x;
    int wid = tid >> 5;
    int lid = tid & 31;
    int wm = wid & 3;
    int wn = wid >> 2;

    int y = blockIdx.y;
    const __half* Apan;
    const __half* Wpan;
    const float* bias;
    int slotOff;
    if (y < 32) {
        Apan = g_oc2; Wpan = g_wco; bias = ctx_out_b; slotOff = 0;
    } else {
        Apan = g_ot2; Wpan = g_wto; bias = tgt_out_b; slotOff = PNC;
        y -= 32;
    }
    int b = y >> 3;
    int l = y & 7;
    const char* pA = (const char*)(Apan + ((long)(b * 8 + l) * 32) * PANEL);
    const char* pW = (const char*)(Wpan + ((long)blockIdx.x * 16) * PANEL);

    float acc[2][8][4];
#pragma unroll
    for (int mt = 0; mt < 2; mt++)
#pragma unroll
        for (int nt = 0; nt < 8; nt++)
#pragma unroll
            for (int e = 0; e < 4; e++) acc[mt][nt][e] = 0.0f;

    int rA0 = wm * 32 + (lid & 15);
    int rB0 = wn * 64 + (lid & 15);
    int cb  = (lid >> 4) * 16;
    uint32_t xm = (uint32_t)((lid & 7) << 4);

    gemm_mainloop(pA, pW, tiles, tid, rA0, rB0, cb, xm, acc);

    int n0 = blockIdx.x * 128;
#pragma unroll
    for (int nt = 0; nt < 8; nt++) {
        int cc = wn * 64 + nt * 8 + (lid & 3) * 2;
        float2 bv;
        bv.x = bias[n0 + cc];
        bv.y = bias[n0 + cc + 1];
#pragma unroll
        for (int mt = 0; mt < 2; mt++) {
            int r0 = wm * 32 + mt * 16 + (lid >> 2);
            float2 v0, v1;
            v0.x = acc[mt][nt][0] + bv.x;
            v0.y = acc[mt][nt][1] + bv.y;
            v1.x = acc[mt][nt][2] + bv.x;
            v1.y = acc[mt][nt][3] + bv.y;
            int tok0 = g_perm[b * PK + l * 128 + r0 + slotOff];
            int tok1 = g_perm[b * PK + l * 128 + r0 + 8 + slotOff];
            *(float2*)(C + ((long)b * PK + tok0) * PD + n0 + cc) = v0;
            *(float2*)(C + ((long)b * PK + tok1) * PD + n0 + cc) = v1;
        }
    }
}

// ---------------- merged fp16 HMMA flash attention --------------------------
// grid (8, 16, 8): z<4 ctx (b=z), else tgt (b=z-4).
__global__ __launch_bounds__(256) void attn_mma() {
    extern __shared__ char dsm[];
    uint32_t base = smem_u32(dsm);
    uint32_t sQ = (base + 1023u) & ~1023u;     // Qh 16KB | Ql 16KB
    uint32_t sT = sQ + 32768u;                 // 2 stages x [Kh|Kl|Vh] 8KB each

    int tid = threadIdx.x, wid = tid >> 5, lid = tid & 31;
    int qt = blockIdx.x, h = blockIdx.y, z = blockIdx.z;
    int b;
    const __half* baseAp;
    __half* Opan;
    if (z < 4) { b = z;     baseAp = g_ap;                 Opan = g_oc2; }
    else       { b = z - 4; baseAp = g_ap + 6ll * ATT_T;   Opan = g_ot2; }

    long pb = ((long)b * PH + h) * 16;
    const char* pQh = (const char*)(baseAp + 0ll * ATT_T + (pb + qt * 2) * APAN);
    const char* pQl = (const char*)(baseAp + 1ll * ATT_T + (pb + qt * 2) * APAN);
    const char* pKh = (const char*)(baseAp + 2ll * ATT_T + pb * APAN);
    const char* pKl = (const char*)(baseAp + 3ll * ATT_T + pb * APAN);
    const char* pVh = (const char*)(baseAp + 4ll * ATT_T + pb * APAN);

#pragma unroll
    for (int q = 0; q < 8; q++) {
        int ch = tid + q * 256;
        int idx = ch & 1023;
        if (q < 4) cp_async16(sQ + idx * 16, pQh + idx * 16);
        else       cp_async16(sQ + 16384 + idx * 16, pQl + idx * 16);
    }
#pragma unroll
    for (int q = 0; q < 6; q++) {
        int ch = tid + q * 256;
        int idx = ch & 511;
        const char* s = (q < 2) ? pKh : (q < 4) ? pKl : pVh;
        cp_async16(sT + ch * 16, s + idx * 16);
    }
    CP_COMMIT();
    CP_WAIT(0);
    __syncthreads();

    int cb = (lid >> 4) * 16;
    uint32_t xm = (uint32_t)((lid & 7) << 4);

    uint32_t qra = sQ + (uint32_t)(wid >> 2) * 8192u
                 + (uint32_t)(((wid & 3) * 16 + (lid & 15)) * 128);
    uint32_t qhf[4][4], qlf[4][4];
#pragma unroll
    for (int ks = 0; ks < 4; ks++) {
        uint32_t col = (uint32_t)(ks * 32 + cb) ^ xm;
        ldmat_x4(qhf[ks], qra + col);
        ldmat_x4(qlf[ks], qra + 16384u + col);
    }

    float m0 = -1e30f, m1 = -1e30f, l0 = 0.0f, l1 = 0.0f;
    float oa[8][4];
#pragma unroll
    for (int nt = 0; nt < 8; nt++)
#pragma unroll
        for (int e = 0; e < 4; e++) oa[nt][e] = 0.0f;

    for (int kt = 0; kt < 16; kt++) {
        uint32_t st = sT + (uint32_t)(kt & 1) * 24576u;
        if (kt + 1 < 16) {
            uint32_t sn = sT + (uint32_t)((kt + 1) & 1) * 24576u;
            long off = (long)(kt + 1) * 8192;
#pragma unroll
            for (int q = 0; q < 6; q++) {
                int ch = tid + q * 256;
                int idx = ch & 511;
                const char* s = (q < 2) ? pKh : (q < 4) ? pKl : pVh;
                cp_async16(sn + ch * 16, s + off + idx * 16);
            }
            CP_COMMIT();
        }

        float sc[8][4];
#pragma unroll
        for (int nt = 0; nt < 8; nt++)
#pragma unroll
            for (int e = 0; e < 4; e++) sc[nt][e] = 0.0f;

#pragma unroll
        for (int ks = 0; ks < 4; ks++) {
            uint32_t col = (uint32_t)(ks * 32 + cb) ^ xm;
            uint32_t bh_[4][4], bl_[4][4];
#pragma unroll
            for (int np = 0; np < 4; np++) {
                uint32_t ra = (uint32_t)((np * 16 + (lid & 15)) * 128);
                ldmat_x4(bh_[np], st + ra + col);
                ldmat_x4(bl_[np], st + 8192u + ra + col);
            }
#pragma unroll
            for (int nt = 0; nt < 8; nt++) {
                int np = nt >> 1, sel = nt & 1;
                mma16816(sc[nt], qhf[ks], bh_[np][sel], bh_[np][sel + 2]);
                mma16816(sc[nt], qlf[ks], bh_[np][sel], bh_[np][sel + 2]);
                mma16816(sc[nt], qhf[ks], bl_[np][sel], bl_[np][sel + 2]);
            }
        }

        float mt0 = -1e30f, mt1 = -1e30f;
#pragma unroll
        for (int nt = 0; nt < 8; nt++) {
            mt0 = fmaxf(mt0, fmaxf(sc[nt][0], sc[nt][1]));
            mt1 = fmaxf(mt1, fmaxf(sc[nt][2], sc[nt][3]));
        }
        mt0 = fmaxf(mt0, __shfl_xor_sync(0xffffffffu, mt0, 1));
        mt0 = fmaxf(mt0, __shfl_xor_sync(0xffffffffu, mt0, 2));
        mt1 = fmaxf(mt1, __shfl_xor_sync(0xffffffffu, mt1, 1));
        mt1 = fmaxf(mt1, __shfl_xor_sync(0xffffffffu, mt1, 2));

        float mn0 = fmaxf(m0, mt0), mn1 = fmaxf(m1, mt1);
        float a0 = __expf(m0 - mn0), a1 = __expf(m1 - mn1);

        uint32_t php[8][2], plp[8][2];
        float ps0 = 0.0f, ps1 = 0.0f;
#pragma unroll
        for (int nt = 0; nt < 8; nt++) {
            float p00 = __expf(sc[nt][0] - mn0);
            float p01 = __expf(sc[nt][1] - mn0);
            float p10 = __expf(sc[nt][2] - mn1);
            float p11 = __expf(sc[nt][3] - mn1);
            ps0 += p00 + p01;
            ps1 += p10 + p11;
            uint32_t u0, u1, w0, w1;
            split2h(p00, p01, u0, w0);
            split2h(p10, p11, u1, w1);
            php[nt][0] = u0;  php[nt][1] = u1;
            plp[nt][0] = w0;  plp[nt][1] = w1;
        }
        ps0 += __shfl_xor_sync(0xffffffffu, ps0, 1);
        ps0 += __shfl_xor_sync(0xffffffffu, ps0, 2);
        ps1 += __shfl_xor_sync(0xffffffffu, ps1, 1);
        ps1 += __shfl_xor_sync(0xffffffffu, ps1, 2);

        l0 = l0 * a0 + ps0;
        l1 = l1 * a1 + ps1;
        m0 = mn0;
        m1 = mn1;
#pragma unroll
        for (int nt = 0; nt < 8; nt++) {
            oa[nt][0] *= a0; oa[nt][1] *= a0;
            oa[nt][2] *= a1; oa[nt][3] *= a1;
        }

#pragma unroll
        for (int ks = 0; ks < 4; ks++) {
            uint32_t ah[4] = {php[2 * ks][0], php[2 * ks][1],
                              php[2 * ks + 1][0], php[2 * ks + 1][1]};
            uint32_t al[4] = {plp[2 * ks][0], plp[2 * ks][1],
                              plp[2 * ks + 1][0], plp[2 * ks + 1][1]};
            uint32_t vh_[4][4];
            uint32_t ra = (uint32_t)((ks * 16 + (lid & 15)) * 128);
#pragma unroll
            for (int np = 0; np < 4; np++) {
                uint32_t col = (uint32_t)(np * 32 + cb) ^ xm;
                ldmat_x4_trans(vh_[np], st + 16384u + ra + col);
            }
#pragma unroll
            for (int nt = 0; nt < 8; nt++) {
                int np = nt >> 1, s2 = (nt & 1) * 2;
                mma16816(oa[nt], ah, vh_[np][s2], vh_[np][s2 + 1]);
                mma16816(oa[nt], al, vh_[np][s2], vh_[np][s2 + 1]);
            }
        }

        if (kt + 1 < 16) CP_WAIT(0);
        __syncthreads();
    }

    // epilogue: split A-panels [mb = b*8+qt][32 chunks]; hi -> h, lo -> 16+h
    float i0 = 1.0f / l0, i1 = 1.0f / l1;
    int rl = wid * 16 + (lid >> 2);
    long panB = ((long)b * 8 + qt) * 32;
    __half* c_hi = Opan + (panB + h) * (long)PANEL;
    __half* c_lo = Opan + (panB + 16 + h) * (long)PANEL;
#pragma unroll
    for (int nt = 0; nt < 8; nt++) {
        int col = nt * 8 + (lid & 3) * 2;
        uint32_t sw0 = sw128((uint32_t)(rl * 128 + col * 2));
        uint32_t sw1 = sw128((uint32_t)((rl + 8) * 128 + col * 2));
        uint32_t uhi0, ulo0, uhi1, ulo1;
        split2h(oa[nt][0] * i0, oa[nt][1] * i0, uhi0, ulo0);
        split2h(oa[nt][2] * i1, oa[nt][3] * i1, uhi1, ulo1);
        *(uint32_t*)((char*)c_hi + sw0) = uhi0;
        *(uint32_t*)((char*)c_lo + sw0) = ulo0;
        *(uint32_t*)((char*)c_hi + sw1) = uhi1;
        *(uint32_t*)((char*)c_lo + sw1) = ulo1;
    }
}

// ---------------- launch ----------------
extern "C" void kernel_launch(void* const* d_in, const int* in_sizes, int n_in,
                              void* d_out, int out_size) {
    const float* x         = (const float*)d_in[0];
    const float* coords    = (const float*)d_in[1];
    const void*  is_ctx    = d_in[2];
    const float* rope      = (const float*)d_in[3];
    const float* ctx_in_w  = (const float*)d_in[4];
    const float* ctx_in_b  = (const float*)d_in[5];
    const float* ctx_out_w = (const float*)d_in[6];
    const float* ctx_out_b = (const float*)d_in[7];
    const float* tgt_in_w  = (const float*)d_in[8];
    const float* tgt_in_b  = (const float*)d_in[9];
    const float* tgt_out_w = (const float*)d_in[10];
    const float* tgt_out_b = (const float*)d_in[11];
    float* out = (float*)d_out;

    const int GSM = 1024 + 2 * 49152;           // 99328
    const int ASM = 1024 + 32768 + 2 * 24576;   // 82944
    cudaFuncSetAttribute(gemm_proj, cudaFuncAttributeMaxDynamicSharedMemorySize, GSM);
    cudaFuncSetAttribute(gemm_out,  cudaFuncAttributeMaxDynamicSharedMemorySize, GSM);
    cudaFuncSetAttribute(attn_mma,  cudaFuncAttributeMaxDynamicSharedMemorySize, ASM);

    build_perm<<<PB, 32>>>(is_ctx);
    rope_gather<<<PB * PK, 512>>>(x, coords, rope);
    convert_w_all<<<64 * 16, 256>>>(ctx_in_w, tgt_in_w, ctx_out_w, tgt_out_w);
    gemm_proj<<<dim3(48, 32), 256, GSM>>>(ctx_in_b, tgt_in_b);
    attn_mma<<<dim3(8, PH, 2 * PB), 256, ASM>>>();
    gemm_out<<<dim3(8, 64), 256, GSM>>>(ctx_out_b, tgt_out_b, out);
}

// round 11
// speedup vs baseline: 4.6844x; 1.1149x over previous
#include <cuda_runtime.h>
#include <cuda_fp16.h>
#include <cstdint>

// Problem constants
#define PB   4
#define PK   2048
#define PD   1024
#define PH   16
#define PNC  1024   // NCTX = K/2

#define PANEL 8192      // fp16 elems per 128x64 tile panel (16KB)
#define APAN  4096      // fp16 elems per 64x64 attention panel (8KB)
#define ATT_T (PB * PH * 16 * APAN)

// ---------------- scratch (device globals: allocation-free) ----------------
__device__ __align__(256) int g_perm[PB * PK];
// split-fp16 swizzled tile panels. A panels: 32 chunks (16 hi + 16 lo).
// W panels: 16 chunks (hi only).
__device__ __align__(256) __half g_a2 [64ll * 32 * PANEL];
__device__ __align__(256) __half g_wc [24ll * 16 * PANEL];
__device__ __align__(256) __half g_wt [24ll * 16 * PANEL];
__device__ __align__(256) __half g_wco[ 8ll * 16 * PANEL];
__device__ __align__(256) __half g_wto[ 8ll * 16 * PANEL];
__device__ __align__(256) __half g_oc2[32ll * 16 * PANEL];   // attn out, hi only
__device__ __align__(256) __half g_ot2[32ll * 16 * PANEL];
// attention panels: 0..5 ctx {Qh,Ql,Kh,Kl,Vh,Vl}, 6..11 tgt
__device__ __align__(256) __half g_ap[12ll * ATT_T];

// ---------------- PTX helpers (base-PTX only) ----------------
__device__ __forceinline__ uint32_t smem_u32(const void* p) {
    uint32_t a;
    asm("{ .reg .u64 t; cvta.to.shared.u64 t, %1; cvt.u32.u64 %0, t; }" : "=r"(a) : "l"(p));
    return a;
}

__device__ __forceinline__ void cp_async16(uint32_t s, const void* g) {
    asm volatile("cp.async.cg.shared.global [%0], [%1], 16;" :: "r"(s), "l"(g));
}
#define CP_COMMIT() asm volatile("cp.async.commit_group;" ::: "memory")
#define CP_WAIT(n)  asm volatile("cp.async.wait_group %0;" :: "n"(n) : "memory")

__device__ __forceinline__ void ldmat_x4(uint32_t* r, uint32_t addr) {
    asm volatile("ldmatrix.sync.aligned.m8n8.x4.shared.b16 {%0,%1,%2,%3}, [%4];"
                 : "=r"(r[0]), "=r"(r[1]), "=r"(r[2]), "=r"(r[3]) : "r"(addr));
}

__device__ __forceinline__ void ldmat_x4_trans(uint32_t* r, uint32_t addr) {
    asm volatile("ldmatrix.sync.aligned.m8n8.x4.trans.shared.b16 {%0,%1,%2,%3}, [%4];"
                 : "=r"(r[0]), "=r"(r[1]), "=r"(r[2]), "=r"(r[3]) : "r"(addr));
}

__device__ __forceinline__ void mma16816(float* c, const uint32_t* a,
                                         uint32_t b0, uint32_t b1) {
    asm volatile(
        "mma.sync.aligned.m16n8k16.row.col.f32.f16.f16.f32 "
        "{%0,%1,%2,%3}, {%4,%5,%6,%7}, {%8,%9}, {%0,%1,%2,%3};"
        : "+f"(c[0]), "+f"(c[1]), "+f"(c[2]), "+f"(c[3])
        : "r"(a[0]), "r"(a[1]), "r"(a[2]), "r"(a[3]), "r"(b0), "r"(b1));
}

__device__ __forceinline__ uint32_t packh2(float lo, float hi) {
    __half2 h = __floats2half2_rn(lo, hi);
    return *(uint32_t*)&h;
}

__device__ __forceinline__ void split2h(float vx, float vy,
                                        uint32_t& uhi, uint32_t& ulo) {
    __half2 h = __floats2half2_rn(vx, vy);
    uhi = *(uint32_t*)&h;
    float hx = __half2float(__low2half(h));
    float hy = __half2float(__high2half(h));
    ulo = packh2(vx - hx, vy - hy);
}

__device__ __forceinline__ uint32_t sw128(uint32_t off) {
    return off ^ ((off >> 3) & 0x70);
}

// ---------------- perm (dtype-agnostic detection) ----------------
__global__ void build_perm(const void* __restrict__ is_ctx_raw) {
    const unsigned char* u8  = (const unsigned char*)is_ctx_raw;
    const unsigned int*  u32 = (const unsigned int*)is_ctx_raw;
    int b = blockIdx.x;
    int lane = threadIdx.x;

    int s = 0;
    for (int i = lane; i < 2048; i += 32) s += (int)u8[i];
#pragma unroll
    for (int off = 16; off; off >>= 1) s += __shfl_xor_sync(0xffffffffu, s, off);
    bool one_byte = (s == 1024) || (s == 255 * 1024);

    int cbase = 0, tbase = PNC;
    for (int j0 = 0; j0 < PK; j0 += 32) {
        int j = j0 + lane;
        int c = one_byte ? (u8[b * PK + j] != 0) : (u32[b * PK + j] != 0u);
        unsigned mask = __ballot_sync(0xffffffffu, c);
        int pre = __popc(mask & ((1u << lane) - 1u));
        int slot = c ? (cbase + pre) : (tbase + lane - pre);
        g_perm[b * PK + slot] = j;
        int nc = __popc(mask);
        cbase += nc;
        tbase += 32 - nc;
    }
}

// ---------------- RoPE + gather -> a2 panels directly -----------------------
__global__ __launch_bounds__(512) void rope_gather(
    const float* __restrict__ x, const float* __restrict__ coords,
    const float* __restrict__ rope) {
    int s = blockIdx.x & (PK - 1);
    int b = blockIdx.x >> 11;
    int j = g_perm[b * PK + s];
    long tokin = (long)b * PK + j;

    float cy = coords[tokin * 2 + 0];
    float cx = coords[tokin * 2 + 1];
    int ypos = (int)fminf(fmaxf(cy / 224.0f * 1023.0f, 0.0f), 1023.0f);
    int xpos = (int)fminf(fmaxf(cx / 224.0f * 1023.0f, 0.0f), 1023.0f);

    int t = threadIdx.x;
    int i = t & 255;
    int pos = (t < 256) ? xpos : ypos;
    int base = (t < 256) ? (2 * i) : (512 + 2 * i);

    float c  = rope[((long)pos * 256 + i) * 2 + 0];
    float sn = rope[((long)pos * 256 + i) * 2 + 1];
    float2 p = *(const float2*)(x + tokin * PD + base);
    float rx = p.x * c - p.y * sn;
    float ry = p.x * sn + p.y * c;

    uint32_t uhi, ulo;
    split2h(rx, ry, uhi, ulo);

    int mbp = b * 16 + (s >> 7);
    int rowp = s & 127;
    int ck = base >> 6;
    uint32_t sw = sw128((uint32_t)(rowp * 128 + (base & 63) * 2));
    long pb = (long)mbp * 32;
    *(uint32_t*)((char*)(g_a2 + (pb + ck) * PANEL) + sw)      = uhi;
    *(uint32_t*)((char*)(g_a2 + (pb + 16 + ck) * PANEL) + sw) = ulo;
}

// ---------------- merged fp16-hi conversion of ALL weights ------------------
__global__ __launch_bounds__(256) void convert_w_all(
    const float* __restrict__ s_ci, const float* __restrict__ s_ti,
    const float* __restrict__ s_co, const float* __restrict__ s_to) {
    int gm = blockIdx.x >> 4;
    int kb = blockIdx.x & 15;
    const float* src;
    __half* dst;
    int mb;
    if (gm < 24)      { src = s_ci; dst = g_wc;  mb = gm; }
    else if (gm < 48) { src = s_ti; dst = g_wt;  mb = gm - 24; }
    else if (gm < 56) { src = s_co; dst = g_wco; mb = gm - 48; }
    else              { src = s_to; dst = g_wto; mb = gm - 56; }
    int kc0 = kb * 64;
    long pan = (long)mb * 16 + kb;

    int t = threadIdx.x;
#pragma unroll
    for (int q = 0; q < 4; q++) {
        int ch = t + q * 256;
        int r = ch >> 3;
        int c0 = (ch & 7) * 8;
        const float* sp = src + ((long)mb * 128 + r) * 1024 + kc0 + c0;
        float4 f0 = *(const float4*)sp;
        float4 f1 = *(const float4*)(sp + 4);
        float vals[8] = {f0.x, f0.y, f0.z, f0.w, f1.x, f1.y, f1.z, f1.w};
        union { __half h[8]; uint4 u; } pk;
#pragma unroll
        for (int e = 0; e < 8; e++) pk.h[e] = __float2half_rn(vals[e]);
        uint32_t sw = sw128((uint32_t)(r * 128 + c0 * 2));
        *(uint4*)((char*)(dst + pan * PANEL) + sw) = pk.u;
    }
}

// ---------------- GEMM mainloop, 2-term A (proj): single sync per chunk -----
// Stage = [Ah 16KB | Al 16KB | Wh 16KB], double buffered.
__device__ __forceinline__ void gemm_mainloop2(
    const char* pA, const char* pW, uint32_t tiles,
    int tid, int rA0, int rB0, int cb, uint32_t xm,
    float acc[2][8][4]) {
    {
        uint32_t sa = tiles;
#pragma unroll
        for (int q = 0; q < 12; q++) {
            int ch = tid + q * 256;
            int reg = ch >> 10;
            int idx = ch & 1023;
            const char* src = (reg == 0) ? (pA + idx * 16)
                            : (reg == 1) ? (pA + 16 * 16384 + idx * 16)
                                         : (pW + idx * 16);
            cp_async16(sa + ch * 16, src);
        }
        CP_COMMIT();
    }

    for (int kb = 0; kb < 16; kb++) {
        CP_WAIT(0);
        __syncthreads();   // stage kb visible; all reads of stage (kb+1)&1 done
        if (kb + 1 < 16) {
            uint32_t sa = tiles + (uint32_t)((kb + 1) & 1) * 49152u;
            const char* gAh = pA + (long)(kb + 1) * 16384;
            const char* gAl = pA + (long)(16 + kb + 1) * 16384;
            const char* gW  = pW + (long)(kb + 1) * 16384;
#pragma unroll
            for (int q = 0; q < 12; q++) {
                int ch = tid + q * 256;
                int reg = ch >> 10;
                int idx = ch & 1023;
                const char* src = (reg == 0) ? (gAh + idx * 16)
                                : (reg == 1) ? (gAl + idx * 16)
                                             : (gW + idx * 16);
                cp_async16(sa + ch * 16, src);
            }
            CP_COMMIT();
        }

        uint32_t sA = tiles + (uint32_t)(kb & 1) * 49152u;
        uint32_t sW = sA + 32768u;
#pragma unroll
        for (int ks = 0; ks < 4; ks++) {
            uint32_t colb = (uint32_t)(cb + ks * 32) ^ xm;
            uint32_t bf[4][4];
#pragma unroll
            for (int np = 0; np < 4; np++)
                ldmat_x4(bf[np], sW + (uint32_t)(rB0 + np * 16) * 128u + colb);
#pragma unroll
            for (int half = 0; half < 2; half++) {
                uint32_t aB = sA + (uint32_t)half * 16384u;
                uint32_t af[2][4];
#pragma unroll
                for (int mt = 0; mt < 2; mt++)
                    ldmat_x4(af[mt], aB + (uint32_t)(rA0 + mt * 16) * 128u + colb);
#pragma unroll
                for (int mt = 0; mt < 2; mt++) {
#pragma unroll
                    for (int nt = 0; nt < 8; nt++) {
                        int np = nt >> 1;
                        int sel = nt & 1;
                        mma16816(acc[mt][nt], af[mt], bf[np][sel], bf[np][sel + 2]);
                    }
                }
            }
        }
    }
}

// ---------------- GEMM mainloop, 1-term A (out-proj): single sync -----------
// Stage = [Ah 16KB | Wh 16KB], double buffered. A panel stride 16 chunks.
__device__ __forceinline__ void gemm_mainloop1(
    const char* pA, const char* pW, uint32_t tiles,
    int tid, int rA0, int rB0, int cb, uint32_t xm,
    float acc[2][8][4]) {
    {
        uint32_t sa = tiles;
#pragma unroll
        for (int q = 0; q < 8; q++) {
            int ch = tid + q * 256;
            int reg = ch >> 10;
            int idx = ch & 1023;
            const char* src = (reg == 0) ? (pA + idx * 16) : (pW + idx * 16);
            cp_async16(sa + ch * 16, src);
        }
        CP_COMMIT();
    }

    for (int kb = 0; kb < 16; kb++) {
        CP_WAIT(0);
        __syncthreads();
        if (kb + 1 < 16) {
            uint32_t sa = tiles + (uint32_t)((kb + 1) & 1) * 32768u;
            const char* gAh = pA + (long)(kb + 1) * 16384;
            const char* gW  = pW + (long)(kb + 1) * 16384;
#pragma unroll
            for (int q = 0; q < 8; q++) {
                int ch = tid + q * 256;
                int reg = ch >> 10;
                int idx = ch & 1023;
                const char* src = (reg == 0) ? (gAh + idx * 16) : (gW + idx * 16);
                cp_async16(sa + ch * 16, src);
            }
            CP_COMMIT();
        }

        uint32_t sA = tiles + (uint32_t)(kb & 1) * 32768u;
        uint32_t sW = sA + 16384u;
#pragma unroll
        for (int ks = 0; ks < 4; ks++) {
            uint32_t colb = (uint32_t)(cb + ks * 32) ^ xm;
            uint32_t bf[4][4];
#pragma unroll
            for (int np = 0; np < 4; np++)
                ldmat_x4(bf[np], sW + (uint32_t)(rB0 + np * 16) * 128u + colb);
            uint32_t af[2][4];
#pragma unroll
            for (int mt = 0; mt < 2; mt++)
                ldmat_x4(af[mt], sA + (uint32_t)(rA0 + mt * 16) * 128u + colb);
#pragma unroll
            for (int mt = 0; mt < 2; mt++) {
#pragma unroll
                for (int nt = 0; nt < 8; nt++) {
                    int np = nt >> 1;
                    int sel = nt & 1;
                    mma16816(acc[mt][nt], af[mt], bf[np][sel], bf[np][sel + 2]);
                }
            }
        }
    }
}

// ---------------- merged projection GEMM -> attention panels ----------------
// grid (48, 32): x<24 ctx qkv, x<40 tgt kv, else tgt q.
__global__ __launch_bounds__(256, 2) void gemm_proj(
    const float* __restrict__ ctx_in_b, const float* __restrict__ tgt_in_b) {
    extern __shared__ char dsm[];
    uint32_t base = smem_u32(dsm);
    uint32_t tiles = (base + 1023u) & ~1023u;

    int tid = threadIdx.x;
    int wid = tid >> 5;
    int lid = tid & 31;
    int wm = wid & 3;
    int wn = wid >> 2;

    int nx = blockIdx.x;
    const __half* Apan;
    const __half* Wpan;
    const float* bias;
    __half* apDst;
    float qscale;
    int nloc;
    if (nx < 24) {
        Apan = g_a2; Wpan = g_wc; bias = ctx_in_b;
        apDst = g_ap; qscale = 0.125f; nloc = nx;
    } else if (nx < 40) {
        Apan = g_a2; Wpan = g_wt + 8ll * 16 * PANEL; bias = tgt_in_b + 1024;
        apDst = g_ap + 8ll * ATT_T; qscale = 1.0f; nloc = nx - 24;
    } else {
        Apan = g_a2 + 8ll * 32 * PANEL; Wpan = g_wt; bias = tgt_in_b;
        apDst = g_ap + 6ll * ATT_T; qscale = 0.125f; nloc = nx - 40;
    }

    int by = blockIdx.y;
    int b = by >> 3;
    int l = by & 7;
    const char* pA = (const char*)(Apan + ((long)(b * 16 + l) * 32) * PANEL);
    const char* pW = (const char*)(Wpan + ((long)nloc * 16) * PANEL);

    float acc[2][8][4];
#pragma unroll
    for (int mt = 0; mt < 2; mt++)
#pragma unroll
        for (int nt = 0; nt < 8; nt++)
#pragma unroll
            for (int e = 0; e < 4; e++) acc[mt][nt][e] = 0.0f;

    int rA0 = wm * 32 + (lid & 15);
    int rB0 = wn * 64 + (lid & 15);
    int cb  = (lid >> 4) * 16;
    uint32_t xm = (uint32_t)((lid & 7) << 4);

    gemm_mainloop2(pA, pW, tiles, tid, rA0, rB0, cb, xm, acc);

    int n0 = nloc * 128;
#pragma unroll
    for (int nt = 0; nt < 8; nt++) {
        int cc = wn * 64 + nt * 8 + (lid & 3) * 2;
        int ng = n0 + cc;
        int g = ng >> 10;
        int head = (ng >> 6) & 15;
        float sc = (g == 0) ? qscale : 1.0f;
        float bx = bias[ng];
        float by2 = bias[ng + 1];
        __half* hiB = apDst + (long)(2 * g) * ATT_T;
        __half* loB = apDst + (long)(2 * g + 1) * ATT_T;
#pragma unroll
        for (int mt = 0; mt < 2; mt++) {
            int r0 = wm * 32 + mt * 16 + (lid >> 2);
#pragma unroll
            for (int half = 0; half < 2; half++) {
                int tr = l * 128 + r0 + half * 8;
                int kt = tr >> 6;
                int row = tr & 63;
                float vx = (acc[mt][nt][half * 2 + 0] + bx) * sc;
                float vy = (acc[mt][nt][half * 2 + 1] + by2) * sc;
                uint32_t uhi, ulo;
                split2h(vx, vy, uhi, ulo);
                long pan = (((long)b * PH + head) * 16 + kt) * APAN;
                uint32_t sw = sw128((uint32_t)(row * 128 + (nt * 8 + (lid & 3) * 2) * 2));
                *(uint32_t*)((char*)(hiB + pan) + sw) = uhi;
                *(uint32_t*)((char*)(loB + pan) + sw) = ulo;
            }
        }
    }
}

// ---------------- merged output projection -> d_out (perm scatter) ----------
// grid (8, 64): y<32 ctx, else tgt. 1-term A (attn output hi only).
__global__ __launch_bounds__(256, 2) void gemm_out(
    const float* __restrict__ ctx_out_b, const float* __restrict__ tgt_out_b,
    float* __restrict__ C) {
    extern __shared__ char dsm[];
    uint32_t base = smem_u32(dsm);
    uint32_t tiles = (base + 1023u) & ~1023u;

    int tid = threadIdx.x;
    int wid = tid >> 5;
    int lid = tid & 31;
    int wm = wid & 3;
    int wn = wid >> 2;

    int y = blockIdx.y;
    const __half* Apan;
    const __half* Wpan;
    const float* bias;
    int slotOff;
    if (y < 32) {
        Apan = g_oc2; Wpan = g_wco; bias = ctx_out_b; slotOff = 0;
    } else {
        Apan = g_ot2; Wpan = g_wto; bias = tgt_out_b; slotOff = PNC;
        y -= 32;
    }
    int b = y >> 3;
    int l = y & 7;
    const char* pA = (const char*)(Apan + ((long)(b * 8 + l) * 16) * PANEL);
    const char* pW = (const char*)(Wpan + ((long)blockIdx.x * 16) * PANEL);

    float acc[2][8][4];
#pragma unroll
    for (int mt = 0; mt < 2; mt++)
#pragma unroll
        for (int nt = 0; nt < 8; nt++)
#pragma unroll
            for (int e = 0; e < 4; e++) acc[mt][nt][e] = 0.0f;

    int rA0 = wm * 32 + (lid & 15);
    int rB0 = wn * 64 + (lid & 15);
    int cb  = (lid >> 4) * 16;
    uint32_t xm = (uint32_t)((lid & 7) << 4);

    gemm_mainloop1(pA, pW, tiles, tid, rA0, rB0, cb, xm, acc);

    int n0 = blockIdx.x * 128;
#pragma unroll
    for (int nt = 0; nt < 8; nt++) {
        int cc = wn * 64 + nt * 8 + (lid & 3) * 2;
        float2 bv;
        bv.x = bias[n0 + cc];
        bv.y = bias[n0 + cc + 1];
#pragma unroll
        for (int mt = 0; mt < 2; mt++) {
            int r0 = wm * 32 + mt * 16 + (lid >> 2);
            float2 v0, v1;
            v0.x = acc[mt][nt][0] + bv.x;
            v0.y = acc[mt][nt][1] + bv.y;
            v1.x = acc[mt][nt][2] + bv.x;
            v1.y = acc[mt][nt][3] + bv.y;
            int tok0 = g_perm[b * PK + l * 128 + r0 + slotOff];
            int tok1 = g_perm[b * PK + l * 128 + r0 + 8 + slotOff];
            *(float2*)(C + ((long)b * PK + tok0) * PD + n0 + cc) = v0;
            *(float2*)(C + ((long)b * PK + tok1) * PD + n0 + cc) = v1;
        }
    }
}

// ---------------- merged fp16 HMMA flash attention --------------------------
// grid (8, 16, 8): z<4 ctx (b=z), else tgt (b=z-4).
__global__ __launch_bounds__(256) void attn_mma() {
    extern __shared__ char dsm[];
    uint32_t base = smem_u32(dsm);
    uint32_t sQ = (base + 1023u) & ~1023u;     // Qh 16KB | Ql 16KB
    uint32_t sT = sQ + 32768u;                 // 2 stages x [Kh|Kl|Vh] 8KB each

    int tid = threadIdx.x, wid = tid >> 5, lid = tid & 31;
    int qt = blockIdx.x, h = blockIdx.y, z = blockIdx.z;
    int b;
    const __half* baseAp;
    __half* Opan;
    if (z < 4) { b = z;     baseAp = g_ap;                 Opan = g_oc2; }
    else       { b = z - 4; baseAp = g_ap + 6ll * ATT_T;   Opan = g_ot2; }

    long pb = ((long)b * PH + h) * 16;
    const char* pQh = (const char*)(baseAp + 0ll * ATT_T + (pb + qt * 2) * APAN);
    const char* pQl = (const char*)(baseAp + 1ll * ATT_T + (pb + qt * 2) * APAN);
    const char* pKh = (const char*)(baseAp + 2ll * ATT_T + pb * APAN);
    const char* pKl = (const char*)(baseAp + 3ll * ATT_T + pb * APAN);
    const char* pVh = (const char*)(baseAp + 4ll * ATT_T + pb * APAN);

#pragma unroll
    for (int q = 0; q < 8; q++) {
        int ch = tid + q * 256;
        int idx = ch & 1023;
        if (q < 4) cp_async16(sQ + idx * 16, pQh + idx * 16);
        else       cp_async16(sQ + 16384 + idx * 16, pQl + idx * 16);
    }
#pragma unroll
    for (int q = 0; q < 6; q++) {
        int ch = tid + q * 256;
        int idx = ch & 511;
        const char* s = (q < 2) ? pKh : (q < 4) ? pKl : pVh;
        cp_async16(sT + ch * 16, s + idx * 16);
    }
    CP_COMMIT();
    CP_WAIT(0);
    __syncthreads();

    int cb = (lid >> 4) * 16;
    uint32_t xm = (uint32_t)((lid & 7) << 4);

    uint32_t qra = sQ + (uint32_t)(wid >> 2) * 8192u
                 + (uint32_t)(((wid & 3) * 16 + (lid & 15)) * 128);
    uint32_t qhf[4][4], qlf[4][4];
#pragma unroll
    for (int ks = 0; ks < 4; ks++) {
        uint32_t col = (uint32_t)(ks * 32 + cb) ^ xm;
        ldmat_x4(qhf[ks], qra + col);
        ldmat_x4(qlf[ks], qra + 16384u + col);
    }

    float m0 = -1e30f, m1 = -1e30f, l0 = 0.0f, l1 = 0.0f;
    float oa[8][4];
#pragma unroll
    for (int nt = 0; nt < 8; nt++)
#pragma unroll
        for (int e = 0; e < 4; e++) oa[nt][e] = 0.0f;

    for (int kt = 0; kt < 16; kt++) {
        uint32_t st = sT + (uint32_t)(kt & 1) * 24576u;
        if (kt + 1 < 16) {
            uint32_t sn = sT + (uint32_t)((kt + 1) & 1) * 24576u;
            long off = (long)(kt + 1) * 8192;
#pragma unroll
            for (int q = 0; q < 6; q++) {
                int ch = tid + q * 256;
                int idx = ch & 511;
                const char* s = (q < 2) ? pKh : (q < 4) ? pKl : pVh;
                cp_async16(sn + ch * 16, s + off + idx * 16);
            }
            CP_COMMIT();
        }

        float sc[8][4];
#pragma unroll
        for (int nt = 0; nt < 8; nt++)
#pragma unroll
            for (int e = 0; e < 4; e++) sc[nt][e] = 0.0f;

#pragma unroll
        for (int ks = 0; ks < 4; ks++) {
            uint32_t col = (uint32_t)(ks * 32 + cb) ^ xm;
            uint32_t bh_[4][4], bl_[4][4];
#pragma unroll
            for (int np = 0; np < 4; np++) {
                uint32_t ra = (uint32_t)((np * 16 + (lid & 15)) * 128);
                ldmat_x4(bh_[np], st + ra + col);
                ldmat_x4(bl_[np], st + 8192u + ra + col);
            }
#pragma unroll
            for (int nt = 0; nt < 8; nt++) {
                int np = nt >> 1, sel = nt & 1;
                mma16816(sc[nt], qhf[ks], bh_[np][sel], bh_[np][sel + 2]);
                mma16816(sc[nt], qlf[ks], bh_[np][sel], bh_[np][sel + 2]);
                mma16816(sc[nt], qhf[ks], bl_[np][sel], bl_[np][sel + 2]);
            }
        }

        float mt0 = -1e30f, mt1 = -1e30f;
#pragma unroll
        for (int nt = 0; nt < 8; nt++) {
            mt0 = fmaxf(mt0, fmaxf(sc[nt][0], sc[nt][1]));
            mt1 = fmaxf(mt1, fmaxf(sc[nt][2], sc[nt][3]));
        }
        mt0 = fmaxf(mt0, __shfl_xor_sync(0xffffffffu, mt0, 1));
        mt0 = fmaxf(mt0, __shfl_xor_sync(0xffffffffu, mt0, 2));
        mt1 = fmaxf(mt1, __shfl_xor_sync(0xffffffffu, mt1, 1));
        mt1 = fmaxf(mt1, __shfl_xor_sync(0xffffffffu, mt1, 2));

        float mn0 = fmaxf(m0, mt0), mn1 = fmaxf(m1, mt1);
        float a0 = __expf(m0 - mn0), a1 = __expf(m1 - mn1);

        uint32_t php[8][2], plp[8][2];
        float ps0 = 0.0f, ps1 = 0.0f;
#pragma unroll
        for (int nt = 0; nt < 8; nt++) {
            float p00 = __expf(sc[nt][0] - mn0);
            float p01 = __expf(sc[nt][1] - mn0);
            float p10 = __expf(sc[nt][2] - mn1);
            float p11 = __expf(sc[nt][3] - mn1);
            ps0 += p00 + p01;
            ps1 += p10 + p11;
            uint32_t u0, u1, w0, w1;
            split2h(p00, p01, u0, w0);
            split2h(p10, p11, u1, w1);
            php[nt][0] = u0;  php[nt][1] = u1;
            plp[nt][0] = w0;  plp[nt][1] = w1;
        }
        ps0 += __shfl_xor_sync(0xffffffffu, ps0, 1);
        ps0 += __shfl_xor_sync(0xffffffffu, ps0, 2);
        ps1 += __shfl_xor_sync(0xffffffffu, ps1, 1);
        ps1 += __shfl_xor_sync(0xffffffffu, ps1, 2);

        l0 = l0 * a0 + ps0;
        l1 = l1 * a1 + ps1;
        m0 = mn0;
        m1 = mn1;
#pragma unroll
        for (int nt = 0; nt < 8; nt++) {
            oa[nt][0] *= a0; oa[nt][1] *= a0;
            oa[nt][2] *= a1; oa[nt][3] *= a1;
        }

#pragma unroll
        for (int ks = 0; ks < 4; ks++) {
            uint32_t ah[4] = {php[2 * ks][0], php[2 * ks][1],
                              php[2 * ks + 1][0], php[2 * ks + 1][1]};
            uint32_t al[4] = {plp[2 * ks][0], plp[2 * ks][1],
                              plp[2 * ks + 1][0], plp[2 * ks + 1][1]};
            uint32_t vh_[4][4];
            uint32_t ra = (uint32_t)((ks * 16 + (lid & 15)) * 128);
#pragma unroll
            for (int np = 0; np < 4; np++) {
                uint32_t col = (uint32_t)(np * 32 + cb) ^ xm;
                ldmat_x4_trans(vh_[np], st + 16384u + ra + col);
            }
#pragma unroll
            for (int nt = 0; nt < 8; nt++) {
                int np = nt >> 1, s2 = (nt & 1) * 2;
                mma16816(oa[nt], ah, vh_[np][s2], vh_[np][s2 + 1]);
                mma16816(oa[nt], al, vh_[np][s2], vh_[np][s2 + 1]);
            }
        }

        if (kt + 1 < 16) CP_WAIT(0);
        __syncthreads();
    }

    // epilogue: hi-only A-panels [mb = b*8+qt][16 chunks]; chunk h
    float i0 = 1.0f / l0, i1 = 1.0f / l1;
    int rl = wid * 16 + (lid >> 2);
    long panB = ((long)b * 8 + qt) * 16;
    __half* c_hi = Opan + (panB + h) * (long)PANEL;
#pragma unroll
    for (int nt = 0; nt < 8; nt++) {
        int col = nt * 8 + (lid & 3) * 2;
        uint32_t sw0 = sw128((uint32_t)(rl * 128 + col * 2));
        uint32_t sw1 = sw128((uint32_t)((rl + 8) * 128 + col * 2));
        *(uint32_t*)((char*)c_hi + sw0) = packh2(oa[nt][0] * i0, oa[nt][1] * i0);
        *(uint32_t*)((char*)c_hi + sw1) = packh2(oa[nt][2] * i1, oa[nt][3] * i1);
    }
}

// ---------------- launch ----------------
extern "C" void kernel_launch(void* const* d_in, const int* in_sizes, int n_in,
                              void* d_out, int out_size) {
    const float* x         = (const float*)d_in[0];
    const float* coords    = (const float*)d_in[1];
    const void*  is_ctx    = d_in[2];
    const float* rope      = (const float*)d_in[3];
    const float* ctx_in_w  = (const float*)d_in[4];
    const float* ctx_in_b  = (const float*)d_in[5];
    const float* ctx_out_w = (const float*)d_in[6];
    const float* ctx_out_b = (const float*)d_in[7];
    const float* tgt_in_w  = (const float*)d_in[8];
    const float* tgt_in_b  = (const float*)d_in[9];
    const float* tgt_out_w = (const float*)d_in[10];
    const float* tgt_out_b = (const float*)d_in[11];
    float* out = (float*)d_out;

    const int GSM  = 1024 + 2 * 49152;           // 99328 (proj, 2-term)
    const int GSM1 = 1024 + 2 * 32768;           // 66560 (out, 1-term)
    const int ASM  = 1024 + 32768 + 2 * 24576;   // 82944
    cudaFuncSetAttribute(gemm_proj, cudaFuncAttributeMaxDynamicSharedMemorySize, GSM);
    cudaFuncSetAttribute(gemm_out,  cudaFuncAttributeMaxDynamicSharedMemorySize, GSM1);
    cudaFuncSetAttribute(attn_mma,  cudaFuncAttributeMaxDynamicSharedMemorySize, ASM);

    build_perm<<<PB, 32>>>(is_ctx);
    rope_gather<<<PB * PK, 512>>>(x, coords, rope);
    convert_w_all<<<64 * 16, 256>>>(ctx_in_w, tgt_in_w, ctx_out_w, tgt_out_w);
    gemm_proj<<<dim3(48, 32), 256, GSM>>>(ctx_in_b, tgt_in_b);
    attn_mma<<<dim3(8, PH, 2 * PB), 256, ASM>>>();
    gemm_out<<<dim3(8, 64), 256, GSM1>>>(ctx_out_b, tgt_out_b, out);
}